// round 2
// baseline (speedup 1.0000x reference)
#include <cuda_runtime.h>
#include <math.h>

#define BB   4
#define TSEQ 1024
#define CCH  768
#define NH   12
#define HD   64
#define NWIN 4
#define NR   9
#define NBH  (BB*NH)   // 48

// Scratch (static __device__ arrays per allocation rules)
static __device__ float g_q[BB*CCH*TSEQ];     // (B, C, T): == (b,h,d,t), q pre-scaled by 1/8
static __device__ float g_k[BB*CCH*TSEQ];     // (B, C, T)
static __device__ float g_v[BB*CCH*TSEQ];     // (B, C, T)
static __device__ float g_mid[BB*CCH*TSEQ];   // attention output, (B, C, T)
static __device__ float g_bv[NBH*TSEQ*HD];    // banded rel-v contribution, (bh, i, d)
static __device__ float g_s[50331648];        // scores/attn, (bh, i, j) = 48*1024*1024

// ---------------------------------------------------------------------------
// Fused QKV projection: out[o,t] = (sum_c W[o,c] * x[b,c,t] + bias[o]) * scale
// 128x128x8 tile, 8x8 microtile, 256 threads.
// ---------------------------------------------------------------------------
__global__ __launch_bounds__(256)
void qkv_kernel(const float* __restrict__ X,
                const float* __restrict__ Wq, const float* __restrict__ Bq,
                const float* __restrict__ Wk, const float* __restrict__ Bk,
                const float* __restrict__ Wv, const float* __restrict__ Bv)
{
    __shared__ float As[8][132];
    __shared__ float Bs[8][132];
    int zb = blockIdx.z;
    int b = zb / 3, which = zb % 3;
    const float* Wm = (which == 0) ? Wq : ((which == 1) ? Wk : Wv);
    const float* Bi = (which == 0) ? Bq : ((which == 1) ? Bk : Bv);
    float* Out = (which == 0) ? g_q : ((which == 1) ? g_k : g_v);
    float scale = (which == 0) ? 0.125f : 1.0f;

    int tid = threadIdx.x;
    int tx = tid & 15, ty = tid >> 4;
    int o0 = blockIdx.x * 128, t0 = blockIdx.y * 128;
    const float* Xb = X + (size_t)b * CCH * TSEQ;

    float acc[8][8];
#pragma unroll
    for (int i = 0; i < 8; i++)
#pragma unroll
        for (int j = 0; j < 8; j++) acc[i][j] = 0.f;

    int ao = tid >> 1, ac4 = (tid & 1) * 4;
    int bc = tid >> 5, bt4 = (tid & 31) * 4;

    for (int k0 = 0; k0 < CCH; k0 += 8) {
        float4 a4 = *(const float4*)(Wm + (size_t)(o0 + ao) * CCH + k0 + ac4);
        float4 b4 = *(const float4*)(Xb + (size_t)(k0 + bc) * TSEQ + t0 + bt4);
        As[ac4 + 0][ao] = a4.x; As[ac4 + 1][ao] = a4.y;
        As[ac4 + 2][ao] = a4.z; As[ac4 + 3][ao] = a4.w;
        *(float4*)&Bs[bc][bt4] = b4;
        __syncthreads();
#pragma unroll
        for (int kk = 0; kk < 8; kk++) {
            float ar[8], br[8];
            *(float4*)&ar[0] = *(const float4*)&As[kk][ty * 8];
            *(float4*)&ar[4] = *(const float4*)&As[kk][ty * 8 + 4];
            *(float4*)&br[0] = *(const float4*)&Bs[kk][tx * 8];
            *(float4*)&br[4] = *(const float4*)&Bs[kk][tx * 8 + 4];
#pragma unroll
            for (int i = 0; i < 8; i++)
#pragma unroll
                for (int j = 0; j < 8; j++) acc[i][j] += ar[i] * br[j];
        }
        __syncthreads();
    }

    float* Ob = Out + (size_t)b * CCH * TSEQ;
#pragma unroll
    for (int i = 0; i < 8; i++) {
        int o = o0 + ty * 8 + i;
        float bv = Bi[o];
        float4 r0, r1;
        r0.x = (acc[i][0] + bv) * scale; r0.y = (acc[i][1] + bv) * scale;
        r0.z = (acc[i][2] + bv) * scale; r0.w = (acc[i][3] + bv) * scale;
        r1.x = (acc[i][4] + bv) * scale; r1.y = (acc[i][5] + bv) * scale;
        r1.z = (acc[i][6] + bv) * scale; r1.w = (acc[i][7] + bv) * scale;
        *(float4*)(Ob + (size_t)o * TSEQ + t0 + tx * 8) = r0;
        *(float4*)(Ob + (size_t)o * TSEQ + t0 + tx * 8 + 4) = r1;
    }
}

// ---------------------------------------------------------------------------
// Output projection: d_out = W_o @ g_mid + b_o
// ---------------------------------------------------------------------------
__global__ __launch_bounds__(256)
void oproj_kernel(const float* __restrict__ Wm, const float* __restrict__ Bi,
                  float* __restrict__ Out)
{
    __shared__ float As[8][132];
    __shared__ float Bs[8][132];
    int b = blockIdx.z;
    int tid = threadIdx.x;
    int tx = tid & 15, ty = tid >> 4;
    int o0 = blockIdx.x * 128, t0 = blockIdx.y * 128;
    const float* Xb = g_mid + (size_t)b * CCH * TSEQ;

    float acc[8][8];
#pragma unroll
    for (int i = 0; i < 8; i++)
#pragma unroll
        for (int j = 0; j < 8; j++) acc[i][j] = 0.f;

    int ao = tid >> 1, ac4 = (tid & 1) * 4;
    int bc = tid >> 5, bt4 = (tid & 31) * 4;

    for (int k0 = 0; k0 < CCH; k0 += 8) {
        float4 a4 = *(const float4*)(Wm + (size_t)(o0 + ao) * CCH + k0 + ac4);
        float4 b4 = *(const float4*)(Xb + (size_t)(k0 + bc) * TSEQ + t0 + bt4);
        As[ac4 + 0][ao] = a4.x; As[ac4 + 1][ao] = a4.y;
        As[ac4 + 2][ao] = a4.z; As[ac4 + 3][ao] = a4.w;
        *(float4*)&Bs[bc][bt4] = b4;
        __syncthreads();
#pragma unroll
        for (int kk = 0; kk < 8; kk++) {
            float ar[8], br[8];
            *(float4*)&ar[0] = *(const float4*)&As[kk][ty * 8];
            *(float4*)&ar[4] = *(const float4*)&As[kk][ty * 8 + 4];
            *(float4*)&br[0] = *(const float4*)&Bs[kk][tx * 8];
            *(float4*)&br[4] = *(const float4*)&Bs[kk][tx * 8 + 4];
#pragma unroll
            for (int i = 0; i < 8; i++)
#pragma unroll
                for (int j = 0; j < 8; j++) acc[i][j] += ar[i] * br[j];
        }
        __syncthreads();
    }

    float* Ob = Out + (size_t)b * CCH * TSEQ;
#pragma unroll
    for (int i = 0; i < 8; i++) {
        int o = o0 + ty * 8 + i;
        float bv = Bi[o];
        float4 r0, r1;
        r0.x = acc[i][0] + bv; r0.y = acc[i][1] + bv;
        r0.z = acc[i][2] + bv; r0.w = acc[i][3] + bv;
        r1.x = acc[i][4] + bv; r1.y = acc[i][5] + bv;
        r1.z = acc[i][6] + bv; r1.w = acc[i][7] + bv;
        *(float4*)(Ob + (size_t)o * TSEQ + t0 + tx * 8) = r0;
        *(float4*)(Ob + (size_t)o * TSEQ + t0 + tx * 8 + 4) = r1;
    }
}

// ---------------------------------------------------------------------------
// Scores: S[bh,i,j] = sum_d q[bh,d,i] * k[bh,d,j]. Both operands are K-major
// in the (B,C,T) layout -> no transposes. K=64 total.
// ---------------------------------------------------------------------------
__global__ __launch_bounds__(256)
void scores_kernel()
{
    __shared__ float As[8][132];
    __shared__ float Bs[8][132];
    int bh = blockIdx.z;
    int b = bh / NH, h = bh % NH;
    int j0 = blockIdx.x * 128, i0 = blockIdx.y * 128;
    const float* qb = g_q + ((size_t)b * CCH + h * HD) * TSEQ;
    const float* kb = g_k + ((size_t)b * CCH + h * HD) * TSEQ;

    int tid = threadIdx.x;
    int tx = tid & 15, ty = tid >> 4;
    int lr = tid >> 5, lc4 = (tid & 31) * 4;

    float acc[8][8];
#pragma unroll
    for (int i = 0; i < 8; i++)
#pragma unroll
        for (int j = 0; j < 8; j++) acc[i][j] = 0.f;

    for (int k0 = 0; k0 < HD; k0 += 8) {
        *(float4*)&As[lr][lc4] = *(const float4*)(qb + (size_t)(k0 + lr) * TSEQ + i0 + lc4);
        *(float4*)&Bs[lr][lc4] = *(const float4*)(kb + (size_t)(k0 + lr) * TSEQ + j0 + lc4);
        __syncthreads();
#pragma unroll
        for (int kk = 0; kk < 8; kk++) {
            float ar[8], br[8];
            *(float4*)&ar[0] = *(const float4*)&As[kk][ty * 8];
            *(float4*)&ar[4] = *(const float4*)&As[kk][ty * 8 + 4];
            *(float4*)&br[0] = *(const float4*)&Bs[kk][tx * 8];
            *(float4*)&br[4] = *(const float4*)&Bs[kk][tx * 8 + 4];
#pragma unroll
            for (int i = 0; i < 8; i++)
#pragma unroll
                for (int j = 0; j < 8; j++) acc[i][j] += ar[i] * br[j];
        }
        __syncthreads();
    }

    float* srow = g_s + (size_t)bh * TSEQ * TSEQ;
#pragma unroll
    for (int i = 0; i < 8; i++) {
        size_t off = (size_t)(i0 + ty * 8 + i) * TSEQ + j0 + tx * 8;
        *(float4*)(srow + off)     = *(float4*)&acc[i][0];
        *(float4*)(srow + off + 4) = *(float4*)&acc[i][4];
    }
}

// ---------------------------------------------------------------------------
// Banded rel-k: S[bh,i,j] += q[bh,:,i] . emb_k[j-i+4] for |j-i| <= 4.
// One warp handles 32 consecutive rows (lane = row), coalesced q reads.
// ---------------------------------------------------------------------------
__global__ __launch_bounds__(256)
void relk_kernel(const float* __restrict__ emb_k)
{
    __shared__ float es[NR * HD];
    int tid = threadIdx.x;
    for (int i = tid; i < NR * HD; i += blockDim.x) es[i] = emb_k[i];
    __syncthreads();

    int gw = blockIdx.x * 8 + (tid >> 5);
    int lane = tid & 31;
    int bh = gw >> 5;                 // 32 warps per (b,h)
    int i = ((gw & 31) << 5) + lane;  // row
    int b = bh / NH, h = bh % NH;
    const float* qb = g_q + ((size_t)b * CCH + h * HD) * TSEQ;

    float acc[NR];
#pragma unroll
    for (int r = 0; r < NR; r++) acc[r] = 0.f;
    for (int d = 0; d < HD; d++) {
        float qv = qb[(size_t)d * TSEQ + i];
#pragma unroll
        for (int r = 0; r < NR; r++) acc[r] += qv * es[r * HD + d];
    }
    float* srow = g_s + (size_t)bh * TSEQ * TSEQ + (size_t)i * TSEQ;
#pragma unroll
    for (int r = 0; r < NR; r++) {
        int j = i + r - NWIN;
        if (j >= 0 && j < TSEQ) srow[j] += acc[r];
    }
}

// ---------------------------------------------------------------------------
// Softmax over j (row length 1024) in-place + banded rel-v projection:
// g_bv[bh,i,d] = sum_r attn[i, i+r-4] * emb_v[r,d]
// ---------------------------------------------------------------------------
__global__ __launch_bounds__(256)
void softmax_kernel(const float* __restrict__ emb_v)
{
    __shared__ float redm[8];
    __shared__ float reds[8];
    __shared__ float band[NR];

    long long row = blockIdx.x;               // 0 .. NBH*TSEQ-1
    float* srow = g_s + row * TSEQ;
    int i = (int)(row & (TSEQ - 1));
    int tid = threadIdx.x;
    int lane = tid & 31, wid = tid >> 5;

    if (tid < NR) band[tid] = 0.f;

    float4 v = *(float4*)(srow + tid * 4);
    float m = fmaxf(fmaxf(v.x, v.y), fmaxf(v.z, v.w));
#pragma unroll
    for (int o = 16; o > 0; o >>= 1) m = fmaxf(m, __shfl_xor_sync(0xffffffffu, m, o));
    if (lane == 0) redm[wid] = m;
    __syncthreads();
    m = redm[0];
#pragma unroll
    for (int w = 1; w < 8; w++) m = fmaxf(m, redm[w]);

    v.x = __expf(v.x - m); v.y = __expf(v.y - m);
    v.z = __expf(v.z - m); v.w = __expf(v.w - m);
    float s = v.x + v.y + v.z + v.w;
#pragma unroll
    for (int o = 16; o > 0; o >>= 1) s += __shfl_xor_sync(0xffffffffu, s, o);
    if (lane == 0) reds[wid] = s;
    __syncthreads();
    s = 0.f;
#pragma unroll
    for (int w = 0; w < 8; w++) s += reds[w];
    float inv = 1.0f / s;
    v.x *= inv; v.y *= inv; v.z *= inv; v.w *= inv;
    *(float4*)(srow + tid * 4) = v;

    // banded attention values -> shared
    float vals[4] = {v.x, v.y, v.z, v.w};
    int jb = tid * 4;
#pragma unroll
    for (int u = 0; u < 4; u++) {
        int r = jb + u - i + NWIN;
        if (r >= 0 && r < NR) band[r] = vals[u];
    }
    __syncthreads();
    if (tid < HD) {
        float acc = 0.f;
#pragma unroll
        for (int r = 0; r < NR; r++) acc += band[r] * emb_v[r * HD + tid];
        g_bv[row * HD + tid] = acc;
    }
}

// ---------------------------------------------------------------------------
// O = attn @ V + bandv, written transposed into g_mid (B,C,T).
// 128(i) x 64(d) tile, BK=16, 128 threads, 8x8 microtile.
// tx indexes i (for coalesced t-writes), ty indexes d.
// ---------------------------------------------------------------------------
__global__ __launch_bounds__(128)
void av_kernel()
{
    __shared__ float As[16][132];  // [j][i]
    __shared__ float Bs[16][68];   // [j][d]
    int bh = blockIdx.y;
    int i0 = blockIdx.x * 128;
    int b = bh / NH, h = bh % NH;
    const float* P  = g_s + (size_t)bh * TSEQ * TSEQ;
    const float* vb = g_v + ((size_t)b * CCH + h * HD) * TSEQ;

    int tid = threadIdx.x;
    int tx = tid & 15, ty = tid >> 4;   // tx: i-group (0..15), ty: d-group (0..7)

    float acc[8][8];  // [ddi][ii]
    const float* bvp = g_bv + ((size_t)bh * TSEQ + i0) * HD;
#pragma unroll
    for (int ii = 0; ii < 8; ii++) {
        float4 u1 = *(const float4*)(bvp + (size_t)(tx * 8 + ii) * HD + ty * 8);
        float4 u2 = *(const float4*)(bvp + (size_t)(tx * 8 + ii) * HD + ty * 8 + 4);
        acc[0][ii] = u1.x; acc[1][ii] = u1.y; acc[2][ii] = u1.z; acc[3][ii] = u1.w;
        acc[4][ii] = u2.x; acc[5][ii] = u2.y; acc[6][ii] = u2.z; acc[7][ii] = u2.w;
    }

    for (int j0 = 0; j0 < TSEQ; j0 += 16) {
        // A: P[i0+ii][j0+j] -> As[j][ii]  (2048 floats, 4 float4 per thread)
#pragma unroll
        for (int mm = 0; mm < 4; mm++) {
            int slot = tid + mm * 128;
            int ii = slot >> 2, j4 = (slot & 3) * 4;
            float4 pv = *(const float4*)(P + (size_t)(i0 + ii) * TSEQ + j0 + j4);
            As[j4 + 0][ii] = pv.x; As[j4 + 1][ii] = pv.y;
            As[j4 + 2][ii] = pv.z; As[j4 + 3][ii] = pv.w;
        }
        // B: v[d][j0+j] -> Bs[j][d]  (1024 floats, 2 float4 per thread)
#pragma unroll
        for (int mm = 0; mm < 2; mm++) {
            int slot = tid + mm * 128;
            int dd = slot >> 2, j4 = (slot & 3) * 4;
            float4 vv = *(const float4*)(vb + (size_t)dd * TSEQ + j0 + j4);
            Bs[j4 + 0][dd] = vv.x; Bs[j4 + 1][dd] = vv.y;
            Bs[j4 + 2][dd] = vv.z; Bs[j4 + 3][dd] = vv.w;
        }
        __syncthreads();
#pragma unroll
        for (int kk = 0; kk < 16; kk++) {
            float ar[8], br[8];
            *(float4*)&ar[0] = *(const float4*)&As[kk][tx * 8];
            *(float4*)&ar[4] = *(const float4*)&As[kk][tx * 8 + 4];
            *(float4*)&br[0] = *(const float4*)&Bs[kk][ty * 8];
            *(float4*)&br[4] = *(const float4*)&Bs[kk][ty * 8 + 4];
#pragma unroll
            for (int d = 0; d < 8; d++)
#pragma unroll
                for (int ii = 0; ii < 8; ii++) acc[d][ii] += br[d] * ar[ii];
        }
        __syncthreads();
    }

    float* outp = g_mid + ((size_t)b * CCH + h * HD) * TSEQ;
#pragma unroll
    for (int d = 0; d < 8; d++) {
        int dd = ty * 8 + d;
        float4 r0, r1;
        r0.x = acc[d][0]; r0.y = acc[d][1]; r0.z = acc[d][2]; r0.w = acc[d][3];
        r1.x = acc[d][4]; r1.y = acc[d][5]; r1.z = acc[d][6]; r1.w = acc[d][7];
        *(float4*)(outp + (size_t)dd * TSEQ + i0 + tx * 8)     = r0;
        *(float4*)(outp + (size_t)dd * TSEQ + i0 + tx * 8 + 4) = r1;
    }
}

// ---------------------------------------------------------------------------
extern "C" void kernel_launch(void* const* d_in, const int* in_sizes, int n_in,
                              void* d_out, int out_size)
{
    const float* x     = (const float*)d_in[0];
    const float* w_q   = (const float*)d_in[1];
    const float* b_q   = (const float*)d_in[2];
    const float* w_k   = (const float*)d_in[3];
    const float* b_k   = (const float*)d_in[4];
    const float* w_v   = (const float*)d_in[5];
    const float* b_v   = (const float*)d_in[6];
    const float* w_o   = (const float*)d_in[7];
    const float* b_o   = (const float*)d_in[8];
    const float* emb_k = (const float*)d_in[9];
    const float* emb_v = (const float*)d_in[10];
    float* out = (float*)d_out;

    dim3 gq(CCH / 128, TSEQ / 128, BB * 3);
    qkv_kernel<<<gq, 256>>>(x, w_q, b_q, w_k, b_k, w_v, b_v);

    dim3 gs(TSEQ / 128, TSEQ / 128, NBH);
    scores_kernel<<<gs, 256>>>();

    relk_kernel<<<NBH * TSEQ / 32 / 8, 256>>>(emb_k);

    softmax_kernel<<<NBH * TSEQ, 256>>>(emb_v);

    dim3 gav(TSEQ / 128, NBH);
    av_kernel<<<gav, 128>>>();

    dim3 go(CCH / 128, TSEQ / 128, BB);
    oproj_kernel<<<go, 256>>>(w_o, b_o, out);
}

// round 6
// speedup vs baseline: 1.8231x; 1.8231x over previous
#include <cuda_runtime.h>
#include <math.h>
#include <stdint.h>

#define BB   4
#define TSEQ 1024
#define CCH  768
#define NH   12
#define HD   64
#define NWIN 4
#define NR   9
#define NBH  (BB*NH)   // 48

// Scratch (static __device__ arrays per allocation rules)
static __device__ float g_q[BB*CCH*TSEQ];     // (B, C, T) == (b,h,d,t), q pre-scaled by 1/8
static __device__ float g_k[BB*CCH*TSEQ];
static __device__ float g_v[BB*CCH*TSEQ];
static __device__ float g_mid[BB*CCH*TSEQ];   // attention output, (B, C, T)
static __device__ float g_bv[NBH*TSEQ*HD];    // banded rel-v contribution, (bh, i, d)
static __device__ float g_s[50331648];        // scores/attn, (bh, i, j)

// ---------------------------------------------------------------------------
// tf32 helpers
// ---------------------------------------------------------------------------
__device__ __forceinline__ uint32_t f2tf(float x) {
    uint32_t u;
    asm("cvt.rna.tf32.f32 %0, %1;" : "=r"(u) : "f"(x));
    return u;
}
__device__ __forceinline__ uint4 cvt4(float4 v) {
    uint4 u; u.x = f2tf(v.x); u.y = f2tf(v.y); u.z = f2tf(v.z); u.w = f2tf(v.w);
    return u;
}
__device__ __forceinline__ void mma_tf32(float c[4], const uint32_t a[4], const uint32_t b[2]) {
    asm volatile(
        "mma.sync.aligned.m16n8k8.row.col.f32.tf32.tf32.f32 "
        "{%0,%1,%2,%3}, {%4,%5,%6,%7}, {%8,%9}, {%0,%1,%2,%3};\n"
        : "+f"(c[0]), "+f"(c[1]), "+f"(c[2]), "+f"(c[3])
        : "r"(a[0]), "r"(a[1]), "r"(a[2]), "r"(a[3]), "r"(b[0]), "r"(b[1]));
}

// ---------------------------------------------------------------------------
// Projection GEMM body: Out[o,t] = (sum_c W[o,c]*X[c,t] + bias[o]) * scale
// 128x128 block, BK=16, 8 warps (4m x 2n), warp tile 32x64, tf32 MMA.
// A = W row-major [o][c]; B = X row-major over t: [c][t].
// ---------------------------------------------------------------------------
__device__ __forceinline__ void proj_body(
    const float* __restrict__ X, const float* __restrict__ W,
    const float* __restrict__ bias, float* __restrict__ Out, float scale)
{
    __shared__ uint32_t As[2][128 * 20];   // [m][k], stride 20
    __shared__ uint32_t Bs[2][16 * 136];   // [k][n], stride 136

    int tid = threadIdx.x;
    int lane = tid & 31, wid = tid >> 5;
    int wm = wid >> 1, wn = wid & 1;
    int gid = lane >> 2, tig = lane & 3;
    int o0 = blockIdx.x * 128, t0 = blockIdx.y * 128;

    float c[2][8][4];
#pragma unroll
    for (int f = 0; f < 2; f++)
#pragma unroll
        for (int n = 0; n < 8; n++)
#pragma unroll
            for (int q = 0; q < 4; q++) c[f][n][q] = 0.f;

    float4 al[2], bl[2];

    auto load_g = [&](int k0) {
#pragma unroll
        for (int p = 0; p < 2; p++) {
            int fl = tid + p * 256;
            al[p] = *(const float4*)(W + (size_t)(o0 + (fl >> 2)) * CCH + k0 + (fl & 3) * 4);
            bl[p] = *(const float4*)(X + (size_t)(k0 + (fl >> 5)) * TSEQ + t0 + (fl & 31) * 4);
        }
    };
    auto sts = [&](int buf) {
#pragma unroll
        for (int p = 0; p < 2; p++) {
            int fl = tid + p * 256;
            *(uint4*)&As[buf][(fl >> 2) * 20 + (fl & 3) * 4] = cvt4(al[p]);
            *(uint4*)&Bs[buf][(fl >> 5) * 136 + (fl & 31) * 4] = cvt4(bl[p]);
        }
    };

    load_g(0); sts(0); __syncthreads();
    const int NS = CCH / 16;
    for (int s = 0; s < NS; s++) {
        int cur = s & 1;
        if (s + 1 < NS) load_g((s + 1) * 16);
#pragma unroll
        for (int kk = 0; kk < 16; kk += 8) {
            uint32_t a[2][4], b[8][2];
#pragma unroll
            for (int f = 0; f < 2; f++) {
                int rb = wm * 32 + f * 16 + gid;
                a[f][0] = As[cur][rb * 20 + kk + tig];
                a[f][1] = As[cur][(rb + 8) * 20 + kk + tig];
                a[f][2] = As[cur][rb * 20 + kk + tig + 4];
                a[f][3] = As[cur][(rb + 8) * 20 + kk + tig + 4];
            }
#pragma unroll
            for (int n = 0; n < 8; n++) {
                int col = wn * 64 + n * 8 + gid;
                b[n][0] = Bs[cur][(kk + tig) * 136 + col];
                b[n][1] = Bs[cur][(kk + tig + 4) * 136 + col];
            }
#pragma unroll
            for (int f = 0; f < 2; f++)
#pragma unroll
                for (int n = 0; n < 8; n++) mma_tf32(c[f][n], a[f], b[n]);
        }
        if (s + 1 < NS) sts(cur ^ 1);
        __syncthreads();
    }

#pragma unroll
    for (int f = 0; f < 2; f++) {
        int ro = o0 + wm * 32 + f * 16 + gid;
        float bv0 = bias[ro], bv1 = bias[ro + 8];
#pragma unroll
        for (int n = 0; n < 8; n++) {
            int col = t0 + wn * 64 + n * 8 + 2 * tig;
            *(float2*)(Out + (size_t)ro * TSEQ + col) =
                make_float2((c[f][n][0] + bv0) * scale, (c[f][n][1] + bv0) * scale);
            *(float2*)(Out + (size_t)(ro + 8) * TSEQ + col) =
                make_float2((c[f][n][2] + bv1) * scale, (c[f][n][3] + bv1) * scale);
        }
    }
}

__global__ __launch_bounds__(256, 1)
void qkv_kernel(const float* __restrict__ X,
                const float* __restrict__ Wq, const float* __restrict__ Bq,
                const float* __restrict__ Wk, const float* __restrict__ Bk,
                const float* __restrict__ Wv, const float* __restrict__ Bv)
{
    int zb = blockIdx.z;
    int b = zb / 3, which = zb % 3;
    const float* Wm = (which == 0) ? Wq : ((which == 1) ? Wk : Wv);
    const float* Bi = (which == 0) ? Bq : ((which == 1) ? Bk : Bv);
    float* Out = (which == 0) ? g_q : ((which == 1) ? g_k : g_v);
    float scale = (which == 0) ? 0.125f : 1.0f;
    proj_body(X + (size_t)b * CCH * TSEQ, Wm, Bi, Out + (size_t)b * CCH * TSEQ, scale);
}

__global__ __launch_bounds__(256, 1)
void oproj_kernel(const float* __restrict__ Wm, const float* __restrict__ Bi,
                  float* __restrict__ Out)
{
    int b = blockIdx.z;
    proj_body(g_mid + (size_t)b * CCH * TSEQ, Wm, Bi, Out + (size_t)b * CCH * TSEQ, 1.0f);
}

// ---------------------------------------------------------------------------
// Scores: S[bh,i,j] = sum_d q[bh,d,i] * k[bh,d,j]. K=64, tf32 MMA.
// A col-major (q is [d][i]) -> As stored [k][m] stride 136. B direct [k][n].
// ---------------------------------------------------------------------------
__global__ __launch_bounds__(256, 1)
void scores_kernel()
{
    __shared__ uint32_t As[2][16 * 136];
    __shared__ uint32_t Bs[2][16 * 136];

    int bh = blockIdx.z;
    int b = bh / NH, h = bh % NH;
    int j0 = blockIdx.x * 128, i0 = blockIdx.y * 128;
    const float* qb = g_q + ((size_t)b * CCH + h * HD) * TSEQ;
    const float* kb = g_k + ((size_t)b * CCH + h * HD) * TSEQ;

    int tid = threadIdx.x;
    int lane = tid & 31, wid = tid >> 5;
    int wm = wid >> 1, wn = wid & 1;
    int gid = lane >> 2, tig = lane & 3;

    float c[2][8][4];
#pragma unroll
    for (int f = 0; f < 2; f++)
#pragma unroll
        for (int n = 0; n < 8; n++)
#pragma unroll
            for (int q = 0; q < 4; q++) c[f][n][q] = 0.f;

    float4 al[2], bl[2];
    auto load_g = [&](int k0) {
#pragma unroll
        for (int p = 0; p < 2; p++) {
            int fl = tid + p * 256;
            al[p] = *(const float4*)(qb + (size_t)(k0 + (fl >> 5)) * TSEQ + i0 + (fl & 31) * 4);
            bl[p] = *(const float4*)(kb + (size_t)(k0 + (fl >> 5)) * TSEQ + j0 + (fl & 31) * 4);
        }
    };
    auto sts = [&](int buf) {
#pragma unroll
        for (int p = 0; p < 2; p++) {
            int fl = tid + p * 256;
            *(uint4*)&As[buf][(fl >> 5) * 136 + (fl & 31) * 4] = cvt4(al[p]);
            *(uint4*)&Bs[buf][(fl >> 5) * 136 + (fl & 31) * 4] = cvt4(bl[p]);
        }
    };

    load_g(0); sts(0); __syncthreads();
    const int NS = HD / 16;   // 4
    for (int s = 0; s < NS; s++) {
        int cur = s & 1;
        if (s + 1 < NS) load_g((s + 1) * 16);
#pragma unroll
        for (int kk = 0; kk < 16; kk += 8) {
            uint32_t a[2][4], b[8][2];
#pragma unroll
            for (int f = 0; f < 2; f++) {
                int mb = wm * 32 + f * 16 + gid;
                a[f][0] = As[cur][(kk + tig) * 136 + mb];
                a[f][1] = As[cur][(kk + tig) * 136 + mb + 8];
                a[f][2] = As[cur][(kk + tig + 4) * 136 + mb];
                a[f][3] = As[cur][(kk + tig + 4) * 136 + mb + 8];
            }
#pragma unroll
            for (int n = 0; n < 8; n++) {
                int col = wn * 64 + n * 8 + gid;
                b[n][0] = Bs[cur][(kk + tig) * 136 + col];
                b[n][1] = Bs[cur][(kk + tig + 4) * 136 + col];
            }
#pragma unroll
            for (int f = 0; f < 2; f++)
#pragma unroll
                for (int n = 0; n < 8; n++) mma_tf32(c[f][n], a[f], b[n]);
        }
        if (s + 1 < NS) sts(cur ^ 1);
        __syncthreads();
    }

    float* srow = g_s + (size_t)bh * TSEQ * TSEQ;
#pragma unroll
    for (int f = 0; f < 2; f++) {
        int ri = i0 + wm * 32 + f * 16 + gid;
#pragma unroll
        for (int n = 0; n < 8; n++) {
            int col = j0 + wn * 64 + n * 8 + 2 * tig;
            *(float2*)(srow + (size_t)ri * TSEQ + col) = make_float2(c[f][n][0], c[f][n][1]);
            *(float2*)(srow + (size_t)(ri + 8) * TSEQ + col) = make_float2(c[f][n][2], c[f][n][3]);
        }
    }
}

// ---------------------------------------------------------------------------
// Banded rel-k: S[bh,i,j] += q[bh,:,i] . emb_k[j-i+4] for |j-i| <= 4.
// ---------------------------------------------------------------------------
__global__ __launch_bounds__(256)
void relk_kernel(const float* __restrict__ emb_k)
{
    __shared__ float es[NR * HD];
    int tid = threadIdx.x;
    for (int i = tid; i < NR * HD; i += blockDim.x) es[i] = emb_k[i];
    __syncthreads();

    int gw = blockIdx.x * 8 + (tid >> 5);
    int lane = tid & 31;
    int bh = gw >> 5;
    int i = ((gw & 31) << 5) + lane;
    int b = bh / NH, h = bh % NH;
    const float* qb = g_q + ((size_t)b * CCH + h * HD) * TSEQ;

    float acc[NR];
#pragma unroll
    for (int r = 0; r < NR; r++) acc[r] = 0.f;
    for (int d = 0; d < HD; d++) {
        float qv = qb[(size_t)d * TSEQ + i];
#pragma unroll
        for (int r = 0; r < NR; r++) acc[r] += qv * es[r * HD + d];
    }
    float* srow = g_s + (size_t)bh * TSEQ * TSEQ + (size_t)i * TSEQ;
#pragma unroll
    for (int r = 0; r < NR; r++) {
        int j = i + r - NWIN;
        if (j >= 0 && j < TSEQ) srow[j] += acc[r];
    }
}

// ---------------------------------------------------------------------------
// Softmax over j in-place + banded rel-v projection into g_bv (bh,i,d).
// ---------------------------------------------------------------------------
__global__ __launch_bounds__(256)
void softmax_kernel(const float* __restrict__ emb_v)
{
    __shared__ float redm[8];
    __shared__ float reds[8];
    __shared__ float band[NR];

    long long row = blockIdx.x;
    float* srow = g_s + row * TSEQ;
    int i = (int)(row & (TSEQ - 1));
    int tid = threadIdx.x;
    int lane = tid & 31, wid = tid >> 5;

    if (tid < NR) band[tid] = 0.f;

    float4 v = *(float4*)(srow + tid * 4);
    float m = fmaxf(fmaxf(v.x, v.y), fmaxf(v.z, v.w));
#pragma unroll
    for (int o = 16; o > 0; o >>= 1) m = fmaxf(m, __shfl_xor_sync(0xffffffffu, m, o));
    if (lane == 0) redm[wid] = m;
    __syncthreads();
    m = redm[0];
#pragma unroll
    for (int w = 1; w < 8; w++) m = fmaxf(m, redm[w]);

    v.x = __expf(v.x - m); v.y = __expf(v.y - m);
    v.z = __expf(v.z - m); v.w = __expf(v.w - m);
    float s = v.x + v.y + v.z + v.w;
#pragma unroll
    for (int o = 16; o > 0; o >>= 1) s += __shfl_xor_sync(0xffffffffu, s, o);
    if (lane == 0) reds[wid] = s;
    __syncthreads();
    s = 0.f;
#pragma unroll
    for (int w = 0; w < 8; w++) s += reds[w];
    float inv = 1.0f / s;
    v.x *= inv; v.y *= inv; v.z *= inv; v.w *= inv;
    *(float4*)(srow + tid * 4) = v;

    float vals[4] = {v.x, v.y, v.z, v.w};
    int jb = tid * 4;
#pragma unroll
    for (int u = 0; u < 4; u++) {
        int r = jb + u - i + NWIN;
        if (r >= 0 && r < NR) band[r] = vals[u];
    }
    __syncthreads();
    if (tid < HD) {
        float acc = 0.f;
#pragma unroll
        for (int r = 0; r < NR; r++) acc += band[r] * emb_v[r * HD + tid];
        g_bv[row * HD + tid] = acc;
    }
}

// ---------------------------------------------------------------------------
// O = attn @ V + bandv, written transposed into g_mid (B,C,T), tf32 MMA.
// C[m=d, n=i]: A = v [d][j] row-major; B = P[i][j] -> col-major [k=j][n=i].
// Block 64(m) x 128(n), BK=16, 4 warps (2m x 2n), warp tile 32x64.
// ---------------------------------------------------------------------------
__global__ __launch_bounds__(128, 1)
void av_kernel()
{
    __shared__ uint32_t As[2][64 * 20];    // [m=d][k], stride 20
    __shared__ uint32_t Bs[2][128 * 20];   // [n=i][k], stride 20

    int bh = blockIdx.y;
    int i0 = blockIdx.x * 128;
    int b = bh / NH, h = bh % NH;
    const float* P  = g_s + (size_t)bh * TSEQ * TSEQ;
    const float* vb = g_v + ((size_t)b * CCH + h * HD) * TSEQ;
    const float* bvp = g_bv + (size_t)bh * TSEQ * HD;

    int tid = threadIdx.x;
    int lane = tid & 31, wid = tid >> 5;
    int wm = wid >> 1, wn = wid & 1;
    int gid = lane >> 2, tig = lane & 3;

    float c[2][8][4];
#pragma unroll
    for (int f = 0; f < 2; f++)
#pragma unroll
        for (int n = 0; n < 8; n++)
#pragma unroll
            for (int q = 0; q < 4; q++) c[f][n][q] = 0.f;

    float4 al[2], bl[4];
    auto load_g = [&](int k0) {
#pragma unroll
        for (int p = 0; p < 2; p++) {
            int fl = tid + p * 128;
            al[p] = *(const float4*)(vb + (size_t)(fl >> 2) * TSEQ + k0 + (fl & 3) * 4);
        }
#pragma unroll
        for (int p = 0; p < 4; p++) {
            int fl = tid + p * 128;
            bl[p] = *(const float4*)(P + (size_t)(i0 + (fl >> 2)) * TSEQ + k0 + (fl & 3) * 4);
        }
    };
    auto sts = [&](int buf) {
#pragma unroll
        for (int p = 0; p < 2; p++) {
            int fl = tid + p * 128;
            *(uint4*)&As[buf][(fl >> 2) * 20 + (fl & 3) * 4] = cvt4(al[p]);
        }
#pragma unroll
        for (int p = 0; p < 4; p++) {
            int fl = tid + p * 128;
            *(uint4*)&Bs[buf][(fl >> 2) * 20 + (fl & 3) * 4] = cvt4(bl[p]);
        }
    };

    load_g(0); sts(0); __syncthreads();
    const int NS = TSEQ / 16;   // 64
    for (int s = 0; s < NS; s++) {
        int cur = s & 1;
        if (s + 1 < NS) load_g((s + 1) * 16);
#pragma unroll
        for (int kk = 0; kk < 16; kk += 8) {
            uint32_t a[2][4], b[8][2];
#pragma unroll
            for (int f = 0; f < 2; f++) {
                int rb = wm * 32 + f * 16 + gid;
                a[f][0] = As[cur][rb * 20 + kk + tig];
                a[f][1] = As[cur][(rb + 8) * 20 + kk + tig];
                a[f][2] = As[cur][rb * 20 + kk + tig + 4];
                a[f][3] = As[cur][(rb + 8) * 20 + kk + tig + 4];
            }
#pragma unroll
            for (int n = 0; n < 8; n++) {
                int coln = wn * 64 + n * 8 + gid;
                b[n][0] = Bs[cur][coln * 20 + kk + tig];
                b[n][1] = Bs[cur][coln * 20 + kk + tig + 4];
            }
#pragma unroll
            for (int f = 0; f < 2; f++)
#pragma unroll
                for (int n = 0; n < 8; n++) mma_tf32(c[f][n], a[f], b[n]);
        }
        if (s + 1 < NS) sts(cur ^ 1);
        __syncthreads();
    }

    float* om = g_mid + ((size_t)b * CCH + h * HD) * TSEQ;
#pragma unroll
    for (int f = 0; f < 2; f++) {
        int rd = wm * 32 + f * 16 + gid;
#pragma unroll
        for (int n = 0; n < 8; n++) {
            int ci = i0 + wn * 64 + n * 8 + 2 * tig;
            float v0 = c[f][n][0] + bvp[(size_t)ci * HD + rd];
            float v1 = c[f][n][1] + bvp[(size_t)(ci + 1) * HD + rd];
            float v2 = c[f][n][2] + bvp[(size_t)ci * HD + rd + 8];
            float v3 = c[f][n][3] + bvp[(size_t)(ci + 1) * HD + rd + 8];
            *(float2*)(om + (size_t)rd * TSEQ + ci) = make_float2(v0, v1);
            *(float2*)(om + (size_t)(rd + 8) * TSEQ + ci) = make_float2(v2, v3);
        }
    }
}

// ---------------------------------------------------------------------------
extern "C" void kernel_launch(void* const* d_in, const int* in_sizes, int n_in,
                              void* d_out, int out_size)
{
    const float* x     = (const float*)d_in[0];
    const float* w_q   = (const float*)d_in[1];
    const float* b_q   = (const float*)d_in[2];
    const float* w_k   = (const float*)d_in[3];
    const float* b_k   = (const float*)d_in[4];
    const float* w_v   = (const float*)d_in[5];
    const float* b_v   = (const float*)d_in[6];
    const float* w_o   = (const float*)d_in[7];
    const float* b_o   = (const float*)d_in[8];
    const float* emb_k = (const float*)d_in[9];
    const float* emb_v = (const float*)d_in[10];
    float* out = (float*)d_out;

    dim3 gq(CCH / 128, TSEQ / 128, BB * 3);
    qkv_kernel<<<gq, 256>>>(x, w_q, b_q, w_k, b_k, w_v, b_v);

    dim3 gs(TSEQ / 128, TSEQ / 128, NBH);
    scores_kernel<<<gs, 256>>>();

    relk_kernel<<<NBH * TSEQ / 32 / 8, 256>>>(emb_k);

    softmax_kernel<<<NBH * TSEQ, 256>>>(emb_v);

    dim3 gav(TSEQ / 128, NBH);
    av_kernel<<<gav, 128>>>();

    dim3 go(CCH / 128, TSEQ / 128, BB);
    oproj_kernel<<<go, 256>>>(w_o, b_o, out);
}

// round 7
// speedup vs baseline: 2.5341x; 1.3900x over previous
#include <cuda_runtime.h>
#include <math.h>
#include <stdint.h>

#define BB   4
#define TSEQ 1024
#define CCH  768
#define NH   12
#define HD   64
#define NWIN 4
#define NR   9
#define NBH  (BB*NH)   // 48

// Scratch (static __device__ arrays per allocation rules)
static __device__ float g_q[BB*CCH*TSEQ];     // (B, C, T) == (b,h,d,t), q pre-scaled by 1/8
static __device__ float g_k[BB*CCH*TSEQ];
static __device__ float g_v[BB*CCH*TSEQ];
static __device__ float g_mid[BB*CCH*TSEQ];   // attention output, (B, C, T)

// ---------------------------------------------------------------------------
// tf32 helpers
// ---------------------------------------------------------------------------
__device__ __forceinline__ uint32_t f2tf(float x) {
    uint32_t u;
    asm("cvt.rna.tf32.f32 %0, %1;" : "=r"(u) : "f"(x));
    return u;
}
__device__ __forceinline__ uint4 cvt4(float4 v) {
    uint4 u; u.x = f2tf(v.x); u.y = f2tf(v.y); u.z = f2tf(v.z); u.w = f2tf(v.w);
    return u;
}
__device__ __forceinline__ void mma_tf32(float c[4], const uint32_t a[4], const uint32_t b[2]) {
    asm volatile(
        "mma.sync.aligned.m16n8k8.row.col.f32.tf32.tf32.f32 "
        "{%0,%1,%2,%3}, {%4,%5,%6,%7}, {%8,%9}, {%0,%1,%2,%3};\n"
        : "+f"(c[0]), "+f"(c[1]), "+f"(c[2]), "+f"(c[3])
        : "r"(a[0]), "r"(a[1]), "r"(a[2]), "r"(a[3]), "r"(b[0]), "r"(b[1]));
}

// ---------------------------------------------------------------------------
// Projection GEMM body (unchanged): Out = (W @ X + bias) * scale, tf32 MMA
// ---------------------------------------------------------------------------
__device__ __forceinline__ void proj_body(
    const float* __restrict__ X, const float* __restrict__ W,
    const float* __restrict__ bias, float* __restrict__ Out, float scale)
{
    __shared__ uint32_t As[2][128 * 20];   // [m][k], stride 20
    __shared__ uint32_t Bs[2][16 * 136];   // [k][n], stride 136

    int tid = threadIdx.x;
    int lane = tid & 31, wid = tid >> 5;
    int wm = wid >> 1, wn = wid & 1;
    int gid = lane >> 2, tig = lane & 3;
    int o0 = blockIdx.x * 128, t0 = blockIdx.y * 128;

    float c[2][8][4];
#pragma unroll
    for (int f = 0; f < 2; f++)
#pragma unroll
        for (int n = 0; n < 8; n++)
#pragma unroll
            for (int q = 0; q < 4; q++) c[f][n][q] = 0.f;

    float4 al[2], bl[2];

    auto load_g = [&](int k0) {
#pragma unroll
        for (int p = 0; p < 2; p++) {
            int fl = tid + p * 256;
            al[p] = *(const float4*)(W + (size_t)(o0 + (fl >> 2)) * CCH + k0 + (fl & 3) * 4);
            bl[p] = *(const float4*)(X + (size_t)(k0 + (fl >> 5)) * TSEQ + t0 + (fl & 31) * 4);
        }
    };
    auto sts = [&](int buf) {
#pragma unroll
        for (int p = 0; p < 2; p++) {
            int fl = tid + p * 256;
            *(uint4*)&As[buf][(fl >> 2) * 20 + (fl & 3) * 4] = cvt4(al[p]);
            *(uint4*)&Bs[buf][(fl >> 5) * 136 + (fl & 31) * 4] = cvt4(bl[p]);
        }
    };

    load_g(0); sts(0); __syncthreads();
    const int NS = CCH / 16;
    for (int s = 0; s < NS; s++) {
        int cur = s & 1;
        if (s + 1 < NS) load_g((s + 1) * 16);
#pragma unroll
        for (int kk = 0; kk < 16; kk += 8) {
            uint32_t a[2][4], b[8][2];
#pragma unroll
            for (int f = 0; f < 2; f++) {
                int rb = wm * 32 + f * 16 + gid;
                a[f][0] = As[cur][rb * 20 + kk + tig];
                a[f][1] = As[cur][(rb + 8) * 20 + kk + tig];
                a[f][2] = As[cur][rb * 20 + kk + tig + 4];
                a[f][3] = As[cur][(rb + 8) * 20 + kk + tig + 4];
            }
#pragma unroll
            for (int n = 0; n < 8; n++) {
                int col = wn * 64 + n * 8 + gid;
                b[n][0] = Bs[cur][(kk + tig) * 136 + col];
                b[n][1] = Bs[cur][(kk + tig + 4) * 136 + col];
            }
#pragma unroll
            for (int f = 0; f < 2; f++)
#pragma unroll
                for (int n = 0; n < 8; n++) mma_tf32(c[f][n], a[f], b[n]);
        }
        if (s + 1 < NS) sts(cur ^ 1);
        __syncthreads();
    }

#pragma unroll
    for (int f = 0; f < 2; f++) {
        int ro = o0 + wm * 32 + f * 16 + gid;
        float bv0 = bias[ro], bv1 = bias[ro + 8];
#pragma unroll
        for (int n = 0; n < 8; n++) {
            int col = t0 + wn * 64 + n * 8 + 2 * tig;
            *(float2*)(Out + (size_t)ro * TSEQ + col) =
                make_float2((c[f][n][0] + bv0) * scale, (c[f][n][1] + bv0) * scale);
            *(float2*)(Out + (size_t)(ro + 8) * TSEQ + col) =
                make_float2((c[f][n][2] + bv1) * scale, (c[f][n][3] + bv1) * scale);
        }
    }
}

__global__ __launch_bounds__(256, 1)
void qkv_kernel(const float* __restrict__ X,
                const float* __restrict__ Wq, const float* __restrict__ Bq,
                const float* __restrict__ Wk, const float* __restrict__ Bk,
                const float* __restrict__ Wv, const float* __restrict__ Bv)
{
    int zb = blockIdx.z;
    int b = zb / 3, which = zb % 3;
    const float* Wm = (which == 0) ? Wq : ((which == 1) ? Wk : Wv);
    const float* Bi = (which == 0) ? Bq : ((which == 1) ? Bk : Bv);
    float* Out = (which == 0) ? g_q : ((which == 1) ? g_k : g_v);
    float scale = (which == 0) ? 0.125f : 1.0f;
    proj_body(X + (size_t)b * CCH * TSEQ, Wm, Bi, Out + (size_t)b * CCH * TSEQ, scale);
}

__global__ __launch_bounds__(256, 1)
void oproj_kernel(const float* __restrict__ Wm, const float* __restrict__ Bi,
                  float* __restrict__ Out)
{
    int b = blockIdx.z;
    proj_body(g_mid + (size_t)b * CCH * TSEQ, Wm, Bi, Out + (size_t)b * CCH * TSEQ, 1.0f);
}

// ---------------------------------------------------------------------------
// Fused flash attention: scores + rel-k + softmax + rel-v + AV in one kernel.
// Block = (bh, 128-row i-tile), 256 threads (8 warps).
// S phase: warp w owns rows w*16..w*16+15 across all 128 j (16 n-subtiles).
// AV phase: C[m=d 64][n=i 128], warps 2m x 4n, warp tile 32x32.
// Online softmax across 8 j-tiles. Output written to g_mid [d][i].
// ---------------------------------------------------------------------------
#define ATTN_SMEM 189440

__global__ __launch_bounds__(256, 1)
void attn_kernel(const float* __restrict__ emb_k, const float* __restrict__ emb_v)
{
    extern __shared__ char smc[];
    uint32_t* Qs = (uint32_t*)smc;          // [k=d 64][m=i 128] stride 136
    uint32_t* Ks = Qs + 64 * 136;           // [k=d 64][n=j 128] stride 136
    uint32_t* Vs = Ks + 64 * 136;           // [m=d 64][k=j 128] stride 132
    uint32_t* Ps = Vs + 64 * 132;           // [n=i 128][k=j 128] stride 132
    float* Rk  = (float*)(Ps + 128 * 132);  // [128][12] : q_i . emb_k[r]
    float* bnd = Rk + 128 * 12;             // [128][12] : raw band scores -> pb
    float* ek  = bnd + 128 * 12;            // [9][64]
    float* ev  = ek + NR * HD;              // [9][64]
    float* sc  = ev + NR * HD;              // [128] per-tile rescale
    float* mf  = sc + 128;                  // [128] final max
    float* li  = mf + 128;                  // [128] 1/l

    int bh = blockIdx.y;
    int i0 = blockIdx.x * 128;
    int b = bh / NH, h = bh % NH;
    const float* qb = g_q + ((size_t)b * CCH + h * HD) * TSEQ;
    const float* kb = g_k + ((size_t)b * CCH + h * HD) * TSEQ;
    const float* vb = g_v + ((size_t)b * CCH + h * HD) * TSEQ;

    int tid = threadIdx.x;
    int lane = tid & 31, wid = tid >> 5;
    int gid = lane >> 2, tig = lane & 3;
    int wm2 = wid >> 2, wn2 = wid & 3;   // AV warp coords

    // ---- block init: Q tile, embeddings, band init ----
#pragma unroll
    for (int p = 0; p < 8; p++) {
        int fl = tid + p * 256;
        int d = fl >> 5, c4 = (fl & 31) * 4;
        float4 v = *(const float4*)(qb + (size_t)d * TSEQ + i0 + c4);
        *(uint4*)&Qs[d * 136 + c4] = cvt4(v);
    }
    for (int idx = tid; idx < NR * HD; idx += 256) { ek[idx] = emb_k[idx]; ev[idx] = emb_v[idx]; }
    for (int idx = tid; idx < 128 * 12; idx += 256) bnd[idx] = -1e30f;
    __syncthreads();

    // Rk[i][r] = sum_d q[d][i] * emb_k[r][d]   (q already tf32-rounded, ok)
    for (int idx = tid; idx < 128 * NR; idx += 256) {
        int i = idx / NR, r = idx - i * NR;
        float acc = 0.f;
#pragma unroll
        for (int d = 0; d < HD; d++)
            acc += __uint_as_float(Qs[d * 136 + i]) * ek[r * HD + d];
        Rk[i * 12 + r] = acc;
    }
    __syncthreads();

    float ms0 = -1e30f, ms1 = -1e30f, ls0 = 0.f, ls1 = 0.f;
    float o[2][4][4];
#pragma unroll
    for (int f = 0; f < 2; f++)
#pragma unroll
        for (int n = 0; n < 4; n++)
#pragma unroll
            for (int q = 0; q < 4; q++) o[f][n][q] = 0.f;

    for (int jt = 0; jt < 8; jt++) {
        int j0 = jt * 128;
        // ---- load K, V tiles ----
#pragma unroll
        for (int p = 0; p < 8; p++) {
            int fl = tid + p * 256;
            int d = fl >> 5, c4 = (fl & 31) * 4;
            float4 kv = *(const float4*)(kb + (size_t)d * TSEQ + j0 + c4);
            float4 vv = *(const float4*)(vb + (size_t)d * TSEQ + j0 + c4);
            *(uint4*)&Ks[d * 136 + c4] = cvt4(kv);
            *(uint4*)&Vs[d * 132 + c4] = cvt4(vv);
        }
        __syncthreads();

        // ---- S = Q.K MMA: warp wid owns rows wid*16..+16 ----
        float c[16][4];
#pragma unroll
        for (int n = 0; n < 16; n++)
#pragma unroll
            for (int q = 0; q < 4; q++) c[n][q] = 0.f;

        int mb = wid * 16 + gid;
#pragma unroll
        for (int ks = 0; ks < 8; ks++) {
            int k0 = ks * 8;
            uint32_t a[4];
            a[0] = Qs[(k0 + tig) * 136 + mb];
            a[1] = Qs[(k0 + tig) * 136 + mb + 8];
            a[2] = Qs[(k0 + tig + 4) * 136 + mb];
            a[3] = Qs[(k0 + tig + 4) * 136 + mb + 8];
#pragma unroll
            for (int n = 0; n < 16; n++) {
                uint32_t bb[2];
                bb[0] = Ks[(k0 + tig) * 136 + n * 8 + gid];
                bb[1] = Ks[(k0 + tig + 4) * 136 + n * 8 + gid];
                mma_tf32(c[n], a, bb);
            }
        }

        // ---- rel-k add + raw band stash (near-diagonal tiles only) ----
        int dj = j0 - i0;
        if (dj <= 128 && dj >= -128) {
#pragma unroll
            for (int n = 0; n < 16; n++) {
#pragma unroll
                for (int q = 0; q < 4; q++) {
                    int ir = wid * 16 + gid + ((q >> 1) << 3);
                    int jc = n * 8 + 2 * tig + (q & 1);
                    int r = dj + jc - ir + NWIN;
                    if (r >= 0 && r < NR) {
                        c[n][q] += Rk[ir * 12 + r];
                        bnd[ir * 12 + r] = c[n][q];
                    }
                }
            }
        }

        // ---- online softmax ----
        float mx0 = -1e30f, mx1 = -1e30f;
#pragma unroll
        for (int n = 0; n < 16; n++) {
            mx0 = fmaxf(mx0, fmaxf(c[n][0], c[n][1]));
            mx1 = fmaxf(mx1, fmaxf(c[n][2], c[n][3]));
        }
        mx0 = fmaxf(mx0, __shfl_xor_sync(0xffffffffu, mx0, 1));
        mx0 = fmaxf(mx0, __shfl_xor_sync(0xffffffffu, mx0, 2));
        mx1 = fmaxf(mx1, __shfl_xor_sync(0xffffffffu, mx1, 1));
        mx1 = fmaxf(mx1, __shfl_xor_sync(0xffffffffu, mx1, 2));
        float nm0 = fmaxf(ms0, mx0), nm1 = fmaxf(ms1, mx1);
        float al0 = __expf(ms0 - nm0), al1 = __expf(ms1 - nm1);

        float s0 = 0.f, s1 = 0.f;
#pragma unroll
        for (int n = 0; n < 16; n++) {
            c[n][0] = __expf(c[n][0] - nm0); s0 += c[n][0];
            c[n][1] = __expf(c[n][1] - nm0); s0 += c[n][1];
            c[n][2] = __expf(c[n][2] - nm1); s1 += c[n][2];
            c[n][3] = __expf(c[n][3] - nm1); s1 += c[n][3];
        }
        s0 += __shfl_xor_sync(0xffffffffu, s0, 1);
        s0 += __shfl_xor_sync(0xffffffffu, s0, 2);
        s1 += __shfl_xor_sync(0xffffffffu, s1, 1);
        s1 += __shfl_xor_sync(0xffffffffu, s1, 2);
        ls0 = ls0 * al0 + s0;
        ls1 = ls1 * al1 + s1;
        ms0 = nm0; ms1 = nm1;
        if (tig == 0) { sc[mb] = al0; sc[mb + 8] = al1; }

        // ---- write P (tf32) to SMEM [n=i][k=j] stride 132 ----
#pragma unroll
        for (int n = 0; n < 16; n++) {
            int jc = n * 8 + 2 * tig;
            uint2 p0 = make_uint2(f2tf(c[n][0]), f2tf(c[n][1]));
            uint2 p1 = make_uint2(f2tf(c[n][2]), f2tf(c[n][3]));
            *(uint2*)&Ps[mb * 132 + jc] = p0;
            *(uint2*)&Ps[(mb + 8) * 132 + jc] = p1;
        }
        __syncthreads();

        // ---- rescale O by sc[i], then O += V @ P ----
#pragma unroll
        for (int n = 0; n < 4; n++) {
            int col = wn2 * 32 + n * 8 + 2 * tig;
            float s0v = sc[col], s1v = sc[col + 1];
#pragma unroll
            for (int f = 0; f < 2; f++) {
                o[f][n][0] *= s0v; o[f][n][1] *= s1v;
                o[f][n][2] *= s0v; o[f][n][3] *= s1v;
            }
        }
#pragma unroll
        for (int ks = 0; ks < 16; ks++) {
            int k0 = ks * 8;
            uint32_t a[2][4];
#pragma unroll
            for (int f = 0; f < 2; f++) {
                int rb = wm2 * 32 + f * 16 + gid;
                a[f][0] = Vs[rb * 132 + k0 + tig];
                a[f][1] = Vs[(rb + 8) * 132 + k0 + tig];
                a[f][2] = Vs[rb * 132 + k0 + tig + 4];
                a[f][3] = Vs[(rb + 8) * 132 + k0 + tig + 4];
            }
#pragma unroll
            for (int n = 0; n < 4; n++) {
                uint32_t bb[2];
                int coln = wn2 * 32 + n * 8 + gid;
                bb[0] = Ps[coln * 132 + k0 + tig];
                bb[1] = Ps[coln * 132 + k0 + tig + 4];
#pragma unroll
                for (int f = 0; f < 2; f++) mma_tf32(o[f][n], a[f], bb);
            }
        }
        __syncthreads();
    }

    // ---- final stats ----
    if (tig == 0) {
        int r0 = wid * 16 + gid;
        mf[r0] = ms0; mf[r0 + 8] = ms1;
        li[r0] = 1.f / ls0; li[r0 + 8] = 1.f / ls1;
    }
    __syncthreads();

    // pb[i][r] = exp(bnd - m_final) / l  (in place)
    for (int idx = tid; idx < 128 * NR; idx += 256) {
        int i = idx / NR, r = idx - i * NR;
        bnd[i * 12 + r] = __expf(bnd[i * 12 + r] - mf[i]) * li[i];
    }
    __syncthreads();

    // ---- epilogue: out[d][i] = O*inv_l + sum_r pb[i][r]*emb_v[r][d] ----
    float* om = g_mid + ((size_t)b * CCH + h * HD) * TSEQ;
#pragma unroll
    for (int f = 0; f < 2; f++) {
        int rd = wm2 * 32 + f * 16 + gid;
#pragma unroll
        for (int n = 0; n < 4; n++) {
            int cil = wn2 * 32 + n * 8 + 2 * tig;
            float inv0 = li[cil], inv1 = li[cil + 1];
            float v0 = o[f][n][0] * inv0, v1 = o[f][n][1] * inv1;
            float v2 = o[f][n][2] * inv0, v3 = o[f][n][3] * inv1;
#pragma unroll
            for (int r = 0; r < NR; r++) {
                float p0 = bnd[cil * 12 + r], p1 = bnd[(cil + 1) * 12 + r];
                float e0 = ev[r * HD + rd], e1 = ev[r * HD + rd + 8];
                v0 += p0 * e0; v1 += p1 * e0;
                v2 += p0 * e1; v3 += p1 * e1;
            }
            *(float2*)(om + (size_t)rd * TSEQ + i0 + cil) = make_float2(v0, v1);
            *(float2*)(om + (size_t)(rd + 8) * TSEQ + i0 + cil) = make_float2(v2, v3);
        }
    }
}

// ---------------------------------------------------------------------------
extern "C" void kernel_launch(void* const* d_in, const int* in_sizes, int n_in,
                              void* d_out, int out_size)
{
    const float* x     = (const float*)d_in[0];
    const float* w_q   = (const float*)d_in[1];
    const float* b_q   = (const float*)d_in[2];
    const float* w_k   = (const float*)d_in[3];
    const float* b_k   = (const float*)d_in[4];
    const float* w_v   = (const float*)d_in[5];
    const float* b_v   = (const float*)d_in[6];
    const float* w_o   = (const float*)d_in[7];
    const float* b_o   = (const float*)d_in[8];
    const float* emb_k = (const float*)d_in[9];
    const float* emb_v = (const float*)d_in[10];
    float* out = (float*)d_out;

    cudaFuncSetAttribute(attn_kernel, cudaFuncAttributeMaxDynamicSharedMemorySize, ATTN_SMEM);

    dim3 gq(CCH / 128, TSEQ / 128, BB * 3);
    qkv_kernel<<<gq, 256>>>(x, w_q, b_q, w_k, b_k, w_v, b_v);

    dim3 ga(TSEQ / 128, NBH);
    attn_kernel<<<ga, 256, ATTN_SMEM>>>(emb_k, emb_v);

    dim3 go(CCH / 128, TSEQ / 128, BB);
    oproj_kernel<<<go, 256>>>(w_o, b_o, out);
}

// round 9
// speedup vs baseline: 2.6508x; 1.0460x over previous
#include <cuda_runtime.h>
#include <math.h>
#include <stdint.h>

#define BB   4
#define TSEQ 1024
#define CCH  768
#define NH   12
#define HD   64
#define NWIN 4
#define NR   9
#define NBH  (BB*NH)   // 48

// Scratch (static __device__ arrays per allocation rules)
static __device__ float g_q[BB*CCH*TSEQ];     // (B, C, T) == (b,h,d,t), q pre-scaled by 1/8
static __device__ float g_k[BB*CCH*TSEQ];
static __device__ float g_v[BB*CCH*TSEQ];
static __device__ float g_mid[BB*CCH*TSEQ];   // attention output, (B, C, T)

// ---------------------------------------------------------------------------
// tf32 helpers
// ---------------------------------------------------------------------------
__device__ __forceinline__ uint32_t f2tf(float x) {
    uint32_t u;
    asm("cvt.rna.tf32.f32 %0, %1;" : "=r"(u) : "f"(x));
    return u;
}
__device__ __forceinline__ uint4 cvt4(float4 v) {
    uint4 u; u.x = f2tf(v.x); u.y = f2tf(v.y); u.z = f2tf(v.z); u.w = f2tf(v.w);
    return u;
}
__device__ __forceinline__ void mma_tf32(float c[4], const uint32_t a[4], const uint32_t b[2]) {
    asm volatile(
        "mma.sync.aligned.m16n8k8.row.col.f32.tf32.tf32.f32 "
        "{%0,%1,%2,%3}, {%4,%5,%6,%7}, {%8,%9}, {%0,%1,%2,%3};\n"
        : "+f"(c[0]), "+f"(c[1]), "+f"(c[2]), "+f"(c[3])
        : "r"(a[0]), "r"(a[1]), "r"(a[2]), "r"(a[3]), "r"(b[0]), "r"(b[1]));
}

// ---------------------------------------------------------------------------
// Projection GEMM body: Out[o,t] = (sum_c W[o,c]*X[c,t] + bias[o]) * scale
// 64x128 block tile (2 CTAs/SM), BK=16, 8 warps (2m x 4n), warp tile 32x32.
// ---------------------------------------------------------------------------
__device__ __forceinline__ void proj_body(
    const float* __restrict__ X, const float* __restrict__ W,
    const float* __restrict__ bias, float* __restrict__ Out, float scale)
{
    __shared__ uint32_t As[2][64 * 20];    // [m][k], stride 20
    __shared__ uint32_t Bs[2][16 * 136];   // [k][n], stride 136

    int tid = threadIdx.x;
    int lane = tid & 31, wid = tid >> 5;
    int wm = wid >> 2, wn = wid & 3;
    int gid = lane >> 2, tig = lane & 3;
    int o0 = blockIdx.x * 64, t0 = blockIdx.y * 128;

    float c[2][4][4];
#pragma unroll
    for (int f = 0; f < 2; f++)
#pragma unroll
        for (int n = 0; n < 4; n++)
#pragma unroll
            for (int q = 0; q < 4; q++) c[f][n][q] = 0.f;

    float4 al, bl[2];

    auto load_g = [&](int k0) {
        al = *(const float4*)(W + (size_t)(o0 + (tid >> 2)) * CCH + k0 + (tid & 3) * 4);
#pragma unroll
        for (int p = 0; p < 2; p++) {
            int fl = tid + p * 256;
            bl[p] = *(const float4*)(X + (size_t)(k0 + (fl >> 5)) * TSEQ + t0 + (fl & 31) * 4);
        }
    };
    auto sts = [&](int buf) {
        *(uint4*)&As[buf][(tid >> 2) * 20 + (tid & 3) * 4] = cvt4(al);
#pragma unroll
        for (int p = 0; p < 2; p++) {
            int fl = tid + p * 256;
            *(uint4*)&Bs[buf][(fl >> 5) * 136 + (fl & 31) * 4] = cvt4(bl[p]);
        }
    };

    load_g(0); sts(0); __syncthreads();
    const int NS = CCH / 16;
    for (int s = 0; s < NS; s++) {
        int cur = s & 1;
        if (s + 1 < NS) load_g((s + 1) * 16);
#pragma unroll
        for (int kk = 0; kk < 16; kk += 8) {
            uint32_t a[2][4], b[4][2];
#pragma unroll
            for (int f = 0; f < 2; f++) {
                int rb = wm * 32 + f * 16 + gid;
                a[f][0] = As[cur][rb * 20 + kk + tig];
                a[f][1] = As[cur][(rb + 8) * 20 + kk + tig];
                a[f][2] = As[cur][rb * 20 + kk + tig + 4];
                a[f][3] = As[cur][(rb + 8) * 20 + kk + tig + 4];
            }
#pragma unroll
            for (int n = 0; n < 4; n++) {
                int col = wn * 32 + n * 8 + gid;
                b[n][0] = Bs[cur][(kk + tig) * 136 + col];
                b[n][1] = Bs[cur][(kk + tig + 4) * 136 + col];
            }
#pragma unroll
            for (int f = 0; f < 2; f++)
#pragma unroll
                for (int n = 0; n < 4; n++) mma_tf32(c[f][n], a[f], b[n]);
        }
        if (s + 1 < NS) sts(cur ^ 1);
        __syncthreads();
    }

#pragma unroll
    for (int f = 0; f < 2; f++) {
        int ro = o0 + wm * 32 + f * 16 + gid;
        float bv0 = bias[ro], bv1 = bias[ro + 8];
#pragma unroll
        for (int n = 0; n < 4; n++) {
            int col = t0 + wn * 32 + n * 8 + 2 * tig;
            *(float2*)(Out + (size_t)ro * TSEQ + col) =
                make_float2((c[f][n][0] + bv0) * scale, (c[f][n][1] + bv0) * scale);
            *(float2*)(Out + (size_t)(ro + 8) * TSEQ + col) =
                make_float2((c[f][n][2] + bv1) * scale, (c[f][n][3] + bv1) * scale);
        }
    }
}

__global__ __launch_bounds__(256, 2)
void qkv_kernel(const float* __restrict__ X,
                const float* __restrict__ Wq, const float* __restrict__ Bq,
                const float* __restrict__ Wk, const float* __restrict__ Bk,
                const float* __restrict__ Wv, const float* __restrict__ Bv)
{
    int zb = blockIdx.z;
    int b = zb / 3, which = zb % 3;
    const float* Wm = (which == 0) ? Wq : ((which == 1) ? Wk : Wv);
    const float* Bi = (which == 0) ? Bq : ((which == 1) ? Bk : Bv);
    float* Out = (which == 0) ? g_q : ((which == 1) ? g_k : g_v);
    float scale = (which == 0) ? 0.125f : 1.0f;
    proj_body(X + (size_t)b * CCH * TSEQ, Wm, Bi, Out + (size_t)b * CCH * TSEQ, scale);
}

__global__ __launch_bounds__(256, 2)
void oproj_kernel(const float* __restrict__ Wm, const float* __restrict__ Bi,
                  float* __restrict__ Out)
{
    int b = blockIdx.z;
    proj_body(g_mid + (size_t)b * CCH * TSEQ, Wm, Bi, Out + (size_t)b * CCH * TSEQ, 1.0f);
}

// ---------------------------------------------------------------------------
// Fused flash attention: scores + rel-k + softmax + rel-v + AV in one kernel.
// Block = (bh, 128-row i-tile), 256 threads (8 warps).
// S phase: warp w owns rows w*16..w*16+15 across all 128 j (16 n-subtiles).
// AV phase: C[m=d 64][n=i 128], warps 2m x 4n, warp tile 32x32.
// Online softmax across 8 j-tiles. Output written to g_mid [d][i].
// ---------------------------------------------------------------------------
#define ATTN_SMEM 189440

__global__ __launch_bounds__(256, 1)
void attn_kernel(const float* __restrict__ emb_k, const float* __restrict__ emb_v)
{
    extern __shared__ char smc[];
    uint32_t* Qs = (uint32_t*)smc;          // [k=d 64][m=i 128] stride 136
    uint32_t* Ks = Qs + 64 * 136;           // [k=d 64][n=j 128] stride 136
    uint32_t* Vs = Ks + 64 * 136;           // [m=d 64][k=j 128] stride 132
    uint32_t* Ps = Vs + 64 * 132;           // [n=i 128][k=j 128] stride 132
    float* Rk  = (float*)(Ps + 128 * 132);  // [128][12] : q_i . emb_k[r]
    float* bnd = Rk + 128 * 12;             // [128][12] : raw band scores -> pb
    float* ek  = bnd + 128 * 12;            // [9][64]
    float* ev  = ek + NR * HD;              // [9][64]
    float* sc  = ev + NR * HD;              // [128] per-tile rescale
    float* mf  = sc + 128;                  // [128] final max
    float* li  = mf + 128;                  // [128] 1/l

    int bh = blockIdx.y;
    int i0 = blockIdx.x * 128;
    int b = bh / NH, h = bh % NH;
    const float* qb = g_q + ((size_t)b * CCH + h * HD) * TSEQ;
    const float* kb = g_k + ((size_t)b * CCH + h * HD) * TSEQ;
    const float* vb = g_v + ((size_t)b * CCH + h * HD) * TSEQ;

    int tid = threadIdx.x;
    int lane = tid & 31, wid = tid >> 5;
    int gid = lane >> 2, tig = lane & 3;
    int wm2 = wid >> 2, wn2 = wid & 3;   // AV warp coords

    // ---- block init: Q tile, embeddings, band init ----
#pragma unroll
    for (int p = 0; p < 8; p++) {
        int fl = tid + p * 256;
        int d = fl >> 5, c4 = (fl & 31) * 4;
        float4 v = *(const float4*)(qb + (size_t)d * TSEQ + i0 + c4);
        *(uint4*)&Qs[d * 136 + c4] = cvt4(v);
    }
    for (int idx = tid; idx < NR * HD; idx += 256) { ek[idx] = emb_k[idx]; ev[idx] = emb_v[idx]; }
    for (int idx = tid; idx < 128 * 12; idx += 256) bnd[idx] = -1e30f;
    __syncthreads();

    // Rk[i][r] = sum_d q[d][i] * emb_k[r][d]
    for (int idx = tid; idx < 128 * NR; idx += 256) {
        int i = idx / NR, r = idx - i * NR;
        float acc = 0.f;
#pragma unroll
        for (int d = 0; d < HD; d++)
            acc += __uint_as_float(Qs[d * 136 + i]) * ek[r * HD + d];
        Rk[i * 12 + r] = acc;
    }
    __syncthreads();

    float ms0 = -1e30f, ms1 = -1e30f, ls0 = 0.f, ls1 = 0.f;
    float o[2][4][4];
#pragma unroll
    for (int f = 0; f < 2; f++)
#pragma unroll
        for (int n = 0; n < 4; n++)
#pragma unroll
            for (int q = 0; q < 4; q++) o[f][n][q] = 0.f;

    for (int jt = 0; jt < 8; jt++) {
        int j0 = jt * 128;
        // ---- load K, V tiles ----
#pragma unroll
        for (int p = 0; p < 8; p++) {
            int fl = tid + p * 256;
            int d = fl >> 5, c4 = (fl & 31) * 4;
            float4 kv = *(const float4*)(kb + (size_t)d * TSEQ + j0 + c4);
            float4 vv = *(const float4*)(vb + (size_t)d * TSEQ + j0 + c4);
            *(uint4*)&Ks[d * 136 + c4] = cvt4(kv);
            *(uint4*)&Vs[d * 132 + c4] = cvt4(vv);
        }
        __syncthreads();

        // ---- S = Q.K MMA: warp wid owns rows wid*16..+16 ----
        float c[16][4];
#pragma unroll
        for (int n = 0; n < 16; n++)
#pragma unroll
            for (int q = 0; q < 4; q++) c[n][q] = 0.f;

        int mb = wid * 16 + gid;
#pragma unroll
        for (int ks = 0; ks < 8; ks++) {
            int k0 = ks * 8;
            uint32_t a[4];
            a[0] = Qs[(k0 + tig) * 136 + mb];
            a[1] = Qs[(k0 + tig) * 136 + mb + 8];
            a[2] = Qs[(k0 + tig + 4) * 136 + mb];
            a[3] = Qs[(k0 + tig + 4) * 136 + mb + 8];
#pragma unroll
            for (int n = 0; n < 16; n++) {
                uint32_t bb[2];
                bb[0] = Ks[(k0 + tig) * 136 + n * 8 + gid];
                bb[1] = Ks[(k0 + tig + 4) * 136 + n * 8 + gid];
                mma_tf32(c[n], a, bb);
            }
        }

        // ---- rel-k add + raw band stash (near-diagonal tiles only) ----
        int dj = j0 - i0;
        if (dj <= 128 && dj >= -128) {
#pragma unroll
            for (int n = 0; n < 16; n++) {
#pragma unroll
                for (int q = 0; q < 4; q++) {
                    int ir = wid * 16 + gid + ((q >> 1) << 3);
                    int jc = n * 8 + 2 * tig + (q & 1);
                    int r = dj + jc - ir + NWIN;
                    if (r >= 0 && r < NR) {
                        c[n][q] += Rk[ir * 12 + r];
                        bnd[ir * 12 + r] = c[n][q];
                    }
                }
            }
        }

        // ---- online softmax ----
        float mx0 = -1e30f, mx1 = -1e30f;
#pragma unroll
        for (int n = 0; n < 16; n++) {
            mx0 = fmaxf(mx0, fmaxf(c[n][0], c[n][1]));
            mx1 = fmaxf(mx1, fmaxf(c[n][2], c[n][3]));
        }
        mx0 = fmaxf(mx0, __shfl_xor_sync(0xffffffffu, mx0, 1));
        mx0 = fmaxf(mx0, __shfl_xor_sync(0xffffffffu, mx0, 2));
        mx1 = fmaxf(mx1, __shfl_xor_sync(0xffffffffu, mx1, 1));
        mx1 = fmaxf(mx1, __shfl_xor_sync(0xffffffffu, mx1, 2));
        float nm0 = fmaxf(ms0, mx0), nm1 = fmaxf(ms1, mx1);
        float al0 = __expf(ms0 - nm0), al1 = __expf(ms1 - nm1);

        float s0 = 0.f, s1 = 0.f;
#pragma unroll
        for (int n = 0; n < 16; n++) {
            c[n][0] = __expf(c[n][0] - nm0); s0 += c[n][0];
            c[n][1] = __expf(c[n][1] - nm0); s0 += c[n][1];
            c[n][2] = __expf(c[n][2] - nm1); s1 += c[n][2];
            c[n][3] = __expf(c[n][3] - nm1); s1 += c[n][3];
        }
        s0 += __shfl_xor_sync(0xffffffffu, s0, 1);
        s0 += __shfl_xor_sync(0xffffffffu, s0, 2);
        s1 += __shfl_xor_sync(0xffffffffu, s1, 1);
        s1 += __shfl_xor_sync(0xffffffffu, s1, 2);
        ls0 = ls0 * al0 + s0;
        ls1 = ls1 * al1 + s1;
        ms0 = nm0; ms1 = nm1;
        if (tig == 0) { sc[mb] = al0; sc[mb + 8] = al1; }

        // ---- write P (tf32) to SMEM [n=i][k=j] stride 132 ----
#pragma unroll
        for (int n = 0; n < 16; n++) {
            int jc = n * 8 + 2 * tig;
            uint2 p0 = make_uint2(f2tf(c[n][0]), f2tf(c[n][1]));
            uint2 p1 = make_uint2(f2tf(c[n][2]), f2tf(c[n][3]));
            *(uint2*)&Ps[mb * 132 + jc] = p0;
            *(uint2*)&Ps[(mb + 8) * 132 + jc] = p1;
        }
        __syncthreads();

        // ---- rescale O by sc[i], then O += V @ P ----
#pragma unroll
        for (int n = 0; n < 4; n++) {
            int col = wn2 * 32 + n * 8 + 2 * tig;
            float s0v = sc[col], s1v = sc[col + 1];
#pragma unroll
            for (int f = 0; f < 2; f++) {
                o[f][n][0] *= s0v; o[f][n][1] *= s1v;
                o[f][n][2] *= s0v; o[f][n][3] *= s1v;
            }
        }
#pragma unroll
        for (int ks = 0; ks < 16; ks++) {
            int k0 = ks * 8;
            uint32_t a[2][4];
#pragma unroll
            for (int f = 0; f < 2; f++) {
                int rb = wm2 * 32 + f * 16 + gid;
                a[f][0] = Vs[rb * 132 + k0 + tig];
                a[f][1] = Vs[(rb + 8) * 132 + k0 + tig];
                a[f][2] = Vs[rb * 132 + k0 + tig + 4];
                a[f][3] = Vs[(rb + 8) * 132 + k0 + tig + 4];
            }
#pragma unroll
            for (int n = 0; n < 4; n++) {
                uint32_t bb[2];
                int coln = wn2 * 32 + n * 8 + gid;
                bb[0] = Ps[coln * 132 + k0 + tig];
                bb[1] = Ps[coln * 132 + k0 + tig + 4];
#pragma unroll
                for (int f = 0; f < 2; f++) mma_tf32(o[f][n], a[f], bb);
            }
        }
        __syncthreads();
    }

    // ---- final stats ----
    if (tig == 0) {
        int r0 = wid * 16 + gid;
        mf[r0] = ms0; mf[r0 + 8] = ms1;
        li[r0] = 1.f / ls0; li[r0 + 8] = 1.f / ls1;
    }
    __syncthreads();

    // pb[i][r] = exp(bnd - m_final) / l  (in place)
    for (int idx = tid; idx < 128 * NR; idx += 256) {
        int i = idx / NR, r = idx - i * NR;
        bnd[i * 12 + r] = __expf(bnd[i * 12 + r] - mf[i]) * li[i];
    }
    __syncthreads();

    // ---- epilogue: out[d][i] = O*inv_l + sum_r pb[i][r]*emb_v[r][d] ----
    float* om = g_mid + ((size_t)b * CCH + h * HD) * TSEQ;
#pragma unroll
    for (int f = 0; f < 2; f++) {
        int rd = wm2 * 32 + f * 16 + gid;
#pragma unroll
        for (int n = 0; n < 4; n++) {
            int cil = wn2 * 32 + n * 8 + 2 * tig;
            float inv0 = li[cil], inv1 = li[cil + 1];
            float v0 = o[f][n][0] * inv0, v1 = o[f][n][1] * inv1;
            float v2 = o[f][n][2] * inv0, v3 = o[f][n][3] * inv1;
#pragma unroll
            for (int r = 0; r < NR; r++) {
                float p0 = bnd[cil * 12 + r], p1 = bnd[(cil + 1) * 12 + r];
                float e0 = ev[r * HD + rd], e1 = ev[r * HD + rd + 8];
                v0 += p0 * e0; v1 += p1 * e0;
                v2 += p0 * e1; v3 += p1 * e1;
            }
            *(float2*)(om + (size_t)rd * TSEQ + i0 + cil) = make_float2(v0, v1);
            *(float2*)(om + (size_t)(rd + 8) * TSEQ + i0 + cil) = make_float2(v2, v3);
        }
    }
}

// ---------------------------------------------------------------------------
extern "C" void kernel_launch(void* const* d_in, const int* in_sizes, int n_in,
                              void* d_out, int out_size)
{
    const float* x     = (const float*)d_in[0];
    const float* w_q   = (const float*)d_in[1];
    const float* b_q   = (const float*)d_in[2];
    const float* w_k   = (const float*)d_in[3];
    const float* b_k   = (const float*)d_in[4];
    const float* w_v   = (const float*)d_in[5];
    const float* b_v   = (const float*)d_in[6];
    const float* w_o   = (const float*)d_in[7];
    const float* b_o   = (const float*)d_in[8];
    const float* emb_k = (const float*)d_in[9];
    const float* emb_v = (const float*)d_in[10];
    float* out = (float*)d_out;

    cudaFuncSetAttribute(attn_kernel, cudaFuncAttributeMaxDynamicSharedMemorySize, ATTN_SMEM);

    dim3 gq(CCH / 64, TSEQ / 128, BB * 3);
    qkv_kernel<<<gq, 256>>>(x, w_q, b_q, w_k, b_k, w_v, b_v);

    dim3 ga(TSEQ / 128, NBH);
    attn_kernel<<<ga, 256, ATTN_SMEM>>>(emb_k, emb_v);

    dim3 go(CCH / 64, TSEQ / 128, BB);
    oproj_kernel<<<go, 256>>>(w_o, b_o, out);
}

// round 11
// speedup vs baseline: 2.9453x; 1.1111x over previous
#include <cuda_runtime.h>
#include <math.h>
#include <stdint.h>

#define BB   4
#define TSEQ 1024
#define CCH  768
#define NH   12
#define HD   64
#define NWIN 4
#define NR   9
#define NBH  (BB*NH)   // 48

// Scratch (static __device__ arrays per allocation rules)
static __device__ float g_q[BB*CCH*TSEQ];     // (B, C, T) == (b,h,d,t), q pre-scaled by 1/8
static __device__ float g_k[BB*CCH*TSEQ];
static __device__ float g_v[BB*CCH*TSEQ];
static __device__ float g_mid[BB*CCH*TSEQ];   // attention output (tf32-rounded), (B, C, T)
static __device__ float g_x[BB*CCH*TSEQ];     // tf32-rounded input x
static __device__ float g_wq[CCH*CCH];        // tf32-rounded weights
static __device__ float g_wk[CCH*CCH];
static __device__ float g_wv[CCH*CCH];
static __device__ float g_wo[CCH*CCH];

// ---------------------------------------------------------------------------
// tf32 / async helpers
// ---------------------------------------------------------------------------
__device__ __forceinline__ uint32_t f2tf(float x) {
    uint32_t u;
    asm("cvt.rna.tf32.f32 %0, %1;" : "=r"(u) : "f"(x));
    return u;
}
__device__ __forceinline__ uint4 cvt4(float4 v) {
    uint4 u; u.x = f2tf(v.x); u.y = f2tf(v.y); u.z = f2tf(v.z); u.w = f2tf(v.w);
    return u;
}
__device__ __forceinline__ float4 rnd4(float4 v) {
    float4 r;
    r.x = __uint_as_float(f2tf(v.x)); r.y = __uint_as_float(f2tf(v.y));
    r.z = __uint_as_float(f2tf(v.z)); r.w = __uint_as_float(f2tf(v.w));
    return r;
}
__device__ __forceinline__ void mma_tf32(float c[4], const uint32_t a[4], const uint32_t b[2]) {
    asm volatile(
        "mma.sync.aligned.m16n8k8.row.col.f32.tf32.tf32.f32 "
        "{%0,%1,%2,%3}, {%4,%5,%6,%7}, {%8,%9}, {%0,%1,%2,%3};\n"
        : "+f"(c[0]), "+f"(c[1]), "+f"(c[2]), "+f"(c[3])
        : "r"(a[0]), "r"(a[1]), "r"(a[2]), "r"(a[3]), "r"(b[0]), "r"(b[1]));
}
__device__ __forceinline__ void cp16(uint32_t dst, const void* src) {
    asm volatile("cp.async.cg.shared.global [%0], [%1], 16;\n" :: "r"(dst), "l"(src));
}
#define CP_COMMIT() asm volatile("cp.async.commit_group;\n")
#define CP_WAIT0()  asm volatile("cp.async.wait_group 0;\n")

// ---------------------------------------------------------------------------
// Prep: round x and weights to tf32 bit patterns (one rounding per element,
// identical precision to converting at SMEM-store time).
// ---------------------------------------------------------------------------
__global__ __launch_bounds__(256)
void prep_kernel(const float* __restrict__ x,
                 const float* __restrict__ wq, const float* __restrict__ wk,
                 const float* __restrict__ wv, const float* __restrict__ wo)
{
    int stride = gridDim.x * blockDim.x;
    int idx = blockIdx.x * blockDim.x + threadIdx.x;
    for (int i = idx; i < BB * CCH * TSEQ / 4; i += stride)
        ((float4*)g_x)[i] = rnd4(((const float4*)x)[i]);
    for (int i = idx; i < CCH * CCH / 4; i += stride) {
        ((float4*)g_wq)[i] = rnd4(((const float4*)wq)[i]);
        ((float4*)g_wk)[i] = rnd4(((const float4*)wk)[i]);
        ((float4*)g_wv)[i] = rnd4(((const float4*)wv)[i]);
        ((float4*)g_wo)[i] = rnd4(((const float4*)wo)[i]);
    }
}

// ---------------------------------------------------------------------------
// Projection GEMM body: Out[o,t] = (sum_c W[o,c]*X[c,t] + bias[o]) * scale
// Inputs pre-rounded to tf32. 128x128 block, BK=16, cp.async double buffer,
// 8 warps (4m x 2n), warp tile 32x64. 2 CTAs/SM.
// ---------------------------------------------------------------------------
__device__ __forceinline__ void proj_body(
    const float* __restrict__ X, const float* __restrict__ W,
    const float* __restrict__ bias, float* __restrict__ Out, float scale)
{
    __shared__ float As[2][128 * 20];    // [m][k], stride 20
    __shared__ float Bs[2][16 * 136];    // [k][n], stride 136

    int tid = threadIdx.x;
    int lane = tid & 31, wid = tid >> 5;
    int wm = wid >> 1, wn = wid & 1;
    int gid = lane >> 2, tig = lane & 3;
    int o0 = blockIdx.x * 128, t0 = blockIdx.y * 128;

    const uint32_t aS = (uint32_t)__cvta_generic_to_shared(&As[0][0]);
    const uint32_t bS = (uint32_t)__cvta_generic_to_shared(&Bs[0][0]);
    const uint32_t aBuf = 128 * 20 * 4, bBuf = 16 * 136 * 4;

    // per-thread copy coordinates
    const float* aptr[2]; const float* bptr[2];
    uint32_t adst[2], bdst[2];
#pragma unroll
    for (int p = 0; p < 2; p++) {
        int fl = tid + p * 256;
        int am = fl >> 2, ac4 = (fl & 3) * 4;
        aptr[p] = W + (size_t)(o0 + am) * CCH + ac4;
        adst[p] = aS + (uint32_t)(am * 20 + ac4) * 4;
        int bk = fl >> 5, bt4 = (fl & 31) * 4;
        bptr[p] = X + (size_t)bk * TSEQ + t0 + bt4;
        bdst[p] = bS + (uint32_t)(bk * 136 + bt4) * 4;
    }

    float c[2][8][4];
#pragma unroll
    for (int f = 0; f < 2; f++)
#pragma unroll
        for (int n = 0; n < 8; n++)
#pragma unroll
            for (int q = 0; q < 4; q++) c[f][n][q] = 0.f;

    auto issue = [&](int buf) {
#pragma unroll
        for (int p = 0; p < 2; p++) {
            cp16(adst[p] + buf * aBuf, aptr[p]);
            cp16(bdst[p] + buf * bBuf, bptr[p]);
            aptr[p] += 16;
            bptr[p] += 16 * TSEQ;
        }
    };

    issue(0); CP_COMMIT();

    const int NS = CCH / 16;   // 48
    for (int s = 0; s < NS; s++) {
        CP_WAIT0();
        __syncthreads();
        if (s + 1 < NS) { issue((s + 1) & 1); CP_COMMIT(); }
        const float* Ac = As[s & 1];
        const float* Bc = Bs[s & 1];
#pragma unroll
        for (int kk = 0; kk < 16; kk += 8) {
            uint32_t a[2][4], b[8][2];
#pragma unroll
            for (int f = 0; f < 2; f++) {
                int rb = wm * 32 + f * 16 + gid;
                a[f][0] = __float_as_uint(Ac[rb * 20 + kk + tig]);
                a[f][1] = __float_as_uint(Ac[(rb + 8) * 20 + kk + tig]);
                a[f][2] = __float_as_uint(Ac[rb * 20 + kk + tig + 4]);
                a[f][3] = __float_as_uint(Ac[(rb + 8) * 20 + kk + tig + 4]);
            }
#pragma unroll
            for (int n = 0; n < 8; n++) {
                int col = wn * 64 + n * 8 + gid;
                b[n][0] = __float_as_uint(Bc[(kk + tig) * 136 + col]);
                b[n][1] = __float_as_uint(Bc[(kk + tig + 4) * 136 + col]);
            }
#pragma unroll
            for (int f = 0; f < 2; f++)
#pragma unroll
                for (int n = 0; n < 8; n++) mma_tf32(c[f][n], a[f], b[n]);
        }
    }

#pragma unroll
    for (int f = 0; f < 2; f++) {
        int ro = o0 + wm * 32 + f * 16 + gid;
        float bv0 = bias[ro], bv1 = bias[ro + 8];
#pragma unroll
        for (int n = 0; n < 8; n++) {
            int col = t0 + wn * 64 + n * 8 + 2 * tig;
            *(float2*)(Out + (size_t)ro * TSEQ + col) =
                make_float2((c[f][n][0] + bv0) * scale, (c[f][n][1] + bv0) * scale);
            *(float2*)(Out + (size_t)(ro + 8) * TSEQ + col) =
                make_float2((c[f][n][2] + bv1) * scale, (c[f][n][3] + bv1) * scale);
        }
    }
}

__global__ __launch_bounds__(256, 2)
void qkv_kernel(const float* __restrict__ Bq, const float* __restrict__ Bk,
                const float* __restrict__ Bv)
{
    int zb = blockIdx.z;
    int b = zb / 3, which = zb % 3;
    const float* Wm = (which == 0) ? g_wq : ((which == 1) ? g_wk : g_wv);
    const float* Bi = (which == 0) ? Bq : ((which == 1) ? Bk : Bv);
    float* Out = (which == 0) ? g_q : ((which == 1) ? g_k : g_v);
    float scale = (which == 0) ? 0.125f : 1.0f;
    proj_body(g_x + (size_t)b * CCH * TSEQ, Wm, Bi, Out + (size_t)b * CCH * TSEQ, scale);
}

__global__ __launch_bounds__(256, 2)
void oproj_kernel(const float* __restrict__ Bi, float* __restrict__ Out)
{
    int b = blockIdx.z;
    proj_body(g_mid + (size_t)b * CCH * TSEQ, g_wo, Bi, Out + (size_t)b * CCH * TSEQ, 1.0f);
}

// ---------------------------------------------------------------------------
// Fused flash attention: scores + rel-k + softmax + rel-v + AV in one kernel.
// (unchanged except epilogue rounds g_mid to tf32 bits for oproj's cp.async)
// ---------------------------------------------------------------------------
#define ATTN_SMEM 189440

__global__ __launch_bounds__(256, 1)
void attn_kernel(const float* __restrict__ emb_k, const float* __restrict__ emb_v)
{
    extern __shared__ char smc[];
    uint32_t* Qs = (uint32_t*)smc;          // [k=d 64][m=i 128] stride 136
    uint32_t* Ks = Qs + 64 * 136;           // [k=d 64][n=j 128] stride 136
    uint32_t* Vs = Ks + 64 * 136;           // [m=d 64][k=j 128] stride 132
    uint32_t* Ps = Vs + 64 * 132;           // [n=i 128][k=j 128] stride 132
    float* Rk  = (float*)(Ps + 128 * 132);  // [128][12]
    float* bnd = Rk + 128 * 12;             // [128][12]
    float* ek  = bnd + 128 * 12;            // [9][64]
    float* ev  = ek + NR * HD;              // [9][64]
    float* sc  = ev + NR * HD;              // [128]
    float* mf  = sc + 128;                  // [128]
    float* li  = mf + 128;                  // [128]

    int bh = blockIdx.y;
    int i0 = blockIdx.x * 128;
    int b = bh / NH, h = bh % NH;
    const float* qb = g_q + ((size_t)b * CCH + h * HD) * TSEQ;
    const float* kb = g_k + ((size_t)b * CCH + h * HD) * TSEQ;
    const float* vb = g_v + ((size_t)b * CCH + h * HD) * TSEQ;

    int tid = threadIdx.x;
    int lane = tid & 31, wid = tid >> 5;
    int gid = lane >> 2, tig = lane & 3;
    int wm2 = wid >> 2, wn2 = wid & 3;

#pragma unroll
    for (int p = 0; p < 8; p++) {
        int fl = tid + p * 256;
        int d = fl >> 5, c4 = (fl & 31) * 4;
        float4 v = *(const float4*)(qb + (size_t)d * TSEQ + i0 + c4);
        *(uint4*)&Qs[d * 136 + c4] = cvt4(v);
    }
    for (int idx = tid; idx < NR * HD; idx += 256) { ek[idx] = emb_k[idx]; ev[idx] = emb_v[idx]; }
    for (int idx = tid; idx < 128 * 12; idx += 256) bnd[idx] = -1e30f;
    __syncthreads();

    for (int idx = tid; idx < 128 * NR; idx += 256) {
        int i = idx / NR, r = idx - i * NR;
        float acc = 0.f;
#pragma unroll
        for (int d = 0; d < HD; d++)
            acc += __uint_as_float(Qs[d * 136 + i]) * ek[r * HD + d];
        Rk[i * 12 + r] = acc;
    }
    __syncthreads();

    float ms0 = -1e30f, ms1 = -1e30f, ls0 = 0.f, ls1 = 0.f;
    float o[2][4][4];
#pragma unroll
    for (int f = 0; f < 2; f++)
#pragma unroll
        for (int n = 0; n < 4; n++)
#pragma unroll
            for (int q = 0; q < 4; q++) o[f][n][q] = 0.f;

    for (int jt = 0; jt < 8; jt++) {
        int j0 = jt * 128;
#pragma unroll
        for (int p = 0; p < 8; p++) {
            int fl = tid + p * 256;
            int d = fl >> 5, c4 = (fl & 31) * 4;
            float4 kv = *(const float4*)(kb + (size_t)d * TSEQ + j0 + c4);
            float4 vv = *(const float4*)(vb + (size_t)d * TSEQ + j0 + c4);
            *(uint4*)&Ks[d * 136 + c4] = cvt4(kv);
            *(uint4*)&Vs[d * 132 + c4] = cvt4(vv);
        }
        __syncthreads();

        float c[16][4];
#pragma unroll
        for (int n = 0; n < 16; n++)
#pragma unroll
            for (int q = 0; q < 4; q++) c[n][q] = 0.f;

        int mb = wid * 16 + gid;
#pragma unroll
        for (int ks = 0; ks < 8; ks++) {
            int k0 = ks * 8;
            uint32_t a[4];
            a[0] = Qs[(k0 + tig) * 136 + mb];
            a[1] = Qs[(k0 + tig) * 136 + mb + 8];
            a[2] = Qs[(k0 + tig + 4) * 136 + mb];
            a[3] = Qs[(k0 + tig + 4) * 136 + mb + 8];
#pragma unroll
            for (int n = 0; n < 16; n++) {
                uint32_t bb[2];
                bb[0] = Ks[(k0 + tig) * 136 + n * 8 + gid];
                bb[1] = Ks[(k0 + tig + 4) * 136 + n * 8 + gid];
                mma_tf32(c[n], a, bb);
            }
        }

        int dj = j0 - i0;
        if (dj <= 128 && dj >= -128) {
#pragma unroll
            for (int n = 0; n < 16; n++) {
#pragma unroll
                for (int q = 0; q < 4; q++) {
                    int ir = wid * 16 + gid + ((q >> 1) << 3);
                    int jc = n * 8 + 2 * tig + (q & 1);
                    int r = dj + jc - ir + NWIN;
                    if (r >= 0 && r < NR) {
                        c[n][q] += Rk[ir * 12 + r];
                        bnd[ir * 12 + r] = c[n][q];
                    }
                }
            }
        }

        float mx0 = -1e30f, mx1 = -1e30f;
#pragma unroll
        for (int n = 0; n < 16; n++) {
            mx0 = fmaxf(mx0, fmaxf(c[n][0], c[n][1]));
            mx1 = fmaxf(mx1, fmaxf(c[n][2], c[n][3]));
        }
        mx0 = fmaxf(mx0, __shfl_xor_sync(0xffffffffu, mx0, 1));
        mx0 = fmaxf(mx0, __shfl_xor_sync(0xffffffffu, mx0, 2));
        mx1 = fmaxf(mx1, __shfl_xor_sync(0xffffffffu, mx1, 1));
        mx1 = fmaxf(mx1, __shfl_xor_sync(0xffffffffu, mx1, 2));
        float nm0 = fmaxf(ms0, mx0), nm1 = fmaxf(ms1, mx1);
        float al0 = __expf(ms0 - nm0), al1 = __expf(ms1 - nm1);

        float s0 = 0.f, s1 = 0.f;
#pragma unroll
        for (int n = 0; n < 16; n++) {
            c[n][0] = __expf(c[n][0] - nm0); s0 += c[n][0];
            c[n][1] = __expf(c[n][1] - nm0); s0 += c[n][1];
            c[n][2] = __expf(c[n][2] - nm1); s1 += c[n][2];
            c[n][3] = __expf(c[n][3] - nm1); s1 += c[n][3];
        }
        s0 += __shfl_xor_sync(0xffffffffu, s0, 1);
        s0 += __shfl_xor_sync(0xffffffffu, s0, 2);
        s1 += __shfl_xor_sync(0xffffffffu, s1, 1);
        s1 += __shfl_xor_sync(0xffffffffu, s1, 2);
        ls0 = ls0 * al0 + s0;
        ls1 = ls1 * al1 + s1;
        ms0 = nm0; ms1 = nm1;
        if (tig == 0) { sc[mb] = al0; sc[mb + 8] = al1; }

#pragma unroll
        for (int n = 0; n < 16; n++) {
            int jc = n * 8 + 2 * tig;
            uint2 p0 = make_uint2(f2tf(c[n][0]), f2tf(c[n][1]));
            uint2 p1 = make_uint2(f2tf(c[n][2]), f2tf(c[n][3]));
            *(uint2*)&Ps[mb * 132 + jc] = p0;
            *(uint2*)&Ps[(mb + 8) * 132 + jc] = p1;
        }
        __syncthreads();

#pragma unroll
        for (int n = 0; n < 4; n++) {
            int col = wn2 * 32 + n * 8 + 2 * tig;
            float s0v = sc[col], s1v = sc[col + 1];
#pragma unroll
            for (int f = 0; f < 2; f++) {
                o[f][n][0] *= s0v; o[f][n][1] *= s1v;
                o[f][n][2] *= s0v; o[f][n][3] *= s1v;
            }
        }
#pragma unroll
        for (int ks = 0; ks < 16; ks++) {
            int k0 = ks * 8;
            uint32_t a[2][4];
#pragma unroll
            for (int f = 0; f < 2; f++) {
                int rb = wm2 * 32 + f * 16 + gid;
                a[f][0] = Vs[rb * 132 + k0 + tig];
                a[f][1] = Vs[(rb + 8) * 132 + k0 + tig];
                a[f][2] = Vs[rb * 132 + k0 + tig + 4];
                a[f][3] = Vs[(rb + 8) * 132 + k0 + tig + 4];
            }
#pragma unroll
            for (int n = 0; n < 4; n++) {
                uint32_t bb[2];
                int coln = wn2 * 32 + n * 8 + gid;
                bb[0] = Ps[coln * 132 + k0 + tig];
                bb[1] = Ps[coln * 132 + k0 + tig + 4];
#pragma unroll
                for (int f = 0; f < 2; f++) mma_tf32(o[f][n], a[f], bb);
            }
        }
        __syncthreads();
    }

    if (tig == 0) {
        int r0 = wid * 16 + gid;
        mf[r0] = ms0; mf[r0 + 8] = ms1;
        li[r0] = 1.f / ls0; li[r0 + 8] = 1.f / ls1;
    }
    __syncthreads();

    for (int idx = tid; idx < 128 * NR; idx += 256) {
        int i = idx / NR, r = idx - i * NR;
        bnd[i * 12 + r] = __expf(bnd[i * 12 + r] - mf[i]) * li[i];
    }
    __syncthreads();

    // epilogue: out[d][i] = O*inv_l + sum_r pb[i][r]*emb_v[r][d], tf32-rounded
    float* om = g_mid + ((size_t)b * CCH + h * HD) * TSEQ;
#pragma unroll
    for (int f = 0; f < 2; f++) {
        int rd = wm2 * 32 + f * 16 + gid;
#pragma unroll
        for (int n = 0; n < 4; n++) {
            int cil = wn2 * 32 + n * 8 + 2 * tig;
            float inv0 = li[cil], inv1 = li[cil + 1];
            float v0 = o[f][n][0] * inv0, v1 = o[f][n][1] * inv1;
            float v2 = o[f][n][2] * inv0, v3 = o[f][n][3] * inv1;
#pragma unroll
            for (int r = 0; r < NR; r++) {
                float p0 = bnd[cil * 12 + r], p1 = bnd[(cil + 1) * 12 + r];
                float e0 = ev[r * HD + rd], e1 = ev[r * HD + rd + 8];
                v0 += p0 * e0; v1 += p1 * e0;
                v2 += p0 * e1; v3 += p1 * e1;
            }
            *(float2*)(om + (size_t)rd * TSEQ + i0 + cil) =
                make_float2(__uint_as_float(f2tf(v0)), __uint_as_float(f2tf(v1)));
            *(float2*)(om + (size_t)(rd + 8) * TSEQ + i0 + cil) =
                make_float2(__uint_as_float(f2tf(v2)), __uint_as_float(f2tf(v3)));
        }
    }
}

// ---------------------------------------------------------------------------
extern "C" void kernel_launch(void* const* d_in, const int* in_sizes, int n_in,
                              void* d_out, int out_size)
{
    const float* x     = (const float*)d_in[0];
    const float* w_q   = (const float*)d_in[1];
    const float* b_q   = (const float*)d_in[2];
    const float* w_k   = (const float*)d_in[3];
    const float* b_k   = (const float*)d_in[4];
    const float* w_v   = (const float*)d_in[5];
    const float* b_v   = (const float*)d_in[6];
    const float* w_o   = (const float*)d_in[7];
    const float* b_o   = (const float*)d_in[8];
    const float* emb_k = (const float*)d_in[9];
    const float* emb_v = (const float*)d_in[10];
    float* out = (float*)d_out;

    cudaFuncSetAttribute(attn_kernel, cudaFuncAttributeMaxDynamicSharedMemorySize, ATTN_SMEM);

    prep_kernel<<<592, 256>>>(x, w_q, w_k, w_v, w_o);

    dim3 gq(CCH / 128, TSEQ / 128, BB * 3);
    qkv_kernel<<<gq, 256>>>(b_q, b_k, b_v);

    dim3 ga(TSEQ / 128, NBH);
    attn_kernel<<<ga, 256, ATTN_SMEM>>>(emb_k, emb_v);

    dim3 go(CCH / 128, TSEQ / 128, BB);
    oproj_kernel<<<go, 256>>>(b_o, out);
}

// round 12
// speedup vs baseline: 2.9973x; 1.0177x over previous
#include <cuda_runtime.h>
#include <math.h>
#include <stdint.h>

#define BB   4
#define TSEQ 1024
#define CCH  768
#define NH   12
#define HD   64
#define NWIN 4
#define NR   9
#define NBH  (BB*NH)   // 48

// Scratch (static __device__ arrays per allocation rules)
static __device__ float g_q[BB*CCH*TSEQ];     // tf32-rounded, q pre-scaled by 1/8
static __device__ float g_k[BB*CCH*TSEQ];     // tf32-rounded
static __device__ float g_v[BB*CCH*TSEQ];     // tf32-rounded
static __device__ float g_mid[BB*CCH*TSEQ];   // attention output (tf32-rounded)
static __device__ float g_x[BB*CCH*TSEQ];     // tf32-rounded input x
static __device__ float g_wq[CCH*CCH];        // tf32-rounded weights
static __device__ float g_wk[CCH*CCH];
static __device__ float g_wv[CCH*CCH];
static __device__ float g_wo[CCH*CCH];

// ---------------------------------------------------------------------------
// tf32 / async helpers
// ---------------------------------------------------------------------------
__device__ __forceinline__ uint32_t f2tf(float x) {
    uint32_t u;
    asm("cvt.rna.tf32.f32 %0, %1;" : "=r"(u) : "f"(x));
    return u;
}
__device__ __forceinline__ float4 rnd4(float4 v) {
    float4 r;
    r.x = __uint_as_float(f2tf(v.x)); r.y = __uint_as_float(f2tf(v.y));
    r.z = __uint_as_float(f2tf(v.z)); r.w = __uint_as_float(f2tf(v.w));
    return r;
}
__device__ __forceinline__ void mma_tf32(float c[4], const uint32_t a[4], const uint32_t b[2]) {
    asm volatile(
        "mma.sync.aligned.m16n8k8.row.col.f32.tf32.tf32.f32 "
        "{%0,%1,%2,%3}, {%4,%5,%6,%7}, {%8,%9}, {%0,%1,%2,%3};\n"
        : "+f"(c[0]), "+f"(c[1]), "+f"(c[2]), "+f"(c[3])
        : "r"(a[0]), "r"(a[1]), "r"(a[2]), "r"(a[3]), "r"(b[0]), "r"(b[1]));
}
__device__ __forceinline__ void cp16(uint32_t dst, const void* src) {
    asm volatile("cp.async.cg.shared.global [%0], [%1], 16;\n" :: "r"(dst), "l"(src));
}
#define CP_COMMIT() asm volatile("cp.async.commit_group;\n")
#define CP_WAIT0()  asm volatile("cp.async.wait_group 0;\n")
#define CP_WAIT1()  asm volatile("cp.async.wait_group 1;\n")

// ---------------------------------------------------------------------------
// Prep: round x and weights to tf32 bit patterns.
// ---------------------------------------------------------------------------
__global__ __launch_bounds__(256)
void prep_kernel(const float* __restrict__ x,
                 const float* __restrict__ wq, const float* __restrict__ wk,
                 const float* __restrict__ wv, const float* __restrict__ wo)
{
    int stride = gridDim.x * blockDim.x;
    int idx = blockIdx.x * blockDim.x + threadIdx.x;
    for (int i = idx; i < BB * CCH * TSEQ / 4; i += stride)
        ((float4*)g_x)[i] = rnd4(((const float4*)x)[i]);
    for (int i = idx; i < CCH * CCH / 4; i += stride) {
        ((float4*)g_wq)[i] = rnd4(((const float4*)wq)[i]);
        ((float4*)g_wk)[i] = rnd4(((const float4*)wk)[i]);
        ((float4*)g_wv)[i] = rnd4(((const float4*)wv)[i]);
        ((float4*)g_wo)[i] = rnd4(((const float4*)wo)[i]);
    }
}

// ---------------------------------------------------------------------------
// Projection GEMM: Out[o,t] = (sum_c W[o,c]*X[c,t] + bias[o]) * scale
// 128x128 block, BK=16, 3-stage cp.async pipeline, 8 warps (4m x 2n),
// warp tile 32x64, 2 CTAs/SM. round_out: store tf32-rounded bits.
// ---------------------------------------------------------------------------
__device__ __forceinline__ void proj_body(
    const float* __restrict__ X, const float* __restrict__ W,
    const float* __restrict__ bias, float* __restrict__ Out, float scale,
    bool round_out)
{
    __shared__ float As[3][128 * 20];    // [m][k], stride 20
    __shared__ float Bs[3][16 * 136];    // [k][n], stride 136

    int tid = threadIdx.x;
    int lane = tid & 31, wid = tid >> 5;
    int wm = wid >> 1, wn = wid & 1;
    int gid = lane >> 2, tig = lane & 3;
    int o0 = blockIdx.x * 128, t0 = blockIdx.y * 128;

    const uint32_t aS = (uint32_t)__cvta_generic_to_shared(&As[0][0]);
    const uint32_t bS = (uint32_t)__cvta_generic_to_shared(&Bs[0][0]);
    const uint32_t aBuf = 128 * 20 * 4, bBuf = 16 * 136 * 4;

    const float* aptr[2]; const float* bptr[2];
    uint32_t adst[2], bdst[2];
#pragma unroll
    for (int p = 0; p < 2; p++) {
        int fl = tid + p * 256;
        int am = fl >> 2, ac4 = (fl & 3) * 4;
        aptr[p] = W + (size_t)(o0 + am) * CCH + ac4;
        adst[p] = aS + (uint32_t)(am * 20 + ac4) * 4;
        int bk = fl >> 5, bt4 = (fl & 31) * 4;
        bptr[p] = X + (size_t)bk * TSEQ + t0 + bt4;
        bdst[p] = bS + (uint32_t)(bk * 136 + bt4) * 4;
    }

    float c[2][8][4];
#pragma unroll
    for (int f = 0; f < 2; f++)
#pragma unroll
        for (int n = 0; n < 8; n++)
#pragma unroll
            for (int q = 0; q < 4; q++) c[f][n][q] = 0.f;

    auto issue = [&](int buf, int s) {
#pragma unroll
        for (int p = 0; p < 2; p++) {
            cp16(adst[p] + buf * aBuf, aptr[p] + s * 16);
            cp16(bdst[p] + buf * bBuf, bptr[p] + (size_t)s * 16 * TSEQ);
        }
    };

    issue(0, 0); CP_COMMIT();
    issue(1, 1); CP_COMMIT();

    const int NS = CCH / 16;   // 48
    int cur = 0;
    for (int s = 0; s < NS; s++) {
        if (s == NS - 1) { CP_WAIT0(); } else { CP_WAIT1(); }
        __syncthreads();
        if (s + 2 < NS) {
            int nb = cur + 2; if (nb >= 3) nb -= 3;
            issue(nb, s + 2); CP_COMMIT();
        }
        const float* Ac = As[cur];
        const float* Bc = Bs[cur];
#pragma unroll
        for (int kk = 0; kk < 16; kk += 8) {
            uint32_t a[2][4], b[8][2];
#pragma unroll
            for (int f = 0; f < 2; f++) {
                int rb = wm * 32 + f * 16 + gid;
                a[f][0] = __float_as_uint(Ac[rb * 20 + kk + tig]);
                a[f][1] = __float_as_uint(Ac[(rb + 8) * 20 + kk + tig]);
                a[f][2] = __float_as_uint(Ac[rb * 20 + kk + tig + 4]);
                a[f][3] = __float_as_uint(Ac[(rb + 8) * 20 + kk + tig + 4]);
            }
#pragma unroll
            for (int n = 0; n < 8; n++) {
                int col = wn * 64 + n * 8 + gid;
                b[n][0] = __float_as_uint(Bc[(kk + tig) * 136 + col]);
                b[n][1] = __float_as_uint(Bc[(kk + tig + 4) * 136 + col]);
            }
#pragma unroll
            for (int f = 0; f < 2; f++)
#pragma unroll
                for (int n = 0; n < 8; n++) mma_tf32(c[f][n], a[f], b[n]);
        }
        if (++cur >= 3) cur = 0;
    }

#pragma unroll
    for (int f = 0; f < 2; f++) {
        int ro = o0 + wm * 32 + f * 16 + gid;
        float bv0 = bias[ro], bv1 = bias[ro + 8];
#pragma unroll
        for (int n = 0; n < 8; n++) {
            int col = t0 + wn * 64 + n * 8 + 2 * tig;
            float u0 = (c[f][n][0] + bv0) * scale, u1 = (c[f][n][1] + bv0) * scale;
            float u2 = (c[f][n][2] + bv1) * scale, u3 = (c[f][n][3] + bv1) * scale;
            if (round_out) {
                u0 = __uint_as_float(f2tf(u0)); u1 = __uint_as_float(f2tf(u1));
                u2 = __uint_as_float(f2tf(u2)); u3 = __uint_as_float(f2tf(u3));
            }
            *(float2*)(Out + (size_t)ro * TSEQ + col) = make_float2(u0, u1);
            *(float2*)(Out + (size_t)(ro + 8) * TSEQ + col) = make_float2(u2, u3);
        }
    }
}

__global__ __launch_bounds__(256, 2)
void qkv_kernel(const float* __restrict__ Bq, const float* __restrict__ Bk,
                const float* __restrict__ Bv)
{
    int zb = blockIdx.z;
    int b = zb / 3, which = zb % 3;
    const float* Wm = (which == 0) ? g_wq : ((which == 1) ? g_wk : g_wv);
    const float* Bi = (which == 0) ? Bq : ((which == 1) ? Bk : Bv);
    float* Out = (which == 0) ? g_q : ((which == 1) ? g_k : g_v);
    float scale = (which == 0) ? 0.125f : 1.0f;
    proj_body(g_x + (size_t)b * CCH * TSEQ, Wm, Bi, Out + (size_t)b * CCH * TSEQ, scale, true);
}

__global__ __launch_bounds__(256, 2)
void oproj_kernel(const float* __restrict__ Bi, float* __restrict__ Out)
{
    int b = blockIdx.z;
    proj_body(g_mid + (size_t)b * CCH * TSEQ, g_wo, Bi, Out + (size_t)b * CCH * TSEQ, 1.0f, false);
}

// ---------------------------------------------------------------------------
// Fused flash attention. Block = (bh, 128-row i-tile), 256 threads (8 warps).
// j processed in 16 chunks of 64, K/V double-buffered via cp.async.
// S phase: warp w owns rows w*16..+16 x 64 j. AV: [m=d 64][n=i 128], 2m x 4n.
// Inputs are pre-rounded tf32 bits -> no cvt in the mainloop.
// ---------------------------------------------------------------------------
#define BJ 64
#define NJT (TSEQ / BJ)       // 16
#define KW  (64 * 72)         // Ks words per buffer (stride 72)
#define VW  (64 * 68)         // Vs words per buffer (stride 68)
#define ATTN_SMEM 157696

__global__ __launch_bounds__(256, 1)
void attn_kernel(const float* __restrict__ emb_k, const float* __restrict__ emb_v)
{
    extern __shared__ char smc[];
    uint32_t* Qs = (uint32_t*)smc;          // [k=d 64][m=i 128] stride 136
    uint32_t* Ks = Qs + 64 * 136;           // 2 x [k=d 64][j 64] stride 72
    uint32_t* Vs = Ks + 2 * KW;             // 2 x [m=d 64][j 64] stride 68
    uint32_t* Ps = Vs + 2 * VW;             // [n=i 128][k=j 64] stride 68
    float* Rk  = (float*)(Ps + 128 * 68);   // [128][10]
    float* bnd = Rk + 128 * 10;             // [128][10]
    float* ek  = bnd + 128 * 10;            // [9][64]
    float* ev  = ek + NR * HD;              // [9][64]
    float* sc  = ev + NR * HD;              // [128]
    float* mf  = sc + 128;                  // [128]
    float* li  = mf + 128;                  // [128]

    int bh = blockIdx.y;
    int i0 = blockIdx.x * 128;
    int b = bh / NH, h = bh % NH;
    const float* qb = g_q + ((size_t)b * CCH + h * HD) * TSEQ;
    const float* kb = g_k + ((size_t)b * CCH + h * HD) * TSEQ;
    const float* vb = g_v + ((size_t)b * CCH + h * HD) * TSEQ;

    int tid = threadIdx.x;
    int lane = tid & 31, wid = tid >> 5;
    int gid = lane >> 2, tig = lane & 3;
    int wm2 = wid >> 2, wn2 = wid & 3;

    const uint32_t qS = (uint32_t)__cvta_generic_to_shared(Qs);
    const uint32_t kS = (uint32_t)__cvta_generic_to_shared(Ks);
    const uint32_t vS = (uint32_t)__cvta_generic_to_shared(Vs);

    // ---- prologue: async Q + K0 + V0 ----
#pragma unroll
    for (int p = 0; p < 8; p++) {
        int fl = tid + p * 256;
        int d = fl >> 5, c4 = (fl & 31) * 4;
        cp16(qS + (uint32_t)(d * 136 + c4) * 4, qb + (size_t)d * TSEQ + i0 + c4);
    }
#pragma unroll
    for (int p = 0; p < 4; p++) {
        int fl = tid + p * 256;
        int d = fl >> 4, c4 = (fl & 15) * 4;
        cp16(kS + (uint32_t)(d * 72 + c4) * 4, kb + (size_t)d * TSEQ + c4);
        cp16(vS + (uint32_t)(d * 68 + c4) * 4, vb + (size_t)d * TSEQ + c4);
    }
    CP_COMMIT();

    for (int idx = tid; idx < NR * HD; idx += 256) { ek[idx] = emb_k[idx]; ev[idx] = emb_v[idx]; }
    for (int idx = tid; idx < 128 * 10; idx += 256) bnd[idx] = -1e30f;

    CP_WAIT0();
    __syncthreads();

    // Rk[i][r] = sum_d q[d][i] * emb_k[r][d]
    for (int idx = tid; idx < 128 * NR; idx += 256) {
        int i = idx / NR, r = idx - i * NR;
        float acc = 0.f;
#pragma unroll
        for (int d = 0; d < HD; d++)
            acc += __uint_as_float(Qs[d * 136 + i]) * ek[r * HD + d];
        Rk[i * 10 + r] = acc;
    }
    __syncthreads();

    float ms0 = -1e30f, ms1 = -1e30f, ls0 = 0.f, ls1 = 0.f;
    float o[2][4][4];
#pragma unroll
    for (int f = 0; f < 2; f++)
#pragma unroll
        for (int n = 0; n < 4; n++)
#pragma unroll
            for (int q = 0; q < 4; q++) o[f][n][q] = 0.f;

    int mb = wid * 16 + gid;

    for (int jt = 0; jt < NJT; jt++) {
        int cur = jt & 1;
        // ---- issue next chunk's K/V copies (overlap with this chunk's math) ----
        if (jt + 1 < NJT) {
            int j1 = (jt + 1) * BJ;
            int nb = (jt + 1) & 1;
#pragma unroll
            for (int p = 0; p < 4; p++) {
                int fl = tid + p * 256;
                int d = fl >> 4, c4 = (fl & 15) * 4;
                cp16(kS + (uint32_t)(nb * KW + d * 72 + c4) * 4, kb + (size_t)d * TSEQ + j1 + c4);
                cp16(vS + (uint32_t)(nb * VW + d * 68 + c4) * 4, vb + (size_t)d * TSEQ + j1 + c4);
            }
            CP_COMMIT();
        }
        const uint32_t* Kc = Ks + cur * KW;
        const uint32_t* Vc = Vs + cur * VW;

        // ---- S = Q.K : warp wid owns rows mb..mb+15, 64 cols ----
        float c[8][4];
#pragma unroll
        for (int n = 0; n < 8; n++)
#pragma unroll
            for (int q = 0; q < 4; q++) c[n][q] = 0.f;

#pragma unroll
        for (int ks = 0; ks < 8; ks++) {
            int k0 = ks * 8;
            uint32_t a[4];
            a[0] = Qs[(k0 + tig) * 136 + mb];
            a[1] = Qs[(k0 + tig) * 136 + mb + 8];
            a[2] = Qs[(k0 + tig + 4) * 136 + mb];
            a[3] = Qs[(k0 + tig + 4) * 136 + mb + 8];
#pragma unroll
            for (int n = 0; n < 8; n++) {
                uint32_t bb[2];
                bb[0] = Kc[(k0 + tig) * 72 + n * 8 + gid];
                bb[1] = Kc[(k0 + tig + 4) * 72 + n * 8 + gid];
                mma_tf32(c[n], a, bb);
            }
        }

        // ---- rel-k add + raw band stash ----
        int dj = jt * BJ - i0;
        if (dj >= -67 && dj <= 131) {
#pragma unroll
            for (int n = 0; n < 8; n++) {
#pragma unroll
                for (int q = 0; q < 4; q++) {
                    int ir = mb + ((q >> 1) << 3);
                    int jc = n * 8 + 2 * tig + (q & 1);
                    int r = dj + jc - ir + NWIN;
                    if (r >= 0 && r < NR) {
                        c[n][q] += Rk[ir * 10 + r];
                        bnd[ir * 10 + r] = c[n][q];
                    }
                }
            }
        }

        // ---- online softmax (rows mb / mb+8) ----
        float mx0 = -1e30f, mx1 = -1e30f;
#pragma unroll
        for (int n = 0; n < 8; n++) {
            mx0 = fmaxf(mx0, fmaxf(c[n][0], c[n][1]));
            mx1 = fmaxf(mx1, fmaxf(c[n][2], c[n][3]));
        }
        mx0 = fmaxf(mx0, __shfl_xor_sync(0xffffffffu, mx0, 1));
        mx0 = fmaxf(mx0, __shfl_xor_sync(0xffffffffu, mx0, 2));
        mx1 = fmaxf(mx1, __shfl_xor_sync(0xffffffffu, mx1, 1));
        mx1 = fmaxf(mx1, __shfl_xor_sync(0xffffffffu, mx1, 2));
        float nm0 = fmaxf(ms0, mx0), nm1 = fmaxf(ms1, mx1);
        float al0 = __expf(ms0 - nm0), al1 = __expf(ms1 - nm1);

        float s0 = 0.f, s1 = 0.f;
#pragma unroll
        for (int n = 0; n < 8; n++) {
            c[n][0] = __expf(c[n][0] - nm0); s0 += c[n][0];
            c[n][1] = __expf(c[n][1] - nm0); s0 += c[n][1];
            c[n][2] = __expf(c[n][2] - nm1); s1 += c[n][2];
            c[n][3] = __expf(c[n][3] - nm1); s1 += c[n][3];
        }
        s0 += __shfl_xor_sync(0xffffffffu, s0, 1);
        s0 += __shfl_xor_sync(0xffffffffu, s0, 2);
        s1 += __shfl_xor_sync(0xffffffffu, s1, 1);
        s1 += __shfl_xor_sync(0xffffffffu, s1, 2);
        ls0 = ls0 * al0 + s0;
        ls1 = ls1 * al1 + s1;
        ms0 = nm0; ms1 = nm1;
        if (tig == 0) { sc[mb] = al0; sc[mb + 8] = al1; }

        // ---- write P (tf32) [i][j] stride 68 ----
#pragma unroll
        for (int n = 0; n < 8; n++) {
            int jc = n * 8 + 2 * tig;
            uint2 p0 = make_uint2(f2tf(c[n][0]), f2tf(c[n][1]));
            uint2 p1 = make_uint2(f2tf(c[n][2]), f2tf(c[n][3]));
            *(uint2*)&Ps[mb * 68 + jc] = p0;
            *(uint2*)&Ps[(mb + 8) * 68 + jc] = p1;
        }
        __syncthreads();

        // ---- rescale O, then O += V @ P ----
#pragma unroll
        for (int n = 0; n < 4; n++) {
            int col = wn2 * 32 + n * 8 + 2 * tig;
            float s0v = sc[col], s1v = sc[col + 1];
#pragma unroll
            for (int f = 0; f < 2; f++) {
                o[f][n][0] *= s0v; o[f][n][1] *= s1v;
                o[f][n][2] *= s0v; o[f][n][3] *= s1v;
            }
        }
#pragma unroll
        for (int ks = 0; ks < 8; ks++) {
            int k0 = ks * 8;
            uint32_t a[2][4];
#pragma unroll
            for (int f = 0; f < 2; f++) {
                int rb = wm2 * 32 + f * 16 + gid;
                a[f][0] = Vc[rb * 68 + k0 + tig];
                a[f][1] = Vc[(rb + 8) * 68 + k0 + tig];
                a[f][2] = Vc[rb * 68 + k0 + tig + 4];
                a[f][3] = Vc[(rb + 8) * 68 + k0 + tig + 4];
            }
#pragma unroll
            for (int n = 0; n < 4; n++) {
                uint32_t bb[2];
                int coln = wn2 * 32 + n * 8 + gid;
                bb[0] = Ps[coln * 68 + k0 + tig];
                bb[1] = Ps[coln * 68 + k0 + tig + 4];
#pragma unroll
                for (int f = 0; f < 2; f++) mma_tf32(o[f][n], a[f], bb);
            }
        }
        if (jt + 1 < NJT) CP_WAIT0();
        __syncthreads();
    }

    // ---- final stats ----
    if (tig == 0) {
        mf[mb] = ms0; mf[mb + 8] = ms1;
        li[mb] = 1.f / ls0; li[mb + 8] = 1.f / ls1;
    }
    __syncthreads();

    for (int idx = tid; idx < 128 * NR; idx += 256) {
        int i = idx / NR, r = idx - i * NR;
        bnd[i * 10 + r] = __expf(bnd[i * 10 + r] - mf[i]) * li[i];
    }
    __syncthreads();

    // ---- epilogue: out[d][i] = O*inv_l + sum_r pb[i][r]*emb_v[r][d] (tf32) ----
    float* om = g_mid + ((size_t)b * CCH + h * HD) * TSEQ;
#pragma unroll
    for (int f = 0; f < 2; f++) {
        int rd = wm2 * 32 + f * 16 + gid;
#pragma unroll
        for (int n = 0; n < 4; n++) {
            int cil = wn2 * 32 + n * 8 + 2 * tig;
            float inv0 = li[cil], inv1 = li[cil + 1];
            float v0 = o[f][n][0] * inv0, v1 = o[f][n][1] * inv1;
            float v2 = o[f][n][2] * inv0, v3 = o[f][n][3] * inv1;
#pragma unroll
            for (int r = 0; r < NR; r++) {
                float p0 = bnd[cil * 10 + r], p1 = bnd[(cil + 1) * 10 + r];
                float e0 = ev[r * HD + rd], e1 = ev[r * HD + rd + 8];
                v0 += p0 * e0; v1 += p1 * e0;
                v2 += p0 * e1; v3 += p1 * e1;
            }
            *(float2*)(om + (size_t)rd * TSEQ + i0 + cil) =
                make_float2(__uint_as_float(f2tf(v0)), __uint_as_float(f2tf(v1)));
            *(float2*)(om + (size_t)(rd + 8) * TSEQ + i0 + cil) =
                make_float2(__uint_as_float(f2tf(v2)), __uint_as_float(f2tf(v3)));
        }
    }
}

// ---------------------------------------------------------------------------
extern "C" void kernel_launch(void* const* d_in, const int* in_sizes, int n_in,
                              void* d_out, int out_size)
{
    const float* x     = (const float*)d_in[0];
    const float* b_q   = (const float*)d_in[2];
    const float* b_k   = (const float*)d_in[4];
    const float* b_v   = (const float*)d_in[6];
    const float* b_o   = (const float*)d_in[8];
    const float* w_q   = (const float*)d_in[1];
    const float* w_k   = (const float*)d_in[3];
    const float* w_v   = (const float*)d_in[5];
    const float* w_o   = (const float*)d_in[7];
    const float* emb_k = (const float*)d_in[9];
    const float* emb_v = (const float*)d_in[10];
    float* out = (float*)d_out;

    cudaFuncSetAttribute(attn_kernel, cudaFuncAttributeMaxDynamicSharedMemorySize, ATTN_SMEM);

    prep_kernel<<<592, 256>>>(x, w_q, w_k, w_v, w_o);

    dim3 gq(CCH / 128, TSEQ / 128, BB * 3);
    qkv_kernel<<<gq, 256>>>(b_q, b_k, b_v);

    dim3 ga(TSEQ / 128, NBH);
    attn_kernel<<<ga, 256, ATTN_SMEM>>>(emb_k, emb_v);

    dim3 go(CCH / 128, TSEQ / 128, BB);
    oproj_kernel<<<go, 256>>>(b_o, out);
}

// round 13
// speedup vs baseline: 3.0009x; 1.0012x over previous
#include <cuda_runtime.h>
#include <math.h>
#include <stdint.h>

#define BB   4
#define TSEQ 1024
#define CCH  768
#define NH   12
#define HD   64
#define NWIN 4
#define NR   9
#define NBH  (BB*NH)   // 48

// Scratch (static __device__ arrays per allocation rules)
static __device__ float g_q[BB*CCH*TSEQ];     // tf32-rounded, q pre-scaled by 1/8
static __device__ float g_k[BB*CCH*TSEQ];     // tf32-rounded
static __device__ float g_v[BB*CCH*TSEQ];     // tf32-rounded
static __device__ float g_mid[BB*CCH*TSEQ];   // attention output (tf32-rounded)
static __device__ float g_x[BB*CCH*TSEQ];     // tf32-rounded input x
static __device__ float g_wq[CCH*CCH];        // tf32-rounded weights
static __device__ float g_wk[CCH*CCH];
static __device__ float g_wv[CCH*CCH];
static __device__ float g_wo[CCH*CCH];

// ---------------------------------------------------------------------------
// tf32 / async helpers
// ---------------------------------------------------------------------------
__device__ __forceinline__ uint32_t f2tf(float x) {
    uint32_t u;
    asm("cvt.rna.tf32.f32 %0, %1;" : "=r"(u) : "f"(x));
    return u;
}
__device__ __forceinline__ float4 rnd4(float4 v) {
    float4 r;
    r.x = __uint_as_float(f2tf(v.x)); r.y = __uint_as_float(f2tf(v.y));
    r.z = __uint_as_float(f2tf(v.z)); r.w = __uint_as_float(f2tf(v.w));
    return r;
}
__device__ __forceinline__ void mma_tf32(float c[4], const uint32_t a[4], const uint32_t b[2]) {
    asm volatile(
        "mma.sync.aligned.m16n8k8.row.col.f32.tf32.tf32.f32 "
        "{%0,%1,%2,%3}, {%4,%5,%6,%7}, {%8,%9}, {%0,%1,%2,%3};\n"
        : "+f"(c[0]), "+f"(c[1]), "+f"(c[2]), "+f"(c[3])
        : "r"(a[0]), "r"(a[1]), "r"(a[2]), "r"(a[3]), "r"(b[0]), "r"(b[1]));
}
__device__ __forceinline__ void cp16(uint32_t dst, const void* src) {
    asm volatile("cp.async.cg.shared.global [%0], [%1], 16;\n" :: "r"(dst), "l"(src));
}
#define CP_COMMIT() asm volatile("cp.async.commit_group;\n")
#define CP_WAIT0()  asm volatile("cp.async.wait_group 0;\n")
#define CP_WAIT1()  asm volatile("cp.async.wait_group 1;\n")

// ---------------------------------------------------------------------------
// Prep: round x and weights to tf32 bit patterns.
// ---------------------------------------------------------------------------
__global__ __launch_bounds__(256)
void prep_kernel(const float* __restrict__ x,
                 const float* __restrict__ wq, const float* __restrict__ wk,
                 const float* __restrict__ wv, const float* __restrict__ wo)
{
    int stride = gridDim.x * blockDim.x;
    int idx = blockIdx.x * blockDim.x + threadIdx.x;
    for (int i = idx; i < BB * CCH * TSEQ / 4; i += stride)
        ((float4*)g_x)[i] = rnd4(((const float4*)x)[i]);
    for (int i = idx; i < CCH * CCH / 4; i += stride) {
        ((float4*)g_wq)[i] = rnd4(((const float4*)wq)[i]);
        ((float4*)g_wk)[i] = rnd4(((const float4*)wk)[i]);
        ((float4*)g_wv)[i] = rnd4(((const float4*)wv)[i]);
        ((float4*)g_wo)[i] = rnd4(((const float4*)wo)[i]);
    }
}

// ---------------------------------------------------------------------------
// Projection GEMM: Out[o,t] = (sum_c W[o,c]*X[c,t] + bias[o]) * scale
// 128xBN block, BK=16, 3-stage cp.async pipeline, 8 warps (4m x 2n),
// warp tile 32x(BN/2), 2 CTAs/SM.
// ---------------------------------------------------------------------------
template<int BN>
__device__ __forceinline__ void proj_body(
    const float* __restrict__ X, const float* __restrict__ W,
    const float* __restrict__ bias, float* __restrict__ Out, float scale,
    bool round_out)
{
    constexpr int BSTR = (BN == 128) ? 136 : 72;
    constexpr int NSUB = BN / 16;          // n-subtiles per warp
    constexpr int NBCP = BN / 64;          // b cp16s per thread (2 or 1)
    constexpr int B4   = BN / 4;           // float4s per B row

    __shared__ float As[3][128 * 20];      // [m][k], stride 20
    __shared__ float Bs[3][16 * BSTR];     // [k][n]

    int tid = threadIdx.x;
    int lane = tid & 31, wid = tid >> 5;
    int wm = wid >> 1, wn = wid & 1;
    int gid = lane >> 2, tig = lane & 3;
    int o0 = blockIdx.x * 128, t0 = blockIdx.y * BN;

    const uint32_t aS = (uint32_t)__cvta_generic_to_shared(&As[0][0]);
    const uint32_t bS = (uint32_t)__cvta_generic_to_shared(&Bs[0][0]);
    const uint32_t aBuf = 128 * 20 * 4, bBuf = 16 * BSTR * 4;

    const float* aptr[2]; uint32_t adst[2];
#pragma unroll
    for (int p = 0; p < 2; p++) {
        int fl = tid + p * 256;
        int am = fl >> 2, ac4 = (fl & 3) * 4;
        aptr[p] = W + (size_t)(o0 + am) * CCH + ac4;
        adst[p] = aS + (uint32_t)(am * 20 + ac4) * 4;
    }
    const float* bptr[2]; uint32_t bdst[2];
#pragma unroll
    for (int p = 0; p < NBCP; p++) {
        int fl = tid + p * 256;
        int bk = fl / B4, bt4 = (fl % B4) * 4;
        bptr[p] = X + (size_t)bk * TSEQ + t0 + bt4;
        bdst[p] = bS + (uint32_t)(bk * BSTR + bt4) * 4;
    }

    float c[2][NSUB][4];
#pragma unroll
    for (int f = 0; f < 2; f++)
#pragma unroll
        for (int n = 0; n < NSUB; n++)
#pragma unroll
            for (int q = 0; q < 4; q++) c[f][n][q] = 0.f;

    auto issue = [&](int buf, int s) {
#pragma unroll
        for (int p = 0; p < 2; p++)
            cp16(adst[p] + buf * aBuf, aptr[p] + s * 16);
#pragma unroll
        for (int p = 0; p < NBCP; p++)
            cp16(bdst[p] + buf * bBuf, bptr[p] + (size_t)s * 16 * TSEQ);
    };

    issue(0, 0); CP_COMMIT();
    issue(1, 1); CP_COMMIT();

    const int NS = CCH / 16;   // 48
    int cur = 0;
    for (int s = 0; s < NS; s++) {
        if (s == NS - 1) { CP_WAIT0(); } else { CP_WAIT1(); }
        __syncthreads();
        if (s + 2 < NS) {
            int nb = cur + 2; if (nb >= 3) nb -= 3;
            issue(nb, s + 2); CP_COMMIT();
        }
        const float* Ac = As[cur];
        const float* Bc = Bs[cur];
#pragma unroll
        for (int kk = 0; kk < 16; kk += 8) {
            uint32_t a[2][4], b[NSUB][2];
#pragma unroll
            for (int f = 0; f < 2; f++) {
                int rb = wm * 32 + f * 16 + gid;
                a[f][0] = __float_as_uint(Ac[rb * 20 + kk + tig]);
                a[f][1] = __float_as_uint(Ac[(rb + 8) * 20 + kk + tig]);
                a[f][2] = __float_as_uint(Ac[rb * 20 + kk + tig + 4]);
                a[f][3] = __float_as_uint(Ac[(rb + 8) * 20 + kk + tig + 4]);
            }
#pragma unroll
            for (int n = 0; n < NSUB; n++) {
                int col = wn * (BN / 2) + n * 8 + gid;
                b[n][0] = __float_as_uint(Bc[(kk + tig) * BSTR + col]);
                b[n][1] = __float_as_uint(Bc[(kk + tig + 4) * BSTR + col]);
            }
#pragma unroll
            for (int f = 0; f < 2; f++)
#pragma unroll
                for (int n = 0; n < NSUB; n++) mma_tf32(c[f][n], a[f], b[n]);
        }
        if (++cur >= 3) cur = 0;
    }

#pragma unroll
    for (int f = 0; f < 2; f++) {
        int ro = o0 + wm * 32 + f * 16 + gid;
        float bv0 = bias[ro], bv1 = bias[ro + 8];
#pragma unroll
        for (int n = 0; n < NSUB; n++) {
            int col = t0 + wn * (BN / 2) + n * 8 + 2 * tig;
            float u0 = (c[f][n][0] + bv0) * scale, u1 = (c[f][n][1] + bv0) * scale;
            float u2 = (c[f][n][2] + bv1) * scale, u3 = (c[f][n][3] + bv1) * scale;
            if (round_out) {
                u0 = __uint_as_float(f2tf(u0)); u1 = __uint_as_float(f2tf(u1));
                u2 = __uint_as_float(f2tf(u2)); u3 = __uint_as_float(f2tf(u3));
            }
            *(float2*)(Out + (size_t)ro * TSEQ + col) = make_float2(u0, u1);
            *(float2*)(Out + (size_t)(ro + 8) * TSEQ + col) = make_float2(u2, u3);
        }
    }
}

__global__ __launch_bounds__(256, 2)
void qkv_kernel(const float* __restrict__ Bq, const float* __restrict__ Bk,
                const float* __restrict__ Bv)
{
    int zb = blockIdx.z;
    int b = zb / 3, which = zb % 3;
    const float* Wm = (which == 0) ? g_wq : ((which == 1) ? g_wk : g_wv);
    const float* Bi = (which == 0) ? Bq : ((which == 1) ? Bk : Bv);
    float* Out = (which == 0) ? g_q : ((which == 1) ? g_k : g_v);
    float scale = (which == 0) ? 0.125f : 1.0f;
    proj_body<128>(g_x + (size_t)b * CCH * TSEQ, Wm, Bi, Out + (size_t)b * CCH * TSEQ, scale, true);
}

__global__ __launch_bounds__(256, 2)
void oproj_kernel(const float* __restrict__ Bi, float* __restrict__ Out)
{
    int b = blockIdx.z;
    proj_body<64>(g_mid + (size_t)b * CCH * TSEQ, g_wo, Bi, Out + (size_t)b * CCH * TSEQ, 1.0f, false);
}

// ---------------------------------------------------------------------------
// Fused flash attention. Block = (bh, 128-row i-tile), 256 threads (8 warps),
// 2 CTAs/SM. j in 32 chunks of 32, K/V double-buffered via cp.async.
// S phase: warp w owns rows w*16..+16 x 32 j. AV: [m=d 64][n=i 128], 2m x 4n.
// ---------------------------------------------------------------------------
#define BJ 32
#define NJT (TSEQ / BJ)       // 32
#define KSTR 40
#define VSTR 36
#define PSTR 36
#define KW  (64 * KSTR)       // 2560 words per K buffer
#define VW  (64 * VSTR)       // 2304 words per V buffer
#define ATTN_SMEM 108544

__global__ __launch_bounds__(256, 2)
void attn_kernel(const float* __restrict__ emb_k, const float* __restrict__ emb_v)
{
    extern __shared__ char smc[];
    uint32_t* Qs = (uint32_t*)smc;          // [k=d 64][m=i 128] stride 136
    uint32_t* Ks = Qs + 64 * 136;           // 2 x [d 64][j 32] stride 40
    uint32_t* Vs = Ks + 2 * KW;             // 2 x [d 64][j 32] stride 36
    uint32_t* Ps = Vs + 2 * VW;             // [i 128][j 32] stride 36
    float* Rk  = (float*)(Ps + 128 * PSTR); // [128][10]
    float* bnd = Rk + 128 * 10;             // [128][10]
    float* ek  = bnd + 128 * 10;            // [9][64]
    float* ev  = ek + NR * HD;              // [9][64]
    float* sc  = ev + NR * HD;              // [128]
    float* mf  = sc + 128;                  // [128]
    float* li  = mf + 128;                  // [128]

    int bh = blockIdx.y;
    int i0 = blockIdx.x * 128;
    int b = bh / NH, h = bh % NH;
    const float* qb = g_q + ((size_t)b * CCH + h * HD) * TSEQ;
    const float* kb = g_k + ((size_t)b * CCH + h * HD) * TSEQ;
    const float* vb = g_v + ((size_t)b * CCH + h * HD) * TSEQ;

    int tid = threadIdx.x;
    int lane = tid & 31, wid = tid >> 5;
    int gid = lane >> 2, tig = lane & 3;
    int wm2 = wid >> 2, wn2 = wid & 3;

    const uint32_t qS = (uint32_t)__cvta_generic_to_shared(Qs);
    const uint32_t kS = (uint32_t)__cvta_generic_to_shared(Ks);
    const uint32_t vS = (uint32_t)__cvta_generic_to_shared(Vs);

    // copy coordinates for K/V chunks: 64 rows x 32 cols = 512 float4
    int cd = tid >> 3, cc4 = (tid & 7) * 4;          // p=0
    int cd1 = (tid + 256) >> 3;                      // p=1 row

    // ---- prologue: async Q + K0 + V0 ----
#pragma unroll
    for (int p = 0; p < 8; p++) {
        int fl = tid + p * 256;
        int d = fl >> 5, c4 = (fl & 31) * 4;
        cp16(qS + (uint32_t)(d * 136 + c4) * 4, qb + (size_t)d * TSEQ + i0 + c4);
    }
    cp16(kS + (uint32_t)(cd * KSTR + cc4) * 4, kb + (size_t)cd * TSEQ + cc4);
    cp16(kS + (uint32_t)(cd1 * KSTR + cc4) * 4, kb + (size_t)cd1 * TSEQ + cc4);
    cp16(vS + (uint32_t)(cd * VSTR + cc4) * 4, vb + (size_t)cd * TSEQ + cc4);
    cp16(vS + (uint32_t)(cd1 * VSTR + cc4) * 4, vb + (size_t)cd1 * TSEQ + cc4);
    CP_COMMIT();

    for (int idx = tid; idx < NR * HD; idx += 256) { ek[idx] = emb_k[idx]; ev[idx] = emb_v[idx]; }
    for (int idx = tid; idx < 128 * 10; idx += 256) bnd[idx] = -1e30f;

    CP_WAIT0();
    __syncthreads();

    // Rk[i][r] = sum_d q[d][i] * emb_k[r][d]
    for (int idx = tid; idx < 128 * NR; idx += 256) {
        int i = idx / NR, r = idx - i * NR;
        float acc = 0.f;
#pragma unroll
        for (int d = 0; d < HD; d++)
            acc += __uint_as_float(Qs[d * 136 + i]) * ek[r * HD + d];
        Rk[i * 10 + r] = acc;
    }
    __syncthreads();

    float ms0 = -1e30f, ms1 = -1e30f, ls0 = 0.f, ls1 = 0.f;
    float o[2][4][4];
#pragma unroll
    for (int f = 0; f < 2; f++)
#pragma unroll
        for (int n = 0; n < 4; n++)
#pragma unroll
            for (int q = 0; q < 4; q++) o[f][n][q] = 0.f;

    int mb = wid * 16 + gid;

    for (int jt = 0; jt < NJT; jt++) {
        int cur = jt & 1;
        // ---- issue next chunk's K/V copies ----
        if (jt + 1 < NJT) {
            int j1 = (jt + 1) * BJ;
            int nb = (jt + 1) & 1;
            cp16(kS + (uint32_t)(nb * KW + cd * KSTR + cc4) * 4, kb + (size_t)cd * TSEQ + j1 + cc4);
            cp16(kS + (uint32_t)(nb * KW + cd1 * KSTR + cc4) * 4, kb + (size_t)cd1 * TSEQ + j1 + cc4);
            cp16(vS + (uint32_t)(nb * VW + cd * VSTR + cc4) * 4, vb + (size_t)cd * TSEQ + j1 + cc4);
            cp16(vS + (uint32_t)(nb * VW + cd1 * VSTR + cc4) * 4, vb + (size_t)cd1 * TSEQ + j1 + cc4);
            CP_COMMIT();
        }
        const uint32_t* Kc = Ks + cur * KW;
        const uint32_t* Vc = Vs + cur * VW;

        // ---- S = Q.K : warp wid owns rows mb..mb+15, 32 cols ----
        float c[4][4];
#pragma unroll
        for (int n = 0; n < 4; n++)
#pragma unroll
            for (int q = 0; q < 4; q++) c[n][q] = 0.f;

#pragma unroll
        for (int ks = 0; ks < 8; ks++) {
            int k0 = ks * 8;
            uint32_t a[4];
            a[0] = Qs[(k0 + tig) * 136 + mb];
            a[1] = Qs[(k0 + tig) * 136 + mb + 8];
            a[2] = Qs[(k0 + tig + 4) * 136 + mb];
            a[3] = Qs[(k0 + tig + 4) * 136 + mb + 8];
#pragma unroll
            for (int n = 0; n < 4; n++) {
                uint32_t bb[2];
                bb[0] = Kc[(k0 + tig) * KSTR + n * 8 + gid];
                bb[1] = Kc[(k0 + tig + 4) * KSTR + n * 8 + gid];
                mma_tf32(c[n], a, bb);
            }
        }

        // ---- rel-k add + raw band stash ----
        int dj = jt * BJ - i0;
        if (dj >= -35 && dj <= 131) {
#pragma unroll
            for (int n = 0; n < 4; n++) {
#pragma unroll
                for (int q = 0; q < 4; q++) {
                    int ir = mb + ((q >> 1) << 3);
                    int jc = n * 8 + 2 * tig + (q & 1);
                    int r = dj + jc - ir + NWIN;
                    if (r >= 0 && r < NR) {
                        c[n][q] += Rk[ir * 10 + r];
                        bnd[ir * 10 + r] = c[n][q];
                    }
                }
            }
        }

        // ---- online softmax (rows mb / mb+8) ----
        float mx0 = -1e30f, mx1 = -1e30f;
#pragma unroll
        for (int n = 0; n < 4; n++) {
            mx0 = fmaxf(mx0, fmaxf(c[n][0], c[n][1]));
            mx1 = fmaxf(mx1, fmaxf(c[n][2], c[n][3]));
        }
        mx0 = fmaxf(mx0, __shfl_xor_sync(0xffffffffu, mx0, 1));
        mx0 = fmaxf(mx0, __shfl_xor_sync(0xffffffffu, mx0, 2));
        mx1 = fmaxf(mx1, __shfl_xor_sync(0xffffffffu, mx1, 1));
        mx1 = fmaxf(mx1, __shfl_xor_sync(0xffffffffu, mx1, 2));
        float nm0 = fmaxf(ms0, mx0), nm1 = fmaxf(ms1, mx1);
        float al0 = __expf(ms0 - nm0), al1 = __expf(ms1 - nm1);

        float s0 = 0.f, s1 = 0.f;
#pragma unroll
        for (int n = 0; n < 4; n++) {
            c[n][0] = __expf(c[n][0] - nm0); s0 += c[n][0];
            c[n][1] = __expf(c[n][1] - nm0); s0 += c[n][1];
            c[n][2] = __expf(c[n][2] - nm1); s1 += c[n][2];
            c[n][3] = __expf(c[n][3] - nm1); s1 += c[n][3];
        }
        s0 += __shfl_xor_sync(0xffffffffu, s0, 1);
        s0 += __shfl_xor_sync(0xffffffffu, s0, 2);
        s1 += __shfl_xor_sync(0xffffffffu, s1, 1);
        s1 += __shfl_xor_sync(0xffffffffu, s1, 2);
        ls0 = ls0 * al0 + s0;
        ls1 = ls1 * al1 + s1;
        ms0 = nm0; ms1 = nm1;
        if (tig == 0) { sc[mb] = al0; sc[mb + 8] = al1; }

        // ---- write P (tf32) [i][j] stride 36 ----
#pragma unroll
        for (int n = 0; n < 4; n++) {
            int jc = n * 8 + 2 * tig;
            uint2 p0 = make_uint2(f2tf(c[n][0]), f2tf(c[n][1]));
            uint2 p1 = make_uint2(f2tf(c[n][2]), f2tf(c[n][3]));
            *(uint2*)&Ps[mb * PSTR + jc] = p0;
            *(uint2*)&Ps[(mb + 8) * PSTR + jc] = p1;
        }
        __syncthreads();

        // ---- rescale O, then O += V @ P ----
#pragma unroll
        for (int n = 0; n < 4; n++) {
            int col = wn2 * 32 + n * 8 + 2 * tig;
            float s0v = sc[col], s1v = sc[col + 1];
#pragma unroll
            for (int f = 0; f < 2; f++) {
                o[f][n][0] *= s0v; o[f][n][1] *= s1v;
                o[f][n][2] *= s0v; o[f][n][3] *= s1v;
            }
        }
#pragma unroll
        for (int ks = 0; ks < 4; ks++) {
            int k0 = ks * 8;
            uint32_t a[2][4];
#pragma unroll
            for (int f = 0; f < 2; f++) {
                int rb = wm2 * 32 + f * 16 + gid;
                a[f][0] = Vc[rb * VSTR + k0 + tig];
                a[f][1] = Vc[(rb + 8) * VSTR + k0 + tig];
                a[f][2] = Vc[rb * VSTR + k0 + tig + 4];
                a[f][3] = Vc[(rb + 8) * VSTR + k0 + tig + 4];
            }
#pragma unroll
            for (int n = 0; n < 4; n++) {
                uint32_t bb[2];
                int coln = wn2 * 32 + n * 8 + gid;
                bb[0] = Ps[coln * PSTR + k0 + tig];
                bb[1] = Ps[coln * PSTR + k0 + tig + 4];
#pragma unroll
                for (int f = 0; f < 2; f++) mma_tf32(o[f][n], a[f], bb);
            }
        }
        if (jt + 1 < NJT) CP_WAIT0();
        __syncthreads();
    }

    // ---- final stats ----
    if (tig == 0) {
        mf[mb] = ms0; mf[mb + 8] = ms1;
        li[mb] = 1.f / ls0; li[mb + 8] = 1.f / ls1;
    }
    __syncthreads();

    for (int idx = tid; idx < 128 * NR; idx += 256) {
        int i = idx / NR, r = idx - i * NR;
        bnd[i * 10 + r] = __expf(bnd[i * 10 + r] - mf[i]) * li[i];
    }
    __syncthreads();

    // ---- epilogue: out[d][i] = O*inv_l + sum_r pb[i][r]*emb_v[r][d] (tf32) ----
    float* om = g_mid + ((size_t)b * CCH + h * HD) * TSEQ;
#pragma unroll
    for (int f = 0; f < 2; f++) {
        int rd = wm2 * 32 + f * 16 + gid;
#pragma unroll
        for (int n = 0; n < 4; n++) {
            int cil = wn2 * 32 + n * 8 + 2 * tig;
            float inv0 = li[cil], inv1 = li[cil + 1];
            float v0 = o[f][n][0] * inv0, v1 = o[f][n][1] * inv1;
            float v2 = o[f][n][2] * inv0, v3 = o[f][n][3] * inv1;
#pragma unroll
            for (int r = 0; r < NR; r++) {
                float p0 = bnd[cil * 10 + r], p1 = bnd[(cil + 1) * 10 + r];
                float e0 = ev[r * HD + rd], e1 = ev[r * HD + rd + 8];
                v0 += p0 * e0; v1 += p1 * e0;
                v2 += p0 * e1; v3 += p1 * e1;
            }
            *(float2*)(om + (size_t)rd * TSEQ + i0 + cil) =
                make_float2(__uint_as_float(f2tf(v0)), __uint_as_float(f2tf(v1)));
            *(float2*)(om + (size_t)(rd + 8) * TSEQ + i0 + cil) =
                make_float2(__uint_as_float(f2tf(v2)), __uint_as_float(f2tf(v3)));
        }
    }
}

// ---------------------------------------------------------------------------
extern "C" void kernel_launch(void* const* d_in, const int* in_sizes, int n_in,
                              void* d_out, int out_size)
{
    const float* x     = (const float*)d_in[0];
    const float* w_q   = (const float*)d_in[1];
    const float* b_q   = (const float*)d_in[2];
    const float* w_k   = (const float*)d_in[3];
    const float* b_k   = (const float*)d_in[4];
    const float* w_v   = (const float*)d_in[5];
    const float* b_v   = (const float*)d_in[6];
    const float* w_o   = (const float*)d_in[7];
    const float* b_o   = (const float*)d_in[8];
    const float* emb_k = (const float*)d_in[9];
    const float* emb_v = (const float*)d_in[10];
    float* out = (float*)d_out;

    cudaFuncSetAttribute(attn_kernel, cudaFuncAttributeMaxDynamicSharedMemorySize, ATTN_SMEM);

    prep_kernel<<<592, 256>>>(x, w_q, w_k, w_v, w_o);

    dim3 gq(CCH / 128, TSEQ / 128, BB * 3);
    qkv_kernel<<<gq, 256>>>(b_q, b_k, b_v);

    dim3 ga(TSEQ / 128, NBH);
    attn_kernel<<<ga, 256, ATTN_SMEM>>>(emb_k, emb_v);

    dim3 go(CCH / 128, TSEQ / 64, BB);
    oproj_kernel<<<go, 256>>>(b_o, out);
}

// round 14
// speedup vs baseline: 3.0583x; 1.0191x over previous
#include <cuda_runtime.h>
#include <math.h>
#include <stdint.h>

#define BB   4
#define TSEQ 1024
#define CCH  768
#define NH   12
#define HD   64
#define NWIN 4
#define NR   9
#define NBH  (BB*NH)   // 48

// Scratch (static __device__ arrays per allocation rules)
static __device__ float g_q[BB*CCH*TSEQ];     // tf32-rounded, q pre-scaled by 1/8
static __device__ float g_k[BB*CCH*TSEQ];     // tf32-rounded
static __device__ float g_v[BB*CCH*TSEQ];     // tf32-rounded
static __device__ float g_mid[BB*CCH*TSEQ];   // attention output (tf32-rounded)
static __device__ float g_x[BB*CCH*TSEQ];     // tf32-rounded input x
static __device__ float g_wq[CCH*CCH];        // tf32-rounded weights, k-permuted
static __device__ float g_wk[CCH*CCH];
static __device__ float g_wv[CCH*CCH];
static __device__ float g_wo[CCH*CCH];

// ---------------------------------------------------------------------------
// tf32 / async helpers
// ---------------------------------------------------------------------------
__device__ __forceinline__ uint32_t f2tf(float x) {
    uint32_t u;
    asm("cvt.rna.tf32.f32 %0, %1;" : "=r"(u) : "f"(x));
    return u;
}
__device__ __forceinline__ float4 rnd4(float4 v) {
    float4 r;
    r.x = __uint_as_float(f2tf(v.x)); r.y = __uint_as_float(f2tf(v.y));
    r.z = __uint_as_float(f2tf(v.z)); r.w = __uint_as_float(f2tf(v.w));
    return r;
}
__device__ __forceinline__ void mma_tf32(float c[4], const uint32_t a[4], const uint32_t b[2]) {
    asm volatile(
        "mma.sync.aligned.m16n8k8.row.col.f32.tf32.tf32.f32 "
        "{%0,%1,%2,%3}, {%4,%5,%6,%7}, {%8,%9}, {%0,%1,%2,%3};\n"
        : "+f"(c[0]), "+f"(c[1]), "+f"(c[2]), "+f"(c[3])
        : "r"(a[0]), "r"(a[1]), "r"(a[2]), "r"(a[3]), "r"(b[0]), "r"(b[1]));
}
__device__ __forceinline__ void cp16(uint32_t dst, const void* src) {
    asm volatile("cp.async.cg.shared.global [%0], [%1], 16;\n" :: "r"(dst), "l"(src));
}
#define CP_COMMIT() asm volatile("cp.async.commit_group;\n")
#define CP_WAIT0()  asm volatile("cp.async.wait_group 0;\n")
#define CP_WAIT1()  asm volatile("cp.async.wait_group 1;\n")

// ---------------------------------------------------------------------------
// Prep: round x (float4 path) and weights (scalar, k-permuted within 8-groups:
// position (c&~7) | ((c&3)*2) | ((c&4)>>2) holds original column c).
// ---------------------------------------------------------------------------
__global__ __launch_bounds__(256)
void prep_kernel(const float* __restrict__ x,
                 const float* __restrict__ wq, const float* __restrict__ wk,
                 const float* __restrict__ wv, const float* __restrict__ wo)
{
    int stride = gridDim.x * blockDim.x;
    int idx = blockIdx.x * blockDim.x + threadIdx.x;
    for (int i = idx; i < BB * CCH * TSEQ / 4; i += stride)
        ((float4*)g_x)[i] = rnd4(((const float4*)x)[i]);
    for (int i = idx; i < CCH * CCH; i += stride) {
        int c = i & (CCH - 1);   // CCH=768 not pow2! use % instead
        c = i % CCH;
        int o = i / CCH;
        int p = (c & ~7) | ((c & 3) * 2) | ((c & 4) >> 2);
        int dst = o * CCH + p;
        g_wq[dst] = __uint_as_float(f2tf(wq[i]));
        g_wk[dst] = __uint_as_float(f2tf(wk[i]));
        g_wv[dst] = __uint_as_float(f2tf(wv[i]));
        g_wo[dst] = __uint_as_float(f2tf(wo[i]));
    }
}

// ---------------------------------------------------------------------------
// Projection GEMM: Out[o,t] = (sum_c W[o,c]*X[c,t] + bias[o]) * scale
// W is k-permuted -> A fragments load as LDS.64 pairs.
// 128xBN block, BK=16, 3-stage cp.async pipeline, 8 warps (4m x 2n),
// warp tile 32x(BN/2), 2 CTAs/SM. BN=64 additionally prefetches all
// fragments for both kk-halves before the MMA burst.
// ---------------------------------------------------------------------------
template<int BN>
__device__ __forceinline__ void proj_body(
    const float* __restrict__ X, const float* __restrict__ W,
    const float* __restrict__ bias, float* __restrict__ Out, float scale,
    bool round_out)
{
    constexpr int BSTR = (BN == 128) ? 136 : 72;
    constexpr int NSUB = BN / 16;          // n-subtiles per warp
    constexpr int NBCP = BN / 64;          // b cp16s per thread (2 or 1)
    constexpr int B4   = BN / 4;           // float4s per B row

    __shared__ float As[3][128 * 20];      // [m][k-perm], stride 20
    __shared__ float Bs[3][16 * BSTR];     // [k][n]

    int tid = threadIdx.x;
    int lane = tid & 31, wid = tid >> 5;
    int wm = wid >> 1, wn = wid & 1;
    int gid = lane >> 2, tig = lane & 3;
    int o0 = blockIdx.x * 128, t0 = blockIdx.y * BN;

    const uint32_t aS = (uint32_t)__cvta_generic_to_shared(&As[0][0]);
    const uint32_t bS = (uint32_t)__cvta_generic_to_shared(&Bs[0][0]);
    const uint32_t aBuf = 128 * 20 * 4, bBuf = 16 * BSTR * 4;

    const float* aptr[2]; uint32_t adst[2];
#pragma unroll
    for (int p = 0; p < 2; p++) {
        int fl = tid + p * 256;
        int am = fl >> 2, ac4 = (fl & 3) * 4;
        aptr[p] = W + (size_t)(o0 + am) * CCH + ac4;
        adst[p] = aS + (uint32_t)(am * 20 + ac4) * 4;
    }
    const float* bptr[2]; uint32_t bdst[2];
#pragma unroll
    for (int p = 0; p < NBCP; p++) {
        int fl = tid + p * 256;
        int bk = fl / B4, bt4 = (fl % B4) * 4;
        bptr[p] = X + (size_t)bk * TSEQ + t0 + bt4;
        bdst[p] = bS + (uint32_t)(bk * BSTR + bt4) * 4;
    }

    float c[2][NSUB][4];
#pragma unroll
    for (int f = 0; f < 2; f++)
#pragma unroll
        for (int n = 0; n < NSUB; n++)
#pragma unroll
            for (int q = 0; q < 4; q++) c[f][n][q] = 0.f;

    auto issue = [&](int buf, int s) {
#pragma unroll
        for (int p = 0; p < 2; p++)
            cp16(adst[p] + buf * aBuf, aptr[p] + s * 16);
#pragma unroll
        for (int p = 0; p < NBCP; p++)
            cp16(bdst[p] + buf * bBuf, bptr[p] + (size_t)s * 16 * TSEQ);
    };

    issue(0, 0); CP_COMMIT();
    issue(1, 1); CP_COMMIT();

    const int NS = CCH / 16;   // 48
    int cur = 0;
    for (int s = 0; s < NS; s++) {
        if (s == NS - 1) { CP_WAIT0(); } else { CP_WAIT1(); }
        __syncthreads();
        if (s + 2 < NS) {
            int nb = cur + 2; if (nb >= 3) nb -= 3;
            issue(nb, s + 2); CP_COMMIT();
        }
        const float* Ac = As[cur];
        const float* Bc = Bs[cur];

        if constexpr (BN == 64) {
            // full prefetch of both kk-halves, then MMA burst
            uint32_t a[2][2][4], b[2][NSUB][2];
#pragma unroll
            for (int hf = 0; hf < 2; hf++) {
                int kk = hf * 8;
#pragma unroll
                for (int f = 0; f < 2; f++) {
                    int rb = wm * 32 + f * 16 + gid;
                    uint2 lo = *(const uint2*)(Ac + rb * 20 + kk + 2 * tig);
                    uint2 hi = *(const uint2*)(Ac + (rb + 8) * 20 + kk + 2 * tig);
                    a[hf][f][0] = lo.x; a[hf][f][2] = lo.y;
                    a[hf][f][1] = hi.x; a[hf][f][3] = hi.y;
                }
#pragma unroll
                for (int n = 0; n < NSUB; n++) {
                    int col = wn * (BN / 2) + n * 8 + gid;
                    b[hf][n][0] = __float_as_uint(Bc[(kk + tig) * BSTR + col]);
                    b[hf][n][1] = __float_as_uint(Bc[(kk + tig + 4) * BSTR + col]);
                }
            }
#pragma unroll
            for (int hf = 0; hf < 2; hf++)
#pragma unroll
                for (int f = 0; f < 2; f++)
#pragma unroll
                    for (int n = 0; n < NSUB; n++) mma_tf32(c[f][n], a[hf][f], b[hf][n]);
        } else {
#pragma unroll
            for (int kk = 0; kk < 16; kk += 8) {
                uint32_t a[2][4], b[NSUB][2];
#pragma unroll
                for (int f = 0; f < 2; f++) {
                    int rb = wm * 32 + f * 16 + gid;
                    uint2 lo = *(const uint2*)(Ac + rb * 20 + kk + 2 * tig);
                    uint2 hi = *(const uint2*)(Ac + (rb + 8) * 20 + kk + 2 * tig);
                    a[f][0] = lo.x; a[f][2] = lo.y;
                    a[f][1] = hi.x; a[f][3] = hi.y;
                }
#pragma unroll
                for (int n = 0; n < NSUB; n++) {
                    int col = wn * (BN / 2) + n * 8 + gid;
                    b[n][0] = __float_as_uint(Bc[(kk + tig) * BSTR + col]);
                    b[n][1] = __float_as_uint(Bc[(kk + tig + 4) * BSTR + col]);
                }
#pragma unroll
                for (int f = 0; f < 2; f++)
#pragma unroll
                    for (int n = 0; n < NSUB; n++) mma_tf32(c[f][n], a[f], b[n]);
            }
        }
        if (++cur >= 3) cur = 0;
    }

#pragma unroll
    for (int f = 0; f < 2; f++) {
        int ro = o0 + wm * 32 + f * 16 + gid;
        float bv0 = bias[ro], bv1 = bias[ro + 8];
#pragma unroll
        for (int n = 0; n < NSUB; n++) {
            int col = t0 + wn * (BN / 2) + n * 8 + 2 * tig;
            float u0 = (c[f][n][0] + bv0) * scale, u1 = (c[f][n][1] + bv0) * scale;
            float u2 = (c[f][n][2] + bv1) * scale, u3 = (c[f][n][3] + bv1) * scale;
            if (round_out) {
                u0 = __uint_as_float(f2tf(u0)); u1 = __uint_as_float(f2tf(u1));
                u2 = __uint_as_float(f2tf(u2)); u3 = __uint_as_float(f2tf(u3));
            }
            *(float2*)(Out + (size_t)ro * TSEQ + col) = make_float2(u0, u1);
            *(float2*)(Out + (size_t)(ro + 8) * TSEQ + col) = make_float2(u2, u3);
        }
    }
}

__global__ __launch_bounds__(256, 2)
void qkv_kernel(const float* __restrict__ Bq, const float* __restrict__ Bk,
                const float* __restrict__ Bv)
{
    int zb = blockIdx.z;
    int b = zb / 3, which = zb % 3;
    const float* Wm = (which == 0) ? g_wq : ((which == 1) ? g_wk : g_wv);
    const float* Bi = (which == 0) ? Bq : ((which == 1) ? Bk : Bv);
    float* Out = (which == 0) ? g_q : ((which == 1) ? g_k : g_v);
    float scale = (which == 0) ? 0.125f : 1.0f;
    proj_body<128>(g_x + (size_t)b * CCH * TSEQ, Wm, Bi, Out + (size_t)b * CCH * TSEQ, scale, true);
}

__global__ __launch_bounds__(256, 2)
void oproj_kernel(const float* __restrict__ Bi, float* __restrict__ Out)
{
    int b = blockIdx.z;
    proj_body<64>(g_mid + (size_t)b * CCH * TSEQ, g_wo, Bi, Out + (size_t)b * CCH * TSEQ, 1.0f, false);
}

// ---------------------------------------------------------------------------
// Fused flash attention. Block = (bh, 128-row i-tile), 256 threads (8 warps),
// 2 CTAs/SM. j in 32 chunks of 32, K/V double-buffered via cp.async.
// Q fragments hoisted out of the jt loop (invariant; 32 regs).
// ---------------------------------------------------------------------------
#define BJ 32
#define NJT (TSEQ / BJ)       // 32
#define KSTR 40
#define VSTR 36
#define PSTR 36
#define KW  (64 * KSTR)
#define VW  (64 * VSTR)
#define ATTN_SMEM 108544

__global__ __launch_bounds__(256, 2)
void attn_kernel(const float* __restrict__ emb_k, const float* __restrict__ emb_v)
{
    extern __shared__ char smc[];
    uint32_t* Qs = (uint32_t*)smc;          // [k=d 64][m=i 128] stride 136
    uint32_t* Ks = Qs + 64 * 136;           // 2 x [d 64][j 32] stride 40
    uint32_t* Vs = Ks + 2 * KW;             // 2 x [d 64][j 32] stride 36
    uint32_t* Ps = Vs + 2 * VW;             // [i 128][j 32] stride 36
    float* Rk  = (float*)(Ps + 128 * PSTR); // [128][10]
    float* bnd = Rk + 128 * 10;             // [128][10]
    float* ek  = bnd + 128 * 10;            // [9][64]
    float* ev  = ek + NR * HD;              // [9][64]
    float* sc  = ev + NR * HD;              // [128]
    float* mf  = sc + 128;                  // [128]
    float* li  = mf + 128;                  // [128]

    int bh = blockIdx.y;
    int i0 = blockIdx.x * 128;
    int b = bh / NH, h = bh % NH;
    const float* qb = g_q + ((size_t)b * CCH + h * HD) * TSEQ;
    const float* kb = g_k + ((size_t)b * CCH + h * HD) * TSEQ;
    const float* vb = g_v + ((size_t)b * CCH + h * HD) * TSEQ;

    int tid = threadIdx.x;
    int lane = tid & 31, wid = tid >> 5;
    int gid = lane >> 2, tig = lane & 3;
    int wm2 = wid >> 2, wn2 = wid & 3;

    const uint32_t qS = (uint32_t)__cvta_generic_to_shared(Qs);
    const uint32_t kS = (uint32_t)__cvta_generic_to_shared(Ks);
    const uint32_t vS = (uint32_t)__cvta_generic_to_shared(Vs);

    int cd = tid >> 3, cc4 = (tid & 7) * 4;
    int cd1 = (tid + 256) >> 3;

    // ---- prologue: async Q + K0 + V0 ----
#pragma unroll
    for (int p = 0; p < 8; p++) {
        int fl = tid + p * 256;
        int d = fl >> 5, c4 = (fl & 31) * 4;
        cp16(qS + (uint32_t)(d * 136 + c4) * 4, qb + (size_t)d * TSEQ + i0 + c4);
    }
    cp16(kS + (uint32_t)(cd * KSTR + cc4) * 4, kb + (size_t)cd * TSEQ + cc4);
    cp16(kS + (uint32_t)(cd1 * KSTR + cc4) * 4, kb + (size_t)cd1 * TSEQ + cc4);
    cp16(vS + (uint32_t)(cd * VSTR + cc4) * 4, vb + (size_t)cd * TSEQ + cc4);
    cp16(vS + (uint32_t)(cd1 * VSTR + cc4) * 4, vb + (size_t)cd1 * TSEQ + cc4);
    CP_COMMIT();

    for (int idx = tid; idx < NR * HD; idx += 256) { ek[idx] = emb_k[idx]; ev[idx] = emb_v[idx]; }
    for (int idx = tid; idx < 128 * 10; idx += 256) bnd[idx] = -1e30f;

    CP_WAIT0();
    __syncthreads();

    // Rk[i][r] = sum_d q[d][i] * emb_k[r][d]
    for (int idx = tid; idx < 128 * NR; idx += 256) {
        int i = idx / NR, r = idx - i * NR;
        float acc = 0.f;
#pragma unroll
        for (int d = 0; d < HD; d++)
            acc += __uint_as_float(Qs[d * 136 + i]) * ek[r * HD + d];
        Rk[i * 10 + r] = acc;
    }
    __syncthreads();

    int mb = wid * 16 + gid;

    // ---- hoist Q fragments (invariant across jt) ----
    uint32_t qf[8][4];
#pragma unroll
    for (int ks = 0; ks < 8; ks++) {
        int k0 = ks * 8;
        qf[ks][0] = Qs[(k0 + tig) * 136 + mb];
        qf[ks][1] = Qs[(k0 + tig) * 136 + mb + 8];
        qf[ks][2] = Qs[(k0 + tig + 4) * 136 + mb];
        qf[ks][3] = Qs[(k0 + tig + 4) * 136 + mb + 8];
    }

    float ms0 = -1e30f, ms1 = -1e30f, ls0 = 0.f, ls1 = 0.f;
    float o[2][4][4];
#pragma unroll
    for (int f = 0; f < 2; f++)
#pragma unroll
        for (int n = 0; n < 4; n++)
#pragma unroll
            for (int q = 0; q < 4; q++) o[f][n][q] = 0.f;

    for (int jt = 0; jt < NJT; jt++) {
        int cur = jt & 1;
        if (jt + 1 < NJT) {
            int j1 = (jt + 1) * BJ;
            int nb = (jt + 1) & 1;
            cp16(kS + (uint32_t)(nb * KW + cd * KSTR + cc4) * 4, kb + (size_t)cd * TSEQ + j1 + cc4);
            cp16(kS + (uint32_t)(nb * KW + cd1 * KSTR + cc4) * 4, kb + (size_t)cd1 * TSEQ + j1 + cc4);
            cp16(vS + (uint32_t)(nb * VW + cd * VSTR + cc4) * 4, vb + (size_t)cd * TSEQ + j1 + cc4);
            cp16(vS + (uint32_t)(nb * VW + cd1 * VSTR + cc4) * 4, vb + (size_t)cd1 * TSEQ + j1 + cc4);
            CP_COMMIT();
        }
        const uint32_t* Kc = Ks + cur * KW;
        const uint32_t* Vc = Vs + cur * VW;

        // ---- S = Q.K ----
        float c[4][4];
#pragma unroll
        for (int n = 0; n < 4; n++)
#pragma unroll
            for (int q = 0; q < 4; q++) c[n][q] = 0.f;

#pragma unroll
        for (int ks = 0; ks < 8; ks++) {
            int k0 = ks * 8;
#pragma unroll
            for (int n = 0; n < 4; n++) {
                uint32_t bb[2];
                bb[0] = Kc[(k0 + tig) * KSTR + n * 8 + gid];
                bb[1] = Kc[(k0 + tig + 4) * KSTR + n * 8 + gid];
                mma_tf32(c[n], qf[ks], bb);
            }
        }

        // ---- rel-k add + raw band stash ----
        int dj = jt * BJ - i0;
        if (dj >= -35 && dj <= 131) {
#pragma unroll
            for (int n = 0; n < 4; n++) {
#pragma unroll
                for (int q = 0; q < 4; q++) {
                    int ir = mb + ((q >> 1) << 3);
                    int jc = n * 8 + 2 * tig + (q & 1);
                    int r = dj + jc - ir + NWIN;
                    if (r >= 0 && r < NR) {
                        c[n][q] += Rk[ir * 10 + r];
                        bnd[ir * 10 + r] = c[n][q];
                    }
                }
            }
        }

        // ---- online softmax ----
        float mx0 = -1e30f, mx1 = -1e30f;
#pragma unroll
        for (int n = 0; n < 4; n++) {
            mx0 = fmaxf(mx0, fmaxf(c[n][0], c[n][1]));
            mx1 = fmaxf(mx1, fmaxf(c[n][2], c[n][3]));
        }
        mx0 = fmaxf(mx0, __shfl_xor_sync(0xffffffffu, mx0, 1));
        mx0 = fmaxf(mx0, __shfl_xor_sync(0xffffffffu, mx0, 2));
        mx1 = fmaxf(mx1, __shfl_xor_sync(0xffffffffu, mx1, 1));
        mx1 = fmaxf(mx1, __shfl_xor_sync(0xffffffffu, mx1, 2));
        float nm0 = fmaxf(ms0, mx0), nm1 = fmaxf(ms1, mx1);
        float al0 = __expf(ms0 - nm0), al1 = __expf(ms1 - nm1);

        float s0 = 0.f, s1 = 0.f;
#pragma unroll
        for (int n = 0; n < 4; n++) {
            c[n][0] = __expf(c[n][0] - nm0); s0 += c[n][0];
            c[n][1] = __expf(c[n][1] - nm0); s0 += c[n][1];
            c[n][2] = __expf(c[n][2] - nm1); s1 += c[n][2];
            c[n][3] = __expf(c[n][3] - nm1); s1 += c[n][3];
        }
        s0 += __shfl_xor_sync(0xffffffffu, s0, 1);
        s0 += __shfl_xor_sync(0xffffffffu, s0, 2);
        s1 += __shfl_xor_sync(0xffffffffu, s1, 1);
        s1 += __shfl_xor_sync(0xffffffffu, s1, 2);
        ls0 = ls0 * al0 + s0;
        ls1 = ls1 * al1 + s1;
        ms0 = nm0; ms1 = nm1;
        if (tig == 0) { sc[mb] = al0; sc[mb + 8] = al1; }

        // ---- write P (tf32) [i][j] stride 36 ----
#pragma unroll
        for (int n = 0; n < 4; n++) {
            int jc = n * 8 + 2 * tig;
            uint2 p0 = make_uint2(f2tf(c[n][0]), f2tf(c[n][1]));
            uint2 p1 = make_uint2(f2tf(c[n][2]), f2tf(c[n][3]));
            *(uint2*)&Ps[mb * PSTR + jc] = p0;
            *(uint2*)&Ps[(mb + 8) * PSTR + jc] = p1;
        }
        __syncthreads();

        // ---- rescale O, then O += V @ P ----
#pragma unroll
        for (int n = 0; n < 4; n++) {
            int col = wn2 * 32 + n * 8 + 2 * tig;
            float s0v = sc[col], s1v = sc[col + 1];
#pragma unroll
            for (int f = 0; f < 2; f++) {
                o[f][n][0] *= s0v; o[f][n][1] *= s1v;
                o[f][n][2] *= s0v; o[f][n][3] *= s1v;
            }
        }
#pragma unroll
        for (int ks = 0; ks < 4; ks++) {
            int k0 = ks * 8;
            uint32_t a[2][4];
#pragma unroll
            for (int f = 0; f < 2; f++) {
                int rb = wm2 * 32 + f * 16 + gid;
                a[f][0] = Vc[rb * VSTR + k0 + tig];
                a[f][1] = Vc[(rb + 8) * VSTR + k0 + tig];
                a[f][2] = Vc[rb * VSTR + k0 + tig + 4];
                a[f][3] = Vc[(rb + 8) * VSTR + k0 + tig + 4];
            }
#pragma unroll
            for (int n = 0; n < 4; n++) {
                uint32_t bb[2];
                int coln = wn2 * 32 + n * 8 + gid;
                bb[0] = Ps[coln * PSTR + k0 + tig];
                bb[1] = Ps[coln * PSTR + k0 + tig + 4];
#pragma unroll
                for (int f = 0; f < 2; f++) mma_tf32(o[f][n], a[f], bb);
            }
        }
        if (jt + 1 < NJT) CP_WAIT0();
        __syncthreads();
    }

    // ---- final stats ----
    if (tig == 0) {
        mf[mb] = ms0; mf[mb + 8] = ms1;
        li[mb] = 1.f / ls0; li[mb + 8] = 1.f / ls1;
    }
    __syncthreads();

    for (int idx = tid; idx < 128 * NR; idx += 256) {
        int i = idx / NR, r = idx - i * NR;
        bnd[i * 10 + r] = __expf(bnd[i * 10 + r] - mf[i]) * li[i];
    }
    __syncthreads();

    // ---- epilogue ----
    float* om = g_mid + ((size_t)b * CCH + h * HD) * TSEQ;
#pragma unroll
    for (int f = 0; f < 2; f++) {
        int rd = wm2 * 32 + f * 16 + gid;
#pragma unroll
        for (int n = 0; n < 4; n++) {
            int cil = wn2 * 32 + n * 8 + 2 * tig;
            float inv0 = li[cil], inv1 = li[cil + 1];
            float v0 = o[f][n][0] * inv0, v1 = o[f][n][1] * inv1;
            float v2 = o[f][n][2] * inv0, v3 = o[f][n][3] * inv1;
#pragma unroll
            for (int r = 0; r < NR; r++) {
                float p0 = bnd[cil * 10 + r], p1 = bnd[(cil + 1) * 10 + r];
                float e0 = ev[r * HD + rd], e1 = ev[r * HD + rd + 8];
                v0 += p0 * e0; v1 += p1 * e0;
                v2 += p0 * e1; v3 += p1 * e1;
            }
            *(float2*)(om + (size_t)rd * TSEQ + i0 + cil) =
                make_float2(__uint_as_float(f2tf(v0)), __uint_as_float(f2tf(v1)));
            *(float2*)(om + (size_t)(rd + 8) * TSEQ + i0 + cil) =
                make_float2(__uint_as_float(f2tf(v2)), __uint_as_float(f2tf(v3)));
        }
    }
}

// ---------------------------------------------------------------------------
extern "C" void kernel_launch(void* const* d_in, const int* in_sizes, int n_in,
                              void* d_out, int out_size)
{
    const float* x     = (const float*)d_in[0];
    const float* w_q   = (const float*)d_in[1];
    const float* b_q   = (const float*)d_in[2];
    const float* w_k   = (const float*)d_in[3];
    const float* b_k   = (const float*)d_in[4];
    const float* w_v   = (const float*)d_in[5];
    const float* b_v   = (const float*)d_in[6];
    const float* w_o   = (const float*)d_in[7];
    const float* b_o   = (const float*)d_in[8];
    const float* emb_k = (const float*)d_in[9];
    const float* emb_v = (const float*)d_in[10];
    float* out = (float*)d_out;

    cudaFuncSetAttribute(attn_kernel, cudaFuncAttributeMaxDynamicSharedMemorySize, ATTN_SMEM);

    prep_kernel<<<592, 256>>>(x, w_q, w_k, w_v, w_o);

    dim3 gq(CCH / 128, TSEQ / 128, BB * 3);
    qkv_kernel<<<gq, 256>>>(b_q, b_k, b_v);

    dim3 ga(TSEQ / 128, NBH);
    attn_kernel<<<ga, 256, ATTN_SMEM>>>(emb_k, emb_v);

    dim3 go(CCH / 128, TSEQ / 64, BB);
    oproj_kernel<<<go, 256>>>(b_o, out);
}

// round 17
// speedup vs baseline: 4.1535x; 1.3581x over previous
#include <cuda_runtime.h>
#include <cuda_fp16.h>
#include <math.h>
#include <stdint.h>

#define BB   4
#define TSEQ 1024
#define CCH  768
#define NH   12
#define HD   64
#define NWIN 4
#define NR   9
#define NBH  (BB*NH)   // 48

// Scratch (static __device__ arrays per allocation rules) — all fp16 operands
static __device__ __half g_qh[BB*TSEQ*CCH];    // q^T: [b][t][C], pre-scaled 1/8
static __device__ __half g_kh[BB*TSEQ*CCH];    // k^T: [b][t][C]
static __device__ __half g_vh[BB*CCH*TSEQ];    // v:   [b][C][t]
static __device__ __half g_midh[BB*TSEQ*CCH];  // attn out: [b][t][C]
static __device__ __half g_xth[BB*TSEQ*CCH];   // x^T:  [b][t][c]
static __device__ __half g_wqh[CCH*CCH];       // [o][c]
static __device__ __half g_wkh[CCH*CCH];
static __device__ __half g_wvh[CCH*CCH];
static __device__ __half g_woh[CCH*CCH];

// ---------------------------------------------------------------------------
// helpers
// ---------------------------------------------------------------------------
__device__ __forceinline__ void mma_f16(float c[4], const uint32_t a[4], const uint32_t b[2]) {
    asm volatile(
        "mma.sync.aligned.m16n8k16.row.col.f32.f16.f16.f32 "
        "{%0,%1,%2,%3}, {%4,%5,%6,%7}, {%8,%9}, {%0,%1,%2,%3};\n"
        : "+f"(c[0]), "+f"(c[1]), "+f"(c[2]), "+f"(c[3])
        : "r"(a[0]), "r"(a[1]), "r"(a[2]), "r"(a[3]), "r"(b[0]), "r"(b[1]));
}
__device__ __forceinline__ void cp16(uint32_t dst, const void* src) {
    asm volatile("cp.async.cg.shared.global [%0], [%1], 16;\n" :: "r"(dst), "l"(src));
}
#define CP_COMMIT() asm volatile("cp.async.commit_group;\n")
#define CP_WAIT0()  asm volatile("cp.async.wait_group 0;\n")

__device__ __forceinline__ uint32_t smem_u32(const void* p) {
    uint32_t a;
    asm("{ .reg .u64 t; cvta.to.shared.u64 t, %1; cvt.u32.u64 %0, t; }" : "=r"(a) : "l"(p));
    return a;
}

// ---------------------------------------------------------------------------
// Prep: round weights to fp16; transpose+round x to [b][t][c] fp16.
// ---------------------------------------------------------------------------
__global__ __launch_bounds__(256)
void prep_w_kernel(const float* __restrict__ wq, const float* __restrict__ wk,
                   const float* __restrict__ wv, const float* __restrict__ wo)
{
    int stride = gridDim.x * blockDim.x;
    int idx = blockIdx.x * blockDim.x + threadIdx.x;
    for (int i = idx; i < CCH * CCH; i += stride) {
        g_wqh[i] = __float2half_rn(wq[i]);
        g_wkh[i] = __float2half_rn(wk[i]);
        g_wvh[i] = __float2half_rn(wv[i]);
        g_woh[i] = __float2half_rn(wo[i]);
    }
}

__global__ __launch_bounds__(256)
void prep_xt_kernel(const float* __restrict__ x)
{
    __shared__ float tile[32][33];
    int t0 = blockIdx.x * 32, c0 = blockIdx.y * 32, b = blockIdx.z;
    int tx = threadIdx.x & 31, ty = threadIdx.x >> 5;
    const float* xb = x + (size_t)b * CCH * TSEQ;
#pragma unroll
    for (int i = 0; i < 4; i++) {
        int c = c0 + ty + i * 8;
        tile[ty + i * 8][tx] = xb[(size_t)c * TSEQ + t0 + tx];
    }
    __syncthreads();
    __half* ob = g_xth + (size_t)b * TSEQ * CCH;
#pragma unroll
    for (int i = 0; i < 4; i++) {
        int t = t0 + ty + i * 8;
        ob[(size_t)t * CCH + c0 + tx] = __float2half_rn(tile[tx][ty + i * 8]);
    }
}

// ---------------------------------------------------------------------------
// Universal fp16 GEMM: C[M][N] = A[M][K] * B[N][K]^T (+bias) * scale
// Both operands k-contiguous. 128x128 block, BK=32, double-buffered cp.async,
// 8 warps (4m x 2n), warp tile 32x64, m16n8k16 fp16 MMA, 2 CTAs/SM.
// ---------------------------------------------------------------------------
template<bool OUT_HALF, bool BIAS_N>
__device__ __forceinline__ void gemm_body(
    const __half* __restrict__ A, const __half* __restrict__ Bm,
    const float* __restrict__ bias, void* __restrict__ Cout,
    int ldc, float scale, int m0, int n0)
{
    __shared__ __half As[2][128 * 40];   // [m][k] halves, stride 40 (20 words)
    __shared__ __half Bs[2][128 * 40];   // [n][k] halves, stride 40

    int tid = threadIdx.x;
    int lane = tid & 31, wid = tid >> 5;
    int wm = wid >> 1, wn = wid & 1;
    int gid = lane >> 2, tig = lane & 3;

    const uint32_t aS = smem_u32(&As[0][0]);
    const uint32_t bS = smem_u32(&Bs[0][0]);
    const uint32_t bufB = 128 * 40 * 2;  // bytes per stage buffer

    // copy coords: 128 rows x 4 chunks(16B) each operand = 512 cp16; 2/thread
    int cr0 = tid >> 1, cq0 = (tid & 1) * 2;       // rows 0..127, chunk pairs
    // use: each thread copies 2 chunks for A and 2 for B
    float cdummy;
    (void)cdummy;

    float c[2][8][4];
#pragma unroll
    for (int f = 0; f < 2; f++)
#pragma unroll
        for (int n = 0; n < 8; n++)
#pragma unroll
            for (int q = 0; q < 4; q++) c[f][n][q] = 0.f;

    auto issue = [&](int buf, int s) {
        int k0 = s * 32;
#pragma unroll
        for (int p = 0; p < 2; p++) {
            int cq = cq0 + p;
            cp16(aS + buf * bufB + (uint32_t)(cr0 * 20 + cq * 4) * 4,
                 A + (size_t)(m0 + cr0) * CCH + k0 + cq * 8);
            cp16(bS + buf * bufB + (uint32_t)(cr0 * 20 + cq * 4) * 4,
                 Bm + (size_t)(n0 + cr0) * CCH + k0 + cq * 8);
        }
    };

    issue(0, 0); CP_COMMIT();

    const int NS = CCH / 32;   // 24
    for (int s = 0; s < NS; s++) {
        CP_WAIT0();
        __syncthreads();
        if (s + 1 < NS) { issue((s + 1) & 1, s + 1); CP_COMMIT(); }
        const uint32_t* Aw = (const uint32_t*)As[s & 1];
        const uint32_t* Bw = (const uint32_t*)Bs[s & 1];
#pragma unroll
        for (int kw = 0; kw < 2; kw++) {
            int k8 = kw * 8;
            uint32_t a[2][4], b[8][2];
#pragma unroll
            for (int f = 0; f < 2; f++) {
                int rb = wm * 32 + f * 16 + gid;
                a[f][0] = Aw[rb * 20 + k8 + tig];
                a[f][1] = Aw[(rb + 8) * 20 + k8 + tig];
                a[f][2] = Aw[rb * 20 + k8 + tig + 4];
                a[f][3] = Aw[(rb + 8) * 20 + k8 + tig + 4];
            }
#pragma unroll
            for (int n = 0; n < 8; n++) {
                int col = wn * 64 + n * 8 + gid;
                b[n][0] = Bw[col * 20 + k8 + tig];
                b[n][1] = Bw[col * 20 + k8 + tig + 4];
            }
#pragma unroll
            for (int f = 0; f < 2; f++)
#pragma unroll
                for (int n = 0; n < 8; n++) mma_f16(c[f][n], a[f], b[n]);
        }
    }

#pragma unroll
    for (int f = 0; f < 2; f++) {
        int rm = m0 + wm * 32 + f * 16 + gid;
        float bm0 = 0.f, bm1 = 0.f;
        if (!BIAS_N) { bm0 = bias[rm]; bm1 = bias[rm + 8]; }
#pragma unroll
        for (int n = 0; n < 8; n++) {
            int cn = n0 + wn * 64 + n * 8 + 2 * tig;
            float u0, u1, u2, u3;
            if (BIAS_N) {
                float bv0 = bias[cn], bv1 = bias[cn + 1];
                u0 = (c[f][n][0] + bv0) * scale; u1 = (c[f][n][1] + bv1) * scale;
                u2 = (c[f][n][2] + bv0) * scale; u3 = (c[f][n][3] + bv1) * scale;
            } else {
                u0 = (c[f][n][0] + bm0) * scale; u1 = (c[f][n][1] + bm0) * scale;
                u2 = (c[f][n][2] + bm1) * scale; u3 = (c[f][n][3] + bm1) * scale;
            }
            if (OUT_HALF) {
                __half* Ch = (__half*)Cout;
                *(half2*)(Ch + (size_t)rm * ldc + cn) = __floats2half2_rn(u0, u1);
                *(half2*)(Ch + (size_t)(rm + 8) * ldc + cn) = __floats2half2_rn(u2, u3);
            } else {
                float* Cf = (float*)Cout;
                *(float2*)(Cf + (size_t)rm * ldc + cn) = make_float2(u0, u1);
                *(float2*)(Cf + (size_t)(rm + 8) * ldc + cn) = make_float2(u2, u3);
            }
        }
    }
}

// qk projection: C[t][o] = Xt[t][c] * W[o][c]^T; bias on N(=o); out half
__global__ __launch_bounds__(256, 2)
void qk_kernel(const float* __restrict__ bq, const float* __restrict__ bk)
{
    int z = blockIdx.z;
    int b = z >> 1, which = z & 1;
    const __half* A = g_xth + (size_t)b * TSEQ * CCH;
    const __half* Bm = which ? g_wkh : g_wqh;
    const float* bias = which ? bk : bq;
    __half* out = (which ? g_kh : g_qh) + (size_t)b * TSEQ * CCH;
    float scale = which ? 1.0f : 0.125f;
    gemm_body<true, true>(A, Bm, bias, out, CCH, scale,
                          blockIdx.x * 128, blockIdx.y * 128);
}

// v projection: C[o][t] = W[o][c] * Xt[t][c]^T; bias on M(=o); out half
__global__ __launch_bounds__(256, 2)
void v_kernel(const float* __restrict__ bv)
{
    int b = blockIdx.z;
    const __half* Bm = g_xth + (size_t)b * TSEQ * CCH;
    __half* out = g_vh + (size_t)b * CCH * TSEQ;
    gemm_body<true, false>(g_wvh, Bm, bv, out, TSEQ, 1.0f,
                           blockIdx.x * 128, blockIdx.y * 128);
}

// o projection: C[o][t] = Wo[o][c] * mid[t][c]^T; bias on M; out float
__global__ __launch_bounds__(256, 2)
void o_kernel(const float* __restrict__ bo, float* __restrict__ Out)
{
    int b = blockIdx.z;
    const __half* Bm = g_midh + (size_t)b * TSEQ * CCH;
    float* out = Out + (size_t)b * CCH * TSEQ;
    gemm_body<false, false>(g_woh, Bm, bo, out, TSEQ, 1.0f,
                            blockIdx.x * 128, blockIdx.y * 128);
}

// ---------------------------------------------------------------------------
// Fused flash attention, fp16 MMA. Block = (bh, 128 i-rows), 256 thr, 2 CTA/SM.
// Q [i][d] (stride 72h), K chunks [j][d] (72h), V chunks [d][j] (40h),
// P [i][j] (40h). S phase: warp w rows w*16..+16 x 32 j.
// AV: C[m=i 128][n=d 64], warps 4m x 2n. Output mid[t][C] (k-major for oproj).
// ---------------------------------------------------------------------------
#define BJ 32
#define NJT (TSEQ / BJ)
#define KWRDS (32 * 36)   // K stage words
#define VWRDS (64 * 20)   // V stage words
#define ATTN_SMEM 64512

__global__ __launch_bounds__(256, 2)
void attn_kernel(const float* __restrict__ emb_k, const float* __restrict__ emb_v)
{
    extern __shared__ char smc[];
    uint32_t* Qw = (uint32_t*)smc;          // 128*36 words
    uint32_t* Kw = Qw + 128 * 36;           // 2 x 1152
    uint32_t* Vw = Kw + 2 * KWRDS;          // 2 x 1280
    uint32_t* Pw = Vw + 2 * VWRDS;          // 2560
    float* Rk  = (float*)(Pw + 2560);       // [128][10]
    float* bnd = Rk + 1280;                 // [128][10]
    float* ek  = bnd + 1280;                // [9][64]
    float* ev  = ek + NR * HD;              // [9][64]
    float* sc  = ev + NR * HD;              // [128]
    float* mf  = sc + 128;                  // [128]
    float* li  = mf + 128;                  // [128]

    int bh = blockIdx.y;
    int i0 = blockIdx.x * 128;
    int b = bh / NH, h = bh % NH;
    const __half* qb = g_qh + (size_t)b * TSEQ * CCH + h * HD;   // + i*CCH
    const __half* kb = g_kh + (size_t)b * TSEQ * CCH + h * HD;   // + j*CCH
    const __half* vb = g_vh + ((size_t)b * CCH + h * HD) * TSEQ; // + d*TSEQ

    int tid = threadIdx.x;
    int lane = tid & 31, wid = tid >> 5;
    int gid = lane >> 2, tig = lane & 3;
    int wm2 = wid >> 1, wn2 = wid & 1;

    const uint32_t qS = smem_u32(Qw);
    const uint32_t kS = smem_u32(Kw);
    const uint32_t vS = smem_u32(Vw);

    // copy coords
    int kr = tid >> 3, kc = tid & 7;        // K: 32 rows x 8 chunks (kr 0..31)
    int vr = tid >> 2, vc = tid & 3;        // V: 64 rows x 4 chunks

    // ---- prologue: Q + K0 + V0 ----
#pragma unroll
    for (int p = 0; p < 4; p++) {
        int fl = tid + p * 256;
        int r = fl >> 3, cq = fl & 7;
        cp16(qS + (uint32_t)(r * 36 + cq * 4) * 4, qb + (size_t)(i0 + r) * CCH + cq * 8);
    }
    {
        int r = kr & 31;
        cp16(kS + (uint32_t)(r * 36 + kc * 4) * 4, kb + (size_t)r * CCH + kc * 8);
        cp16(vS + (uint32_t)(vr * 20 + vc * 4) * 4, vb + (size_t)vr * TSEQ + vc * 8);
    }
    CP_COMMIT();

    for (int idx = tid; idx < NR * HD; idx += 256) { ek[idx] = emb_k[idx]; ev[idx] = emb_v[idx]; }
    for (int idx = tid; idx < 128 * 10; idx += 256) bnd[idx] = -1e30f;

    CP_WAIT0();
    __syncthreads();

    // Rk[i][r] = sum_d q[i][d] * ek[r][d]
    for (int idx = tid; idx < 128 * NR; idx += 256) {
        int i = idx / NR, r = idx - i * NR;
        const uint32_t* qrow = Qw + i * 36;
        float acc = 0.f;
#pragma unroll
        for (int w = 0; w < 32; w++) {
            half2 hv = *(const half2*)&qrow[w];
            float2 fv = __half22float2(hv);
            acc += fv.x * ek[r * HD + 2 * w] + fv.y * ek[r * HD + 2 * w + 1];
        }
        Rk[i * 10 + r] = acc;
    }
    __syncthreads();

    int mb = wid * 16 + gid;

    // hoist Q fragments: 4 k16-steps
    uint32_t qf[4][4];
#pragma unroll
    for (int ks = 0; ks < 4; ks++) {
        int k8 = ks * 8;
        qf[ks][0] = Qw[mb * 36 + k8 + tig];
        qf[ks][1] = Qw[(mb + 8) * 36 + k8 + tig];
        qf[ks][2] = Qw[mb * 36 + k8 + tig + 4];
        qf[ks][3] = Qw[(mb + 8) * 36 + k8 + tig + 4];
    }

    float ms0 = -1e30f, ms1 = -1e30f, ls0 = 0.f, ls1 = 0.f;
    float o[2][4][4];
#pragma unroll
    for (int f = 0; f < 2; f++)
#pragma unroll
        for (int n = 0; n < 4; n++)
#pragma unroll
            for (int q = 0; q < 4; q++) o[f][n][q] = 0.f;

    for (int jt = 0; jt < NJT; jt++) {
        int cur = jt & 1;
        if (jt + 1 < NJT) {
            int j1 = (jt + 1) * BJ;
            int nb = (jt + 1) & 1;
            cp16(kS + (uint32_t)(nb * KWRDS + kr * 36 + kc * 4) * 4,
                 kb + (size_t)(j1 + kr) * CCH + kc * 8);
            cp16(vS + (uint32_t)(nb * VWRDS + vr * 20 + vc * 4) * 4,
                 vb + (size_t)vr * TSEQ + j1 + vc * 8);
            CP_COMMIT();
        }
        const uint32_t* Kc = Kw + cur * KWRDS;
        const uint32_t* Vc = Vw + cur * VWRDS;

        // ---- S = Q.K^T : rows mb..mb+15 x 32 j ----
        float c[4][4];
#pragma unroll
        for (int n = 0; n < 4; n++)
#pragma unroll
            for (int q = 0; q < 4; q++) c[n][q] = 0.f;

#pragma unroll
        for (int ks = 0; ks < 4; ks++) {
            int k8 = ks * 8;
#pragma unroll
            for (int n = 0; n < 4; n++) {
                uint32_t bb[2];
                bb[0] = Kc[(n * 8 + gid) * 36 + k8 + tig];
                bb[1] = Kc[(n * 8 + gid) * 36 + k8 + tig + 4];
                mma_f16(c[n], qf[ks], bb);
            }
        }

        // ---- rel-k add + raw band stash ----
        int dj = jt * BJ - i0;
        if (dj >= -35 && dj <= 131) {
#pragma unroll
            for (int n = 0; n < 4; n++) {
#pragma unroll
                for (int q = 0; q < 4; q++) {
                    int ir = mb + ((q >> 1) << 3);
                    int jc = n * 8 + 2 * tig + (q & 1);
                    int r = dj + jc - ir + NWIN;
                    if (r >= 0 && r < NR) {
                        c[n][q] += Rk[ir * 10 + r];
                        bnd[ir * 10 + r] = c[n][q];
                    }
                }
            }
        }

        // ---- online softmax (rows mb / mb+8) ----
        float mx0 = -1e30f, mx1 = -1e30f;
#pragma unroll
        for (int n = 0; n < 4; n++) {
            mx0 = fmaxf(mx0, fmaxf(c[n][0], c[n][1]));
            mx1 = fmaxf(mx1, fmaxf(c[n][2], c[n][3]));
        }
        mx0 = fmaxf(mx0, __shfl_xor_sync(0xffffffffu, mx0, 1));
        mx0 = fmaxf(mx0, __shfl_xor_sync(0xffffffffu, mx0, 2));
        mx1 = fmaxf(mx1, __shfl_xor_sync(0xffffffffu, mx1, 1));
        mx1 = fmaxf(mx1, __shfl_xor_sync(0xffffffffu, mx1, 2));
        float nm0 = fmaxf(ms0, mx0), nm1 = fmaxf(ms1, mx1);
        float al0 = __expf(ms0 - nm0), al1 = __expf(ms1 - nm1);

        float s0 = 0.f, s1 = 0.f;
#pragma unroll
        for (int n = 0; n < 4; n++) {
            c[n][0] = __expf(c[n][0] - nm0); s0 += c[n][0];
            c[n][1] = __expf(c[n][1] - nm0); s0 += c[n][1];
            c[n][2] = __expf(c[n][2] - nm1); s1 += c[n][2];
            c[n][3] = __expf(c[n][3] - nm1); s1 += c[n][3];
        }
        s0 += __shfl_xor_sync(0xffffffffu, s0, 1);
        s0 += __shfl_xor_sync(0xffffffffu, s0, 2);
        s1 += __shfl_xor_sync(0xffffffffu, s1, 1);
        s1 += __shfl_xor_sync(0xffffffffu, s1, 2);
        ls0 = ls0 * al0 + s0;
        ls1 = ls1 * al1 + s1;
        ms0 = nm0; ms1 = nm1;
        if (tig == 0) { sc[mb] = al0; sc[mb + 8] = al1; }

        // ---- write P as fp16 [i][j] (stride 40 halves) ----
#pragma unroll
        for (int n = 0; n < 4; n++) {
            *(half2*)&Pw[mb * 20 + n * 4 + tig] = __floats2half2_rn(c[n][0], c[n][1]);
            *(half2*)&Pw[(mb + 8) * 20 + n * 4 + tig] = __floats2half2_rn(c[n][2], c[n][3]);
        }
        __syncthreads();

        // ---- rescale O rows, then O[i][d] += P[i][j] * V[d][j]^T ----
#pragma unroll
        for (int f = 0; f < 2; f++) {
            int r0 = wm2 * 32 + f * 16 + gid;
            float sa = sc[r0], sb = sc[r0 + 8];
#pragma unroll
            for (int n = 0; n < 4; n++) {
                o[f][n][0] *= sa; o[f][n][1] *= sa;
                o[f][n][2] *= sb; o[f][n][3] *= sb;
            }
        }
#pragma unroll
        for (int kw = 0; kw < 2; kw++) {
            int k8 = kw * 8;
            uint32_t a[2][4];
#pragma unroll
            for (int f = 0; f < 2; f++) {
                int r0 = wm2 * 32 + f * 16 + gid;
                a[f][0] = Pw[r0 * 20 + k8 + tig];
                a[f][1] = Pw[(r0 + 8) * 20 + k8 + tig];
                a[f][2] = Pw[r0 * 20 + k8 + tig + 4];
                a[f][3] = Pw[(r0 + 8) * 20 + k8 + tig + 4];
            }
#pragma unroll
            for (int n = 0; n < 4; n++) {
                int col = wn2 * 32 + n * 8 + gid;
                uint32_t bb[2];
                bb[0] = Vc[col * 20 + k8 + tig];
                bb[1] = Vc[col * 20 + k8 + tig + 4];
#pragma unroll
                for (int f = 0; f < 2; f++) mma_f16(o[f][n], a[f], bb);
            }
        }
        if (jt + 1 < NJT) CP_WAIT0();
        __syncthreads();
    }

    // ---- final stats ----
    if (tig == 0) {
        mf[mb] = ms0; mf[mb + 8] = ms1;
        li[mb] = 1.f / ls0; li[mb + 8] = 1.f / ls1;
    }
    __syncthreads();

    for (int idx = tid; idx < 128 * NR; idx += 256) {
        int i = idx / NR, r = idx - i * NR;
        bnd[i * 10 + r] = __expf(bnd[i * 10 + r] - mf[i]) * li[i];
    }
    __syncthreads();

    // ---- epilogue: mid[i][h*64+d] = O*inv_l + sum_r pb[i][r]*ev[r][d] ----
    __half* om = g_midh + (size_t)b * TSEQ * CCH + h * HD;
#pragma unroll
    for (int f = 0; f < 2; f++) {
        int r0 = wm2 * 32 + f * 16 + gid;
        int r1 = r0 + 8;
        float inv0 = li[r0], inv1 = li[r1];
#pragma unroll
        for (int n = 0; n < 4; n++) {
            int dcol = wn2 * 32 + n * 8 + 2 * tig;
            float v0 = o[f][n][0] * inv0, v1 = o[f][n][1] * inv0;
            float v2 = o[f][n][2] * inv1, v3 = o[f][n][3] * inv1;
#pragma unroll
            for (int rr = 0; rr < NR; rr++) {
                float p0 = bnd[r0 * 10 + rr], p1 = bnd[r1 * 10 + rr];
                float e0 = ev[rr * HD + dcol], e1 = ev[rr * HD + dcol + 1];
                v0 += p0 * e0; v1 += p0 * e1;
                v2 += p1 * e0; v3 += p1 * e1;
            }
            *(half2*)(om + (size_t)(i0 + r0) * CCH + dcol) = __floats2half2_rn(v0, v1);
            *(half2*)(om + (size_t)(i0 + r1) * CCH + dcol) = __floats2half2_rn(v2, v3);
        }
    }
}

// ---------------------------------------------------------------------------
extern "C" void kernel_launch(void* const* d_in, const int* in_sizes, int n_in,
                              void* d_out, int out_size)
{
    const float* x     = (const float*)d_in[0];
    const float* w_q   = (const float*)d_in[1];
    const float* b_q   = (const float*)d_in[2];
    const float* w_k   = (const float*)d_in[3];
    const float* b_k   = (const float*)d_in[4];
    const float* w_v   = (const float*)d_in[5];
    const float* b_v   = (const float*)d_in[6];
    const float* w_o   = (const float*)d_in[7];
    const float* b_o   = (const float*)d_in[8];
    const float* emb_k = (const float*)d_in[9];
    const float* emb_v = (const float*)d_in[10];
    float* out = (float*)d_out;

    cudaFuncSetAttribute(attn_kernel, cudaFuncAttributeMaxDynamicSharedMemorySize, ATTN_SMEM);

    prep_w_kernel<<<512, 256>>>(w_q, w_k, w_v, w_o);
    dim3 gx(TSEQ / 32, CCH / 32, BB);
    prep_xt_kernel<<<gx, 256>>>(x);

    dim3 gqk(TSEQ / 128, CCH / 128, BB * 2);
    qk_kernel<<<gqk, 256>>>(b_q, b_k);

    dim3 gv(CCH / 128, TSEQ / 128, BB);
    v_kernel<<<gv, 256>>>(b_v);

    dim3 ga(TSEQ / 128, NBH);
    attn_kernel<<<ga, 256, ATTN_SMEM>>>(emb_k, emb_v);

    dim3 go(CCH / 128, TSEQ / 128, BB);
    o_kernel<<<go, 256>>>(b_o, out);
}